// round 6
// baseline (speedup 1.0000x reference)
#include <cuda_runtime.h>
#include <cuda_bf16.h>
#include <cstdint>

#define CC   128
#define HH   2
#define HC   256
#define NMAX 100000
#define EMAX 1600000

// ---------------- device scratch (static, no allocation) ----------------
__device__ float g_q[(size_t)NMAX * HC];         // normalized qs fp32
__device__ float g_k[(size_t)NMAX * HC];         // normalized ks fp32
__device__ __nv_bfloat16 g_q16[(size_t)NMAX * HC];
__device__ __nv_bfloat16 g_k16[(size_t)NMAX * HC];
__device__ __nv_bfloat16 g_tA16[(size_t)NMAX * HC];  // term ping (bf16)
__device__ __nv_bfloat16 g_tB16[(size_t)NMAX * HC];  // term pong (bf16)
__device__ float g_deginv[NMAX];
__device__ int   g_deg[NMAX];
__device__ int   g_csroff[NMAX + 1];
__device__ int   g_csrcur[NMAX];
__device__ int   g_csrrow[EMAX];
__device__ int   g_blocksum[128];
__device__ float g_den[NMAX * HH];
__device__ float g_kvs[HH * CC * CC];
__device__ float g_vssum[HH * CC];
__device__ float g_kssum[HH * CC];
__device__ int   g_is64;

// ---------------- helpers ----------------
__device__ __forceinline__ uint32_t f2tf(float x) {
    uint32_t r;
    asm("cvt.rna.tf32.f32 %0, %1;" : "=r"(r) : "f"(x));
    return r;
}
__device__ __forceinline__ uint32_t packbf(float lo, float hi) {
    __nv_bfloat162 h2 = __floats2bfloat162_rn(lo, hi);
    return *reinterpret_cast<uint32_t*>(&h2);
}
__device__ __forceinline__ float2 unpackbf(uint32_t u) {
    __nv_bfloat162 h2 = *reinterpret_cast<__nv_bfloat162*>(&u);
    return __bfloat1622float2(h2);
}

__device__ __forceinline__ void mma16(float* c, uint32_t a0, uint32_t a1, uint32_t a2,
                                      uint32_t a3, uint32_t b0, uint32_t b1) {
    asm volatile(
        "mma.sync.aligned.m16n8k16.row.col.f32.bf16.bf16.f32 "
        "{%0,%1,%2,%3},{%4,%5,%6,%7},{%8,%9},{%0,%1,%2,%3};"
        : "+f"(c[0]), "+f"(c[1]), "+f"(c[2]), "+f"(c[3])
        : "r"(a0), "r"(a1), "r"(a2), "r"(a3), "r"(b0), "r"(b1));
}

// tf32 m16n8k8 over a 16-deep k tile (k-major [16][128]) -- used by tf32 GEMMs
__device__ __forceinline__ void ktile_mma(const uint32_t (*As)[128], const uint32_t (*Bs)[128],
                                          int m0, int n0, int lane, float acc[4][4][4]) {
#pragma unroll
    for (int ks = 0; ks < 2; ks++) {
        int ar = ks * 8 + (lane & 3);
        int ac = lane >> 2;
        uint32_t a[4][4], b[4][2];
#pragma unroll
        for (int mt = 0; mt < 4; mt++) {
            int m = m0 + mt * 16 + ac;
            a[mt][0] = As[ar][m];
            a[mt][1] = As[ar][m + 8];
            a[mt][2] = As[ar + 4][m];
            a[mt][3] = As[ar + 4][m + 8];
        }
#pragma unroll
        for (int nt = 0; nt < 4; nt++) {
            int nn = n0 + nt * 8 + ac;
            b[nt][0] = Bs[ar][nn];
            b[nt][1] = Bs[ar + 4][nn];
        }
#pragma unroll
        for (int mt = 0; mt < 4; mt++)
#pragma unroll
            for (int nt = 0; nt < 4; nt++)
                asm volatile(
                    "mma.sync.aligned.m16n8k8.row.col.f32.tf32.tf32.f32 "
                    "{%0,%1,%2,%3},{%4,%5,%6,%7},{%8,%9},{%0,%1,%2,%3};"
                    : "+f"(acc[mt][nt][0]), "+f"(acc[mt][nt][1]),
                      "+f"(acc[mt][nt][2]), "+f"(acc[mt][nt][3])
                    : "r"(a[mt][0]), "r"(a[mt][1]), "r"(a[mt][2]), "r"(a[mt][3]),
                      "r"(b[nt][0]), "r"(b[nt][1]));
    }
}

// bf16 m16n8k16, smem pair-packed along k: S[k2][m], stride 132 (kvs_reduce)
__device__ __forceinline__ void ktile_mma16(const uint32_t (*As)[132], const uint32_t (*Bs)[132],
                                            int m0, int n0, int lane, float acc[4][4][4], int ksteps) {
    for (int ks = 0; ks < ksteps; ks++) {
        int ar = ks * 8 + (lane & 3);
        int ac = lane >> 2;
        uint32_t a[4][4], b[4][2];
#pragma unroll
        for (int mt = 0; mt < 4; mt++) {
            int m = m0 + mt * 16 + ac;
            a[mt][0] = As[ar][m];
            a[mt][1] = As[ar][m + 8];
            a[mt][2] = As[ar + 4][m];
            a[mt][3] = As[ar + 4][m + 8];
        }
#pragma unroll
        for (int nt = 0; nt < 4; nt++) {
            int nn = n0 + nt * 8 + ac;
            b[nt][0] = Bs[ar][nn];
            b[nt][1] = Bs[ar + 4][nn];
        }
#pragma unroll
        for (int mt = 0; mt < 4; mt++)
#pragma unroll
            for (int nt = 0; nt < 4; nt++)
                mma16(acc[mt][nt], a[mt][0], a[mt][1], a[mt][2], a[mt][3], b[nt][0], b[nt][1]);
    }
}

// ---------------- edge dtype detection ----------------
__global__ void detect_dtype_kernel(const int* __restrict__ ei32, int twoE) {
    __shared__ int nz;
    if (threadIdx.x == 0) nz = 0;
    __syncthreads();
    int samples = min(1024, twoE / 2);
    int local = 0;
    for (int i = threadIdx.x; i < samples; i += blockDim.x)
        if (ei32[2 * i + 1] != 0) local++;
    if (local) atomicAdd(&nz, local);
    __syncthreads();
    if (threadIdx.x == 0) g_is64 = (nz == 0) ? 1 : 0;
}

__device__ __forceinline__ int edge_col(const void* ei, int E, int e) {
    if (g_is64) return (int)((const long long*)ei)[(size_t)E + e];
    return ((const int*)ei)[E + e];
}
__device__ __forceinline__ int edge_row(const void* ei, int E, int e) {
    if (g_is64) return (int)((const long long*)ei)[e];
    return ((const int*)ei)[e];
}

// ---------------- edge prep ----------------
__global__ void edge_deg_kernel(const void* __restrict__ ei, int E) {
    int e = blockIdx.x * blockDim.x + threadIdx.x;
    if (e < E) atomicAdd(&g_deg[edge_col(ei, E, e)], 1);
}

// ---- parallel scan: blocks of 1024 local-scan -> scan totals -> apply ----
__global__ void scan_blocks_kernel(int n) {
    __shared__ int sh[1024];
    int i = blockIdx.x * 1024 + threadIdx.x;
    int v = (i < n) ? g_deg[i] : 0;
    sh[threadIdx.x] = v;
    __syncthreads();
    for (int off = 1; off < 1024; off <<= 1) {
        int t = (threadIdx.x >= off) ? sh[threadIdx.x - off] : 0;
        __syncthreads();
        sh[threadIdx.x] += t;
        __syncthreads();
    }
    if (i < n) g_csroff[i] = sh[threadIdx.x] - v;  // block-local exclusive
    if (threadIdx.x == 1023) g_blocksum[blockIdx.x] = sh[1023];
}

__global__ void scan_tops_kernel(int nb) {
    __shared__ int sh[128];
    int v = (threadIdx.x < nb) ? g_blocksum[threadIdx.x] : 0;
    sh[threadIdx.x] = v;
    __syncthreads();
    for (int off = 1; off < 128; off <<= 1) {
        int t = (threadIdx.x >= off) ? sh[threadIdx.x - off] : 0;
        __syncthreads();
        sh[threadIdx.x] += t;
        __syncthreads();
    }
    if (threadIdx.x < nb) g_blocksum[threadIdx.x] = sh[threadIdx.x] - v;  // exclusive
}

__global__ void scan_apply_kernel(int n, int E) {
    int i = blockIdx.x * blockDim.x + threadIdx.x;
    if (i < n) {
        int off = g_csroff[i] + g_blocksum[i >> 10];
        g_csroff[i] = off;
        g_csrcur[i] = off;
        int d = g_deg[i];
        g_deginv[i] = (d > 0) ? 1.0f / (float)d : 0.0f;
    }
    if (i == 0) g_csroff[n] = E;
}

__global__ void csr_scatter_kernel(const void* __restrict__ ei, int E) {
    int e = blockIdx.x * blockDim.x + threadIdx.x;
    if (e < E) {
        int c = edge_col(ei, E, e);
        int pos = atomicAdd(&g_csrcur[c], 1);
        g_csrrow[pos] = edge_row(ei, E, e);
    }
}

// ---------------- iter-1 GCN gather from fp32 x: nxt = 0.5*deginv*sum x[src], dup heads ----------------
__global__ void gcn_gather_x_kernel(const float* __restrict__ x, __nv_bfloat16* __restrict__ nxt, int n) {
    int gw = (blockIdx.x * blockDim.x + threadIdx.x) >> 5;
    int lane = threadIdx.x & 31;
    if (gw >= n) return;
    int beg = g_csroff[gw], end = g_csroff[gw + 1];
    float s = 0.5f * g_deginv[gw];
    float4 a = make_float4(0, 0, 0, 0);
    int e = beg;
    for (; e + 4 <= end; e += 4) {
        int s0 = g_csrrow[e], s1 = g_csrrow[e + 1], s2 = g_csrrow[e + 2], s3 = g_csrrow[e + 3];
        float4 v0 = ((const float4*)(x + (size_t)s0 * 128))[lane];
        float4 v1 = ((const float4*)(x + (size_t)s1 * 128))[lane];
        float4 v2 = ((const float4*)(x + (size_t)s2 * 128))[lane];
        float4 v3 = ((const float4*)(x + (size_t)s3 * 128))[lane];
        a.x += (v0.x + v1.x) + (v2.x + v3.x);
        a.y += (v0.y + v1.y) + (v2.y + v3.y);
        a.z += (v0.z + v1.z) + (v2.z + v3.z);
        a.w += (v0.w + v1.w) + (v2.w + v3.w);
    }
    for (; e < end; e++) {
        float4 v0 = ((const float4*)(x + (size_t)g_csrrow[e] * 128))[lane];
        a.x += v0.x; a.y += v0.y; a.z += v0.z; a.w += v0.w;
    }
    uint2 o;
    o.x = packbf(s * a.x, s * a.y);
    o.y = packbf(s * a.z, s * a.w);
    *(uint2*)(nxt + (size_t)gw * 256 + lane * 4)       = o;
    *(uint2*)(nxt + (size_t)gw * 256 + 128 + lane * 4) = o;
}

// ---------------- GCN gather bf16 (high occupancy, 1 warp/row): nxt = 0.5*deginv*sum prev[src] ----------------
__global__ void gcn_gather_kernel(__nv_bfloat16* __restrict__ nxt, const __nv_bfloat16* __restrict__ prev, int n) {
    int gw = (blockIdx.x * blockDim.x + threadIdx.x) >> 5;
    int lane = threadIdx.x & 31;
    if (gw >= n) return;
    int beg = g_csroff[gw], end = g_csroff[gw + 1];
    float s = 0.5f * g_deginv[gw];
    float a[8];
#pragma unroll
    for (int i = 0; i < 8; i++) a[i] = 0.f;
    int e = beg;
    for (; e + 4 <= end; e += 4) {
        uint4 v0 = *(const uint4*)(prev + (size_t)g_csrrow[e]     * 256 + lane * 8);
        uint4 v1 = *(const uint4*)(prev + (size_t)g_csrrow[e + 1] * 256 + lane * 8);
        uint4 v2 = *(const uint4*)(prev + (size_t)g_csrrow[e + 2] * 256 + lane * 8);
        uint4 v3 = *(const uint4*)(prev + (size_t)g_csrrow[e + 3] * 256 + lane * 8);
#pragma unroll
        for (int p = 0; p < 4; p++) {
            float2 f0 = unpackbf((&v0.x)[p]);
            float2 f1 = unpackbf((&v1.x)[p]);
            float2 f2 = unpackbf((&v2.x)[p]);
            float2 f3 = unpackbf((&v3.x)[p]);
            a[2 * p]     += (f0.x + f1.x) + (f2.x + f3.x);
            a[2 * p + 1] += (f0.y + f1.y) + (f2.y + f3.y);
        }
    }
    for (; e < end; e++) {
        uint4 v0 = *(const uint4*)(prev + (size_t)g_csrrow[e] * 256 + lane * 8);
#pragma unroll
        for (int p = 0; p < 4; p++) {
            float2 f0 = unpackbf((&v0.x)[p]);
            a[2 * p] += f0.x; a[2 * p + 1] += f0.y;
        }
    }
    uint4 o;
    o.x = packbf(s * a[0], s * a[1]);
    o.y = packbf(s * a[2], s * a[3]);
    o.z = packbf(s * a[4], s * a[5]);
    o.w = packbf(s * a[6], s * a[7]);
    *(uint4*)(nxt + (size_t)gw * 256 + lane * 8) = o;
}

// ---------------- q/k projection GEMM (tf32): [N,128] @ [128,512] ----------------
__global__ void __launch_bounds__(256) qk_gemm_kernel(const float* __restrict__ x,
                               const float* __restrict__ Wq, const float* __restrict__ Wqb,
                               const float* __restrict__ Wk, const float* __restrict__ Wkb,
                               int n) {
    __shared__ uint32_t As[16][128];
    __shared__ uint32_t Bs[16][128];
    int t = threadIdx.x;
    int lane = t & 31, wid = t >> 5;
    int m0 = (wid & 1) * 64, n0 = (wid >> 1) * 32;
    int bm0 = blockIdx.x * 128;
    int by = blockIdx.y;
    const float* B   = (by < 2) ? Wq  : Wk;
    const float* bia = (by < 2) ? Wqb : Wkb;
    float*       dst = (by < 2) ? g_q : g_k;
    int coff = (by & 1) * 128;
    int am = t >> 1, akq = (t & 1) * 8;
    int bk = t >> 4, bnq = (t & 15) * 8;
    float acc[4][4][4];
#pragma unroll
    for (int i = 0; i < 4; i++)
#pragma unroll
        for (int j = 0; j < 4; j++)
#pragma unroll
            for (int r = 0; r < 4; r++) acc[i][j][r] = 0.f;

    for (int k0 = 0; k0 < 128; k0 += 16) {
        float4 a0 = make_float4(0, 0, 0, 0), a1 = a0;
        int row = bm0 + am;
        if (row < n) {
            const float4* ap = (const float4*)(x + (size_t)row * 128 + k0 + akq);
            a0 = ap[0]; a1 = ap[1];
        }
        const float4* bp = (const float4*)(B + (size_t)(k0 + bk) * 256 + coff + bnq);
        float4 b0 = bp[0], b1 = bp[1];
        __syncthreads();
        As[akq + 0][am] = f2tf(a0.x); As[akq + 1][am] = f2tf(a0.y);
        As[akq + 2][am] = f2tf(a0.z); As[akq + 3][am] = f2tf(a0.w);
        As[akq + 4][am] = f2tf(a1.x); As[akq + 5][am] = f2tf(a1.y);
        As[akq + 6][am] = f2tf(a1.z); As[akq + 7][am] = f2tf(a1.w);
        Bs[bk][bnq + 0] = f2tf(b0.x); Bs[bk][bnq + 1] = f2tf(b0.y);
        Bs[bk][bnq + 2] = f2tf(b0.z); Bs[bk][bnq + 3] = f2tf(b0.w);
        Bs[bk][bnq + 4] = f2tf(b1.x); Bs[bk][bnq + 5] = f2tf(b1.y);
        Bs[bk][bnq + 6] = f2tf(b1.z); Bs[bk][bnq + 7] = f2tf(b1.w);
        __syncthreads();
        ktile_mma(As, Bs, m0, n0, lane, acc);
    }
#pragma unroll
    for (int mt = 0; mt < 4; mt++) {
        int row = bm0 + m0 + mt * 16 + (lane >> 2);
#pragma unroll
        for (int nt = 0; nt < 4; nt++) {
            int col = coff + n0 + nt * 8 + 2 * (lane & 3);
            float bx = bia[col], by2 = bia[col + 1];
            if (row < n) {
                float2 v = make_float2(acc[mt][nt][0] + bx, acc[mt][nt][1] + by2);
                *(float2*)&dst[(size_t)row * 256 + col] = v;
            }
            if (row + 8 < n) {
                float2 v = make_float2(acc[mt][nt][2] + bx, acc[mt][nt][3] + by2);
                *(float2*)&dst[(size_t)(row + 8) * 256 + col] = v;
            }
        }
    }
}

// ---------------- normalize (fp32) + write bf16 copies ----------------
__global__ void normalize_kernel(int n) {
    int gw = (blockIdx.x * blockDim.x + threadIdx.x) >> 5;
    int lane = threadIdx.x & 31;
    if (gw >= n * 4) return;
    int node = gw >> 2, sel = gw & 3;
    size_t off = (size_t)node * 256 + (sel & 1) * 128;
    float* base = ((sel < 2) ? g_q : g_k) + off;
    __nv_bfloat16* b16 = ((sel < 2) ? g_q16 : g_k16) + off;
    float4 v = ((float4*)base)[lane];
    float ss = v.x * v.x + v.y * v.y + v.z * v.z + v.w * v.w;
#pragma unroll
    for (int o = 16; o; o >>= 1) ss += __shfl_xor_sync(0xffffffffu, ss, o);
    float inv = rsqrtf(ss);
    v.x *= inv; v.y *= inv; v.z *= inv; v.w *= inv;
    ((float4*)base)[lane] = v;
    uint2 u;
    u.x = packbf(v.x, v.y);
    u.y = packbf(v.z, v.w);
    *(uint2*)(b16 + lane * 4) = u;
}

// ---------------- ks_sum (loop-invariant, fp32) ----------------
__global__ void kssum_kernel(int n) {
    int col = threadIdx.x;  // 0..255
    int start = blockIdx.x * 512;
    int end = min(start + 512, n);
    float s = 0.f;
    for (int node = start; node < end; node++) s += g_k[(size_t)node * 256 + col];
    atomicAdd(&g_kssum[col], s);
}

// ---------------- den = qs . ks_sum + n (loop-invariant, fp32) ----------------
__global__ void den_kernel(int n) {
    int gw = (blockIdx.x * blockDim.x + threadIdx.x) >> 5;
    int lane = threadIdx.x & 31;
    if (gw >= n * 2) return;
    int node = gw >> 1, h = gw & 1;
    float4 qv = ((const float4*)(g_q + (size_t)node * 256 + h * 128))[lane];
    float4 kv = ((const float4*)(g_kssum + h * 128))[lane];
    float d = qv.x * kv.x + qv.y * kv.y + qv.z * kv.z + qv.w * kv.w;
#pragma unroll
    for (int o = 16; o; o >>= 1) d += __shfl_xor_sync(0xffffffffu, d, o);
    if (lane == 0) g_den[node * 2 + h] = d + (float)n;
}

// ---------------- term0 = broadcast x over heads (bf16) ----------------
__global__ void broadcast_kernel(const float* __restrict__ x, int n) {
    int idx = blockIdx.x * blockDim.x + threadIdx.x;
    if (idx < n * 256) {
        int node = idx >> 8;
        int c = idx & 127;
        g_tA16[idx] = __float2bfloat16(x[(size_t)node * 128 + c]);
    }
}

// ---------------- out init (tf32): 0.5*(x @ (Wo[h0,k0]+Wo[h1,k0]) + b) ----------------
__global__ void __launch_bounds__(256) out_init_kernel(const float* __restrict__ x, const float* __restrict__ Wo,
                                const float* __restrict__ Wob, float* __restrict__ out, int n) {
    __shared__ uint32_t As[16][128];
    __shared__ uint32_t Bs[16][128];
    int t = threadIdx.x;
    int lane = t & 31, wid = t >> 5;
    int m0 = (wid & 1) * 64, n0 = (wid >> 1) * 32;
    int bm0 = blockIdx.x * 128;
    int am = t >> 1, akq = (t & 1) * 8;
    int bk = t >> 4, bnq = (t & 15) * 8;
    float acc[4][4][4];
#pragma unroll
    for (int i = 0; i < 4; i++)
#pragma unroll
        for (int j = 0; j < 4; j++)
#pragma unroll
            for (int r = 0; r < 4; r++) acc[i][j][r] = 0.f;

    for (int k0 = 0; k0 < 128; k0 += 16) {
        float4 a0 = make_float4(0, 0, 0, 0), a1 = a0;
        int row = bm0 + am;
        if (row < n) {
            const float4* ap = (const float4*)(x + (size_t)row * 128 + k0 + akq);
            a0 = ap[0]; a1 = ap[1];
        }
        int wr = k0 + bk;
        const float4* p0 = (const float4*)(Wo + (size_t)wr * 128 + bnq);
        const float4* p1 = (const float4*)(Wo + (size_t)(640 + wr) * 128 + bnq);
        float4 u0 = p0[0], u1 = p0[1], v0 = p1[0], v1 = p1[1];
        __syncthreads();
        As[akq + 0][am] = f2tf(a0.x); As[akq + 1][am] = f2tf(a0.y);
        As[akq + 2][am] = f2tf(a0.z); As[akq + 3][am] = f2tf(a0.w);
        As[akq + 4][am] = f2tf(a1.x); As[akq + 5][am] = f2tf(a1.y);
        As[akq + 6][am] = f2tf(a1.z); As[akq + 7][am] = f2tf(a1.w);
        Bs[bk][bnq + 0] = f2tf(u0.x + v0.x); Bs[bk][bnq + 1] = f2tf(u0.y + v0.y);
        Bs[bk][bnq + 2] = f2tf(u0.z + v0.z); Bs[bk][bnq + 3] = f2tf(u0.w + v0.w);
        Bs[bk][bnq + 4] = f2tf(u1.x + v1.x); Bs[bk][bnq + 5] = f2tf(u1.y + v1.y);
        Bs[bk][bnq + 6] = f2tf(u1.z + v1.z); Bs[bk][bnq + 7] = f2tf(u1.w + v1.w);
        __syncthreads();
        ktile_mma(As, Bs, m0, n0, lane, acc);
    }
#pragma unroll
    for (int mt = 0; mt < 4; mt++) {
        int row = bm0 + m0 + mt * 16 + (lane >> 2);
#pragma unroll
        for (int nt = 0; nt < 4; nt++) {
            int col = n0 + nt * 8 + 2 * (lane & 3);
            float bx = Wob[col], by2 = Wob[col + 1];
            if (row < n) {
                float2 v = make_float2(0.5f * (acc[mt][nt][0] + bx), 0.5f * (acc[mt][nt][1] + by2));
                *(float2*)&out[(size_t)row * 128 + col] = v;
            }
            if (row + 8 < n) {
                float2 v = make_float2(0.5f * (acc[mt][nt][2] + bx), 0.5f * (acc[mt][nt][3] + by2));
                *(float2*)&out[(size_t)(row + 8) * 128 + col] = v;
            }
        }
    }
}

// ---------------- kvs[h] += ks^T @ prev (bf16 mma) ; vs_sum (fp32) ----------------
__global__ void __launch_bounds__(256) kvs_reduce_kernel(const __nv_bfloat16* __restrict__ prev, int n) {
    int h = blockIdx.y;
    int c0 = blockIdx.x * 1024;
    int c1 = min(c0 + 1024, n);
    __shared__ uint32_t ksS[16][132];
    __shared__ uint32_t pvS[16][132];
    int t = threadIdx.x;
    int lane = t & 31, wid = t >> 5;
    int m0 = (wid & 1) * 64, n0 = (wid >> 1) * 32;
    float acc[4][4][4];
#pragma unroll
    for (int i = 0; i < 4; i++)
#pragma unroll
        for (int j = 0; j < 4; j++)
#pragma unroll
            for (int r = 0; r < 4; r++) acc[i][j][r] = 0.f;
    float colsum = 0.f;
    int myc = t & 127, hb = (t >> 7) * 8;

    for (int s = c0; s < c1; s += 32) {
        __syncthreads();
#pragma unroll
        for (int i = 0; i < 4; i++) {
            int u = t + 256 * i;
            int nn = u >> 6, m2 = u & 63;
            int nd0 = s + 2 * nn, nd1 = nd0 + 1;
            uint32_t k0 = 0, k1 = 0, p0 = 0, p1 = 0;
            if (nd0 < c1) {
                k0 = *(const uint32_t*)(g_k16 + (size_t)nd0 * 256 + h * 128 + 2 * m2);
                p0 = *(const uint32_t*)(prev  + (size_t)nd0 * 256 + h * 128 + 2 * m2);
            }
            if (nd1 < c1) {
                k1 = *(const uint32_t*)(g_k16 + (size_t)nd1 * 256 + h * 128 + 2 * m2);
                p1 = *(const uint32_t*)(prev  + (size_t)nd1 * 256 + h * 128 + 2 * m2);
            }
            ksS[nn][2 * m2]     = __byte_perm(k0, k1, 0x5410);
            ksS[nn][2 * m2 + 1] = __byte_perm(k0, k1, 0x7632);
            pvS[nn][2 * m2]     = __byte_perm(p0, p1, 0x5410);
            pvS[nn][2 * m2 + 1] = __byte_perm(p0, p1, 0x7632);
        }
        __syncthreads();
        ktile_mma16(ksS, pvS, m0, n0, lane, acc, 2);
#pragma unroll
        for (int r = 0; r < 8; r++) {
            float2 f = unpackbf(pvS[hb + r][myc]);
            colsum += f.x + f.y;
        }
    }
    atomicAdd(&g_vssum[h * 128 + myc], colsum);
    float* kv = g_kvs + h * 16384;
#pragma unroll
    for (int mt = 0; mt < 4; mt++) {
        int m = m0 + mt * 16 + (lane >> 2);
#pragma unroll
        for (int nt = 0; nt < 4; nt++) {
            int c = n0 + nt * 8 + 2 * (lane & 3);
            atomicAdd(&kv[m * 128 + c],           acc[mt][nt][0]);
            atomicAdd(&kv[m * 128 + c + 1],       acc[mt][nt][1]);
            atomicAdd(&kv[(m + 8) * 128 + c],     acc[mt][nt][2]);
            atomicAdd(&kv[(m + 8) * 128 + c + 1], acc[mt][nt][3]);
        }
    }
}

// ==================== fused attention + out kernel ====================
// Per 128-row block: load pre-gathered gcn term tile from nxt into smem Ts,
// attention GEMM per head (q16 @ kvs) + add gcn -> write nxt once,
// then out += 0.5 * term @ Wo_slice with A read from Ts in smem.
#define TS_STRIDE 132
#define AQ_STRIDE 20
#define BS_STRIDE 136
#define SM_WORDS  (128 * TS_STRIDE + 128 * AQ_STRIDE + 16 * BS_STRIDE)

__global__ void __launch_bounds__(256) attn_out_fused_kernel(
    __nv_bfloat16* __restrict__ nxt,
    const float* __restrict__ Wo, float* __restrict__ out,
    int n, int ksl) {
    extern __shared__ uint32_t sm[];
    uint32_t (*Ts)[TS_STRIDE] = (uint32_t(*)[TS_STRIDE])sm;
    uint32_t (*Aq)[AQ_STRIDE] = (uint32_t(*)[AQ_STRIDE])(sm + 128 * TS_STRIDE);
    uint32_t (*Bs)[BS_STRIDE] = (uint32_t(*)[BS_STRIDE])(sm + 128 * TS_STRIDE + 128 * AQ_STRIDE);

    int t = threadIdx.x, lane = t & 31, wid = t >> 5;
    int bm0 = blockIdx.x * 128;
    int m0 = (wid & 1) * 64, n0 = (wid >> 1) * 32;

    // ---- phase 1: load pre-gathered gcn tile from nxt into Ts ----
    for (int r = wid; r < 128; r += 8) {
        int row = bm0 + r;
        uint4 v = make_uint4(0, 0, 0, 0);
        if (row < n) v = *(const uint4*)(nxt + (size_t)row * 256 + lane * 8);
        Ts[r][lane * 4 + 0] = v.x; Ts[r][lane * 4 + 1] = v.y;
        Ts[r][lane * 4 + 2] = v.z; Ts[r][lane * 4 + 3] = v.w;
    }
    __syncthreads();

    // ---- phase 2: attention per head: acc = q16 @ kvs; term += (acc+vs)/den ----
    for (int h = 0; h < 2; h++) {
        const float* kvp = g_kvs + h * 16384;
        float acc[4][4][4];
#pragma unroll
        for (int i = 0; i < 4; i++)
#pragma unroll
            for (int j = 0; j < 4; j++)
#pragma unroll
                for (int r = 0; r < 4; r++) acc[i][j][r] = 0.f;

        for (int kc = 0; kc < 4; kc++) {  // 32 k-elems (16 pairs) per chunk
            int kb = kc * 32;
            __syncthreads();
            // stage A: q16 rows [128][16 pairs]
#pragma unroll
            for (int i = 0; i < 2; i++) {
                int u = t + 256 * i;           // 0..511
                int r = u >> 2, q4 = u & 3;    // 4 x uint4 per row
                uint4 v = make_uint4(0, 0, 0, 0);
                if (bm0 + r < n)
                    v = *(const uint4*)(g_q16 + (size_t)(bm0 + r) * 256 + h * 128 + kb + q4 * 8);
                Aq[r][q4 * 4 + 0] = v.x; Aq[r][q4 * 4 + 1] = v.y;
                Aq[r][q4 * 4 + 2] = v.z; Aq[r][q4 * 4 + 3] = v.w;
            }
            // stage B: kvs fp32 -> bf16 pairs [16 pairs][128]
#pragma unroll
            for (int i = 0; i < 8; i++) {
                int u = t + 256 * i;           // 0..2047
                int k2 = u >> 7, c = u & 127;
                int kk = kb + 2 * k2;
                Bs[k2][c] = packbf(kvp[kk * 128 + c], kvp[(kk + 1) * 128 + c]);
            }
            __syncthreads();
#pragma unroll
            for (int ks = 0; ks < 2; ks++) {
                int pb = ks * 8 + (lane & 3);
                uint32_t b[4][2];
#pragma unroll
                for (int nt = 0; nt < 4; nt++) {
                    int nn = n0 + nt * 8 + (lane >> 2);
                    b[nt][0] = Bs[pb][nn];
                    b[nt][1] = Bs[pb + 4][nn];
                }
#pragma unroll
                for (int mt = 0; mt < 4; mt++) {
                    int m = m0 + mt * 16 + (lane >> 2);
                    uint32_t a0 = Aq[m][pb], a1 = Aq[m + 8][pb];
                    uint32_t a2 = Aq[m][pb + 4], a3 = Aq[m + 8][pb + 4];
#pragma unroll
                    for (int nt = 0; nt < 4; nt++)
                        mma16(acc[mt][nt], a0, a1, a2, a3, b[nt][0], b[nt][1]);
                }
            }
        }
        // epilogue: term = Ts + (acc + vs)/den ; write Ts (smem) and nxt (gmem)
#pragma unroll
        for (int mt = 0; mt < 4; mt++) {
            int r = m0 + mt * 16 + (lane >> 2);
#pragma unroll
            for (int nt = 0; nt < 4; nt++) {
                int col = n0 + nt * 8 + 2 * (lane & 3);
                int w2 = h * 64 + (col >> 1);
                float vs0 = g_vssum[h * 128 + col], vs1 = g_vssum[h * 128 + col + 1];
                {
                    int row = bm0 + r;
                    float invd = (row < n) ? 1.0f / g_den[row * 2 + h] : 0.f;
                    float2 g = unpackbf(Ts[r][w2]);
                    uint32_t pw = packbf(g.x + (acc[mt][nt][0] + vs0) * invd,
                                         g.y + (acc[mt][nt][1] + vs1) * invd);
                    Ts[r][w2] = pw;
                    if (row < n) *(uint32_t*)(nxt + (size_t)row * 256 + h * 128 + col) = pw;
                }
                {
                    int row = bm0 + r + 8;
                    float invd = (row < n) ? 1.0f / g_den[row * 2 + h] : 0.f;
                    float2 g = unpackbf(Ts[r + 8][w2]);
                    uint32_t pw = packbf(g.x + (acc[mt][nt][2] + vs0) * invd,
                                         g.y + (acc[mt][nt][3] + vs1) * invd);
                    Ts[r + 8][w2] = pw;
                    if (row < n) *(uint32_t*)(nxt + (size_t)row * 256 + h * 128 + col) = pw;
                }
            }
        }
    }
    __syncthreads();

    // ---- phase 3: out += 0.5 * term @ Wo_slice, A direct from Ts ----
    float acc[4][4][4];
#pragma unroll
    for (int i = 0; i < 4; i++)
#pragma unroll
        for (int j = 0; j < 4; j++)
#pragma unroll
            for (int r = 0; r < 4; r++) acc[i][j][r] = 0.f;

    for (int kc = 0; kc < 8; kc++) {  // 32 k-elems per chunk over K=256
        int kb2 = kc * 16;            // pair base into Ts
        __syncthreads();
#pragma unroll
        for (int i = 0; i < 8; i++) {
            int u = t + 256 * i;
            int k2 = u >> 7, c = u & 127;
            int j = kc * 32 + 2 * k2;
            int wrow = ((j >> 7) * 640) + ksl * 128 + (j & 127);
            Bs[k2][c] = packbf(Wo[(size_t)wrow * 128 + c], Wo[(size_t)(wrow + 1) * 128 + c]);
        }
        __syncthreads();
#pragma unroll
        for (int ks = 0; ks < 2; ks++) {
            int pb = ks * 8 + (lane & 3);
            uint32_t b[4][2];
#pragma unroll
            for (int nt = 0; nt < 4; nt++) {
                int nn = n0 + nt * 8 + (lane >> 2);
                b[nt][0] = Bs[pb][nn];
                b[nt][1] = Bs[pb + 4][nn];
            }
#pragma unroll
            for (int mt = 0; mt < 4; mt++) {
                int m = m0 + mt * 16 + (lane >> 2);
                uint32_t a0 = Ts[m][kb2 + pb], a1 = Ts[m + 8][kb2 + pb];
                uint32_t a2 = Ts[m][kb2 + pb + 4], a3 = Ts[m + 8][kb2 + pb + 4];
#pragma unroll
                for (int nt = 0; nt < 4; nt++)
                    mma16(acc[mt][nt], a0, a1, a2, a3, b[nt][0], b[nt][1]);
            }
        }
    }
#pragma unroll
    for (int mt = 0; mt < 4; mt++) {
        int row = bm0 + m0 + mt * 16 + (lane >> 2);
#pragma unroll
        for (int nt = 0; nt < 4; nt++) {
            int col = n0 + nt * 8 + 2 * (lane & 3);
            if (row < n) {
                float2 c = *(float2*)&out[(size_t)row * 128 + col];
                c.x += 0.5f * acc[mt][nt][0];
                c.y += 0.5f * acc[mt][nt][1];
                *(float2*)&out[(size_t)row * 128 + col] = c;
            }
            if (row + 8 < n) {
                float2 c = *(float2*)&out[(size_t)(row + 8) * 128 + col];
                c.x += 0.5f * acc[mt][nt][2];
                c.y += 0.5f * acc[mt][nt][3];
                *(float2*)&out[(size_t)(row + 8) * 128 + col] = c;
            }
        }
    }
}

// ---------------- host orchestration ----------------
extern "C" void kernel_launch(void* const* d_in, const int* in_sizes, int n_in,
                              void* d_out, int out_size) {
    const float* x   = (const float*)d_in[0];
    const void*  ei  = d_in[1];
    const float* Wqw = (const float*)d_in[2];
    const float* Wqb = (const float*)d_in[3];
    const float* Wkw = (const float*)d_in[4];
    const float* Wkb = (const float*)d_in[5];
    const float* Wow = (const float*)d_in[6];
    const float* Wob = (const float*)d_in[7];
    float* out = (float*)d_out;

    int n = in_sizes[0] / CC;
    int E = in_sizes[1] / 2;

    void *pDeg, *pKvs, *pVs, *pKs, *pA16, *pB16;
    cudaGetSymbolAddress(&pDeg, g_deg);
    cudaGetSymbolAddress(&pKvs, g_kvs);
    cudaGetSymbolAddress(&pVs,  g_vssum);
    cudaGetSymbolAddress(&pKs,  g_kssum);
    cudaGetSymbolAddress(&pA16, g_tA16);
    cudaGetSymbolAddress(&pB16, g_tB16);

    static int smem_set = 0;
    if (!smem_set) {
        cudaFuncSetAttribute(attn_out_fused_kernel,
                             cudaFuncAttributeMaxDynamicSharedMemorySize,
                             SM_WORDS * 4);
        smem_set = 1;
    }

    // ---- edge prep (parallel scan) ----
    int nbScan = (n + 1023) / 1024;
    cudaMemsetAsync(pDeg, 0, (size_t)n * sizeof(int));
    detect_dtype_kernel<<<1, 256>>>((const int*)ei, in_sizes[1]);
    edge_deg_kernel<<<(E + 255) / 256, 256>>>(ei, E);
    scan_blocks_kernel<<<nbScan, 1024>>>(n);
    scan_tops_kernel<<<1, 128>>>(nbScan);
    scan_apply_kernel<<<(n + 255) / 256, 256>>>(n, E);
    csr_scatter_kernel<<<(E + 255) / 256, 256>>>(ei, E);
    gcn_gather_x_kernel<<<(n * 32 + 255) / 256, 256>>>(x, (__nv_bfloat16*)pB16, n);

    dim3 gqk((n + 127) / 128, 4);
    qk_gemm_kernel<<<gqk, 256>>>(x, Wqw, Wqb, Wkw, Wkb, n);
    normalize_kernel<<<(n * 4 * 32 + 255) / 256, 256>>>(n);
    cudaMemsetAsync(pKs, 0, (size_t)HH * CC * sizeof(float));
    kssum_kernel<<<(n + 511) / 512, 256>>>(n);
    den_kernel<<<(n * 2 * 32 + 255) / 256, 256>>>(n);
    broadcast_kernel<<<(n * 256 + 255) / 256, 256>>>(x, n);
    out_init_kernel<<<(n + 127) / 128, 256>>>(x, Wow, Wob, out, n);

    // ---- K_ORDER iterations: kvs_reduce + standalone gather + fused(attn|out) ----
    __nv_bfloat16* prev = (__nv_bfloat16*)pA16;
    __nv_bfloat16* nxt  = (__nv_bfloat16*)pB16;
    int nb = (n + 127) / 128;
    for (int ksl = 1; ksl <= 4; ksl++) {
        cudaMemsetAsync(pKvs, 0, (size_t)HH * CC * CC * sizeof(float));
        cudaMemsetAsync(pVs,  0, (size_t)HH * CC * sizeof(float));
        kvs_reduce_kernel<<<dim3((n + 1023) / 1024, 2), 256>>>(prev, n);
        if (ksl > 1)  // iter 1 gather already done (from x, fp32-exact)
            gcn_gather_kernel<<<(n * 32 + 255) / 256, 256>>>(nxt, prev, n);
        attn_out_fused_kernel<<<nb, 256, SM_WORDS * 4>>>(nxt, Wow, out, n, ksl);
        __nv_bfloat16* tmp = prev; prev = nxt; nxt = tmp;
    }
}

// round 7
// speedup vs baseline: 1.1397x; 1.1397x over previous
#include <cuda_runtime.h>
#include <cuda_bf16.h>
#include <cstdint>

#define CC   128
#define HH   2
#define HC   256
#define NMAX 100000
#define EMAX 1600000

// ---------------- device scratch (static, no allocation) ----------------
__device__ __nv_bfloat16 g_q16[(size_t)NMAX * HC];
__device__ __nv_bfloat16 g_k16[(size_t)NMAX * HC];
__device__ __nv_bfloat16 g_tA16[(size_t)NMAX * HC];  // term ping (bf16)
__device__ __nv_bfloat16 g_tB16[(size_t)NMAX * HC];  // term pong (bf16)
__device__ float g_deginv[NMAX];
__device__ int   g_deg[NMAX];
__device__ int   g_csroff[NMAX + 1];
__device__ int   g_csrcur[NMAX];
__device__ int   g_csrrow[EMAX];
__device__ int   g_blocksum[128];
__device__ float g_den[NMAX * HH];
__device__ float g_kvs[HH * CC * CC];
__device__ float g_vssum[HH * CC];
__device__ float g_kssum[HH * CC];
__device__ int   g_is64;

// ---------------- helpers ----------------
__device__ __forceinline__ uint32_t f2tf(float x) {
    uint32_t r;
    asm("cvt.rna.tf32.f32 %0, %1;" : "=r"(r) : "f"(x));
    return r;
}
__device__ __forceinline__ uint32_t packbf(float lo, float hi) {
    __nv_bfloat162 h2 = __floats2bfloat162_rn(lo, hi);
    return *reinterpret_cast<uint32_t*>(&h2);
}
__device__ __forceinline__ float2 unpackbf(uint32_t u) {
    __nv_bfloat162 h2 = *reinterpret_cast<__nv_bfloat162*>(&u);
    return __bfloat1622float2(h2);
}

__device__ __forceinline__ void mma16(float* c, uint32_t a0, uint32_t a1, uint32_t a2,
                                      uint32_t a3, uint32_t b0, uint32_t b1) {
    asm volatile(
        "mma.sync.aligned.m16n8k16.row.col.f32.bf16.bf16.f32 "
        "{%0,%1,%2,%3},{%4,%5,%6,%7},{%8,%9},{%0,%1,%2,%3};"
        : "+f"(c[0]), "+f"(c[1]), "+f"(c[2]), "+f"(c[3])
        : "r"(a0), "r"(a1), "r"(a2), "r"(a3), "r"(b0), "r"(b1));
}

// tf32 m16n8k8 over a 16-deep k tile (k-major [16][128])
__device__ __forceinline__ void ktile_mma(const uint32_t (*As)[128], const uint32_t (*Bs)[128],
                                          int m0, int n0, int lane, float acc[4][4][4]) {
#pragma unroll
    for (int ks = 0; ks < 2; ks++) {
        int ar = ks * 8 + (lane & 3);
        int ac = lane >> 2;
        uint32_t a[4][4], b[4][2];
#pragma unroll
        for (int mt = 0; mt < 4; mt++) {
            int m = m0 + mt * 16 + ac;
            a[mt][0] = As[ar][m];
            a[mt][1] = As[ar][m + 8];
            a[mt][2] = As[ar + 4][m];
            a[mt][3] = As[ar + 4][m + 8];
        }
#pragma unroll
        for (int nt = 0; nt < 4; nt++) {
            int nn = n0 + nt * 8 + ac;
            b[nt][0] = Bs[ar][nn];
            b[nt][1] = Bs[ar + 4][nn];
        }
#pragma unroll
        for (int mt = 0; mt < 4; mt++)
#pragma unroll
            for (int nt = 0; nt < 4; nt++)
                asm volatile(
                    "mma.sync.aligned.m16n8k8.row.col.f32.tf32.tf32.f32 "
                    "{%0,%1,%2,%3},{%4,%5,%6,%7},{%8,%9},{%0,%1,%2,%3};"
                    : "+f"(acc[mt][nt][0]), "+f"(acc[mt][nt][1]),
                      "+f"(acc[mt][nt][2]), "+f"(acc[mt][nt][3])
                    : "r"(a[mt][0]), "r"(a[mt][1]), "r"(a[mt][2]), "r"(a[mt][3]),
                      "r"(b[nt][0]), "r"(b[nt][1]));
    }
}

// bf16 m16n8k16, smem pair-packed along k: S[k2][m], stride 132
__device__ __forceinline__ void ktile_mma16(const uint32_t (*As)[132], const uint32_t (*Bs)[132],
                                            int m0, int n0, int lane, float acc[4][4][4], int ksteps) {
    for (int ks = 0; ks < ksteps; ks++) {
        int ar = ks * 8 + (lane & 3);
        int ac = lane >> 2;
        uint32_t a[4][4], b[4][2];
#pragma unroll
        for (int mt = 0; mt < 4; mt++) {
            int m = m0 + mt * 16 + ac;
            a[mt][0] = As[ar][m];
            a[mt][1] = As[ar][m + 8];
            a[mt][2] = As[ar + 4][m];
            a[mt][3] = As[ar + 4][m + 8];
        }
#pragma unroll
        for (int nt = 0; nt < 4; nt++) {
            int nn = n0 + nt * 8 + ac;
            b[nt][0] = Bs[ar][nn];
            b[nt][1] = Bs[ar + 4][nn];
        }
#pragma unroll
        for (int mt = 0; mt < 4; mt++)
#pragma unroll
            for (int nt = 0; nt < 4; nt++)
                mma16(acc[mt][nt], a[mt][0], a[mt][1], a[mt][2], a[mt][3], b[nt][0], b[nt][1]);
    }
}

// ---------------- edge dtype detection ----------------
__global__ void detect_dtype_kernel(const int* __restrict__ ei32, int twoE) {
    __shared__ int nz;
    if (threadIdx.x == 0) nz = 0;
    __syncthreads();
    int samples = min(1024, twoE / 2);
    int local = 0;
    for (int i = threadIdx.x; i < samples; i += blockDim.x)
        if (ei32[2 * i + 1] != 0) local++;
    if (local) atomicAdd(&nz, local);
    __syncthreads();
    if (threadIdx.x == 0) g_is64 = (nz == 0) ? 1 : 0;
}

__device__ __forceinline__ int edge_col(const void* ei, int E, int e) {
    if (g_is64) return (int)((const long long*)ei)[(size_t)E + e];
    return ((const int*)ei)[E + e];
}
__device__ __forceinline__ int edge_row(const void* ei, int E, int e) {
    if (g_is64) return (int)((const long long*)ei)[e];
    return ((const int*)ei)[e];
}

// ---------------- edge prep ----------------
__global__ void edge_deg_kernel(const void* __restrict__ ei, int E) {
    int e = blockIdx.x * blockDim.x + threadIdx.x;
    if (e < E) atomicAdd(&g_deg[edge_col(ei, E, e)], 1);
}

__global__ void scan_blocks_kernel(int n) {
    __shared__ int sh[1024];
    int i = blockIdx.x * 1024 + threadIdx.x;
    int v = (i < n) ? g_deg[i] : 0;
    sh[threadIdx.x] = v;
    __syncthreads();
    for (int off = 1; off < 1024; off <<= 1) {
        int t = (threadIdx.x >= off) ? sh[threadIdx.x - off] : 0;
        __syncthreads();
        sh[threadIdx.x] += t;
        __syncthreads();
    }
    if (i < n) g_csroff[i] = sh[threadIdx.x] - v;
    if (threadIdx.x == 1023) g_blocksum[blockIdx.x] = sh[1023];
}

__global__ void scan_tops_kernel(int nb) {
    __shared__ int sh[128];
    int v = (threadIdx.x < nb) ? g_blocksum[threadIdx.x] : 0;
    sh[threadIdx.x] = v;
    __syncthreads();
    for (int off = 1; off < 128; off <<= 1) {
        int t = (threadIdx.x >= off) ? sh[threadIdx.x - off] : 0;
        __syncthreads();
        sh[threadIdx.x] += t;
        __syncthreads();
    }
    if (threadIdx.x < nb) g_blocksum[threadIdx.x] = sh[threadIdx.x] - v;
}

__global__ void scan_apply_kernel(int n, int E) {
    int i = blockIdx.x * blockDim.x + threadIdx.x;
    if (i < n) {
        int off = g_csroff[i] + g_blocksum[i >> 10];
        g_csroff[i] = off;
        g_csrcur[i] = off;
        int d = g_deg[i];
        g_deginv[i] = (d > 0) ? 1.0f / (float)d : 0.0f;
    }
    if (i == 0) g_csroff[n] = E;
}

__global__ void csr_scatter_kernel(const void* __restrict__ ei, int E) {
    int e = blockIdx.x * blockDim.x + threadIdx.x;
    if (e < E) {
        int c = edge_col(ei, E, e);
        int pos = atomicAdd(&g_csrcur[c], 1);
        g_csrrow[pos] = edge_row(ei, E, e);
    }
}

// ---------------- iter-1 GCN gather from fp32 x ----------------
__global__ void gcn_gather_x_kernel(const float* __restrict__ x, __nv_bfloat16* __restrict__ nxt, int n) {
    int gw = (blockIdx.x * blockDim.x + threadIdx.x) >> 5;
    int lane = threadIdx.x & 31;
    if (gw >= n) return;
    int beg = g_csroff[gw], end = g_csroff[gw + 1];
    float s = 0.5f * g_deginv[gw];
    float4 a = make_float4(0, 0, 0, 0);
    int e = beg;
    for (; e + 4 <= end; e += 4) {
        int s0 = g_csrrow[e], s1 = g_csrrow[e + 1], s2 = g_csrrow[e + 2], s3 = g_csrrow[e + 3];
        float4 v0 = ((const float4*)(x + (size_t)s0 * 128))[lane];
        float4 v1 = ((const float4*)(x + (size_t)s1 * 128))[lane];
        float4 v2 = ((const float4*)(x + (size_t)s2 * 128))[lane];
        float4 v3 = ((const float4*)(x + (size_t)s3 * 128))[lane];
        a.x += (v0.x + v1.x) + (v2.x + v3.x);
        a.y += (v0.y + v1.y) + (v2.y + v3.y);
        a.z += (v0.z + v1.z) + (v2.z + v3.z);
        a.w += (v0.w + v1.w) + (v2.w + v3.w);
    }
    for (; e < end; e++) {
        float4 v0 = ((const float4*)(x + (size_t)g_csrrow[e] * 128))[lane];
        a.x += v0.x; a.y += v0.y; a.z += v0.z; a.w += v0.w;
    }
    uint2 o;
    o.x = packbf(s * a.x, s * a.y);
    o.y = packbf(s * a.z, s * a.w);
    *(uint2*)(nxt + (size_t)gw * 256 + lane * 4)       = o;
    *(uint2*)(nxt + (size_t)gw * 256 + 128 + lane * 4) = o;
}

// ---------------- GCN gather bf16 (high occupancy, 1 warp/row) ----------------
__global__ void gcn_gather_kernel(__nv_bfloat16* __restrict__ nxt, const __nv_bfloat16* __restrict__ prev, int n) {
    int gw = (blockIdx.x * blockDim.x + threadIdx.x) >> 5;
    int lane = threadIdx.x & 31;
    if (gw >= n) return;
    int beg = g_csroff[gw], end = g_csroff[gw + 1];
    float s = 0.5f * g_deginv[gw];
    float a[8];
#pragma unroll
    for (int i = 0; i < 8; i++) a[i] = 0.f;
    int e = beg;
    for (; e + 4 <= end; e += 4) {
        uint4 v0 = *(const uint4*)(prev + (size_t)g_csrrow[e]     * 256 + lane * 8);
        uint4 v1 = *(const uint4*)(prev + (size_t)g_csrrow[e + 1] * 256 + lane * 8);
        uint4 v2 = *(const uint4*)(prev + (size_t)g_csrrow[e + 2] * 256 + lane * 8);
        uint4 v3 = *(const uint4*)(prev + (size_t)g_csrrow[e + 3] * 256 + lane * 8);
#pragma unroll
        for (int p = 0; p < 4; p++) {
            float2 f0 = unpackbf((&v0.x)[p]);
            float2 f1 = unpackbf((&v1.x)[p]);
            float2 f2 = unpackbf((&v2.x)[p]);
            float2 f3 = unpackbf((&v3.x)[p]);
            a[2 * p]     += (f0.x + f1.x) + (f2.x + f3.x);
            a[2 * p + 1] += (f0.y + f1.y) + (f2.y + f3.y);
        }
    }
    for (; e < end; e++) {
        uint4 v0 = *(const uint4*)(prev + (size_t)g_csrrow[e] * 256 + lane * 8);
#pragma unroll
        for (int p = 0; p < 4; p++) {
            float2 f0 = unpackbf((&v0.x)[p]);
            a[2 * p] += f0.x; a[2 * p + 1] += f0.y;
        }
    }
    uint4 o;
    o.x = packbf(s * a[0], s * a[1]);
    o.y = packbf(s * a[2], s * a[3]);
    o.z = packbf(s * a[4], s * a[5]);
    o.w = packbf(s * a[6], s * a[7]);
    *(uint4*)(nxt + (size_t)gw * 256 + lane * 8) = o;
}

// ---------------- q/k projection GEMM (tf32) + fused L2 norm -> bf16 only ----------------
// grid.y: 0,1 -> q head0/head1; 2,3 -> k head0/head1. Block holds a full head
// (128 cols) for its 128 rows, so the row norm is block-local.
__global__ void __launch_bounds__(256) qk_gemm_kernel(const float* __restrict__ x,
                               const float* __restrict__ Wq, const float* __restrict__ Wqb,
                               const float* __restrict__ Wk, const float* __restrict__ Wkb,
                               int n) {
    __shared__ uint32_t As[16][128];
    __shared__ uint32_t Bs[16][128];
    __shared__ float rowss[128];
    int t = threadIdx.x;
    int lane = t & 31, wid = t >> 5;
    int m0 = (wid & 1) * 64, n0 = (wid >> 1) * 32;
    int bm0 = blockIdx.x * 128;
    int by = blockIdx.y;
    const float* B   = (by < 2) ? Wq  : Wk;
    const float* bia = (by < 2) ? Wqb : Wkb;
    __nv_bfloat16* dst = (by < 2) ? g_q16 : g_k16;
    int coff = (by & 1) * 128;
    int am = t >> 1, akq = (t & 1) * 8;
    int bk = t >> 4, bnq = (t & 15) * 8;
    float acc[4][4][4];
#pragma unroll
    for (int i = 0; i < 4; i++)
#pragma unroll
        for (int j = 0; j < 4; j++)
#pragma unroll
            for (int r = 0; r < 4; r++) acc[i][j][r] = 0.f;
    if (t < 128) rowss[t] = 0.f;

    for (int k0 = 0; k0 < 128; k0 += 16) {
        float4 a0 = make_float4(0, 0, 0, 0), a1 = a0;
        int row = bm0 + am;
        if (row < n) {
            const float4* ap = (const float4*)(x + (size_t)row * 128 + k0 + akq);
            a0 = ap[0]; a1 = ap[1];
        }
        const float4* bp = (const float4*)(B + (size_t)(k0 + bk) * 256 + coff + bnq);
        float4 b0 = bp[0], b1 = bp[1];
        __syncthreads();
        As[akq + 0][am] = f2tf(a0.x); As[akq + 1][am] = f2tf(a0.y);
        As[akq + 2][am] = f2tf(a0.z); As[akq + 3][am] = f2tf(a0.w);
        As[akq + 4][am] = f2tf(a1.x); As[akq + 5][am] = f2tf(a1.y);
        As[akq + 6][am] = f2tf(a1.z); As[akq + 7][am] = f2tf(a1.w);
        Bs[bk][bnq + 0] = f2tf(b0.x); Bs[bk][bnq + 1] = f2tf(b0.y);
        Bs[bk][bnq + 2] = f2tf(b0.z); Bs[bk][bnq + 3] = f2tf(b0.w);
        Bs[bk][bnq + 4] = f2tf(b1.x); Bs[bk][bnq + 5] = f2tf(b1.y);
        Bs[bk][bnq + 6] = f2tf(b1.z); Bs[bk][bnq + 7] = f2tf(b1.w);
        __syncthreads();
        ktile_mma(As, Bs, m0, n0, lane, acc);
    }

    // add bias, accumulate row sum-of-squares into rowss
#pragma unroll
    for (int mt = 0; mt < 4; mt++) {
        float ss0 = 0.f, ss1 = 0.f;
#pragma unroll
        for (int nt = 0; nt < 4; nt++) {
            int col = coff + n0 + nt * 8 + 2 * (lane & 3);
            float bx = bia[col], by2 = bia[col + 1];
            acc[mt][nt][0] += bx; acc[mt][nt][1] += by2;
            acc[mt][nt][2] += bx; acc[mt][nt][3] += by2;
            ss0 += acc[mt][nt][0] * acc[mt][nt][0] + acc[mt][nt][1] * acc[mt][nt][1];
            ss1 += acc[mt][nt][2] * acc[mt][nt][2] + acc[mt][nt][3] * acc[mt][nt][3];
        }
        ss0 += __shfl_xor_sync(0xffffffffu, ss0, 1);
        ss0 += __shfl_xor_sync(0xffffffffu, ss0, 2);
        ss1 += __shfl_xor_sync(0xffffffffu, ss1, 1);
        ss1 += __shfl_xor_sync(0xffffffffu, ss1, 2);
        if ((lane & 3) == 0) {
            int r = m0 + mt * 16 + (lane >> 2);
            atomicAdd(&rowss[r], ss0);
            atomicAdd(&rowss[r + 8], ss1);
        }
    }
    __syncthreads();

    // normalize and write bf16 only
#pragma unroll
    for (int mt = 0; mt < 4; mt++) {
        int r = m0 + mt * 16 + (lane >> 2);
        float inv0 = rsqrtf(rowss[r]);
        float inv1 = rsqrtf(rowss[r + 8]);
        int row = bm0 + r;
#pragma unroll
        for (int nt = 0; nt < 4; nt++) {
            int col = coff + n0 + nt * 8 + 2 * (lane & 3);
            if (row < n)
                *(uint32_t*)(dst + (size_t)row * 256 + col) =
                    packbf(acc[mt][nt][0] * inv0, acc[mt][nt][1] * inv0);
            if (row + 8 < n)
                *(uint32_t*)(dst + (size_t)(row + 8) * 256 + col) =
                    packbf(acc[mt][nt][2] * inv1, acc[mt][nt][3] * inv1);
        }
    }
}

// ---------------- ks_sum from bf16 (fp32 accumulate) ----------------
__global__ void kssum_kernel(int n) {
    int col = threadIdx.x;  // 0..255
    int start = blockIdx.x * 512;
    int end = min(start + 512, n);
    float s = 0.f;
    for (int node = start; node < end; node++)
        s += __bfloat162float(g_k16[(size_t)node * 256 + col]);
    atomicAdd(&g_kssum[col], s);
}

// ---------------- den = q16 . ks_sum + n ----------------
__global__ void den_kernel(int n) {
    int gw = (blockIdx.x * blockDim.x + threadIdx.x) >> 5;
    int lane = threadIdx.x & 31;
    if (gw >= n * 2) return;
    int node = gw >> 1, h = gw & 1;
    uint2 qu = *(const uint2*)(g_q16 + (size_t)node * 256 + h * 128 + lane * 4);
    float2 qa = unpackbf(qu.x), qb = unpackbf(qu.y);
    float4 kv = ((const float4*)(g_kssum + h * 128))[lane];
    float d = qa.x * kv.x + qa.y * kv.y + qb.x * kv.z + qb.y * kv.w;
#pragma unroll
    for (int o = 16; o; o >>= 1) d += __shfl_xor_sync(0xffffffffu, d, o);
    if (lane == 0) g_den[node * 2 + h] = d + (float)n;
}

// ---------------- term0 = broadcast x over heads (bf16) ----------------
__global__ void broadcast_kernel(const float* __restrict__ x, int n) {
    int idx = blockIdx.x * blockDim.x + threadIdx.x;
    if (idx < n * 256) {
        int node = idx >> 8;
        int c = idx & 127;
        g_tA16[idx] = __float2bfloat16(x[(size_t)node * 128 + c]);
    }
}

// ---------------- out init (tf32): 0.5*(x @ (Wo[h0,k0]+Wo[h1,k0]) + b) ----------------
__global__ void __launch_bounds__(256) out_init_kernel(const float* __restrict__ x, const float* __restrict__ Wo,
                                const float* __restrict__ Wob, float* __restrict__ out, int n) {
    __shared__ uint32_t As[16][128];
    __shared__ uint32_t Bs[16][128];
    int t = threadIdx.x;
    int lane = t & 31, wid = t >> 5;
    int m0 = (wid & 1) * 64, n0 = (wid >> 1) * 32;
    int bm0 = blockIdx.x * 128;
    int am = t >> 1, akq = (t & 1) * 8;
    int bk = t >> 4, bnq = (t & 15) * 8;
    float acc[4][4][4];
#pragma unroll
    for (int i = 0; i < 4; i++)
#pragma unroll
        for (int j = 0; j < 4; j++)
#pragma unroll
            for (int r = 0; r < 4; r++) acc[i][j][r] = 0.f;

    for (int k0 = 0; k0 < 128; k0 += 16) {
        float4 a0 = make_float4(0, 0, 0, 0), a1 = a0;
        int row = bm0 + am;
        if (row < n) {
            const float4* ap = (const float4*)(x + (size_t)row * 128 + k0 + akq);
            a0 = ap[0]; a1 = ap[1];
        }
        int wr = k0 + bk;
        const float4* p0 = (const float4*)(Wo + (size_t)wr * 128 + bnq);
        const float4* p1 = (const float4*)(Wo + (size_t)(640 + wr) * 128 + bnq);
        float4 u0 = p0[0], u1 = p0[1], v0 = p1[0], v1 = p1[1];
        __syncthreads();
        As[akq + 0][am] = f2tf(a0.x); As[akq + 1][am] = f2tf(a0.y);
        As[akq + 2][am] = f2tf(a0.z); As[akq + 3][am] = f2tf(a0.w);
        As[akq + 4][am] = f2tf(a1.x); As[akq + 5][am] = f2tf(a1.y);
        As[akq + 6][am] = f2tf(a1.z); As[akq + 7][am] = f2tf(a1.w);
        Bs[bk][bnq + 0] = f2tf(u0.x + v0.x); Bs[bk][bnq + 1] = f2tf(u0.y + v0.y);
        Bs[bk][bnq + 2] = f2tf(u0.z + v0.z); Bs[bk][bnq + 3] = f2tf(u0.w + v0.w);
        Bs[bk][bnq + 4] = f2tf(u1.x + v1.x); Bs[bk][bnq + 5] = f2tf(u1.y + v1.y);
        Bs[bk][bnq + 6] = f2tf(u1.z + v1.z); Bs[bk][bnq + 7] = f2tf(u1.w + v1.w);
        __syncthreads();
        ktile_mma(As, Bs, m0, n0, lane, acc);
    }
#pragma unroll
    for (int mt = 0; mt < 4; mt++) {
        int row = bm0 + m0 + mt * 16 + (lane >> 2);
#pragma unroll
        for (int nt = 0; nt < 4; nt++) {
            int col = n0 + nt * 8 + 2 * (lane & 3);
            float bx = Wob[col], by2 = Wob[col + 1];
            if (row < n) {
                float2 v = make_float2(0.5f * (acc[mt][nt][0] + bx), 0.5f * (acc[mt][nt][1] + by2));
                *(float2*)&out[(size_t)row * 128 + col] = v;
            }
            if (row + 8 < n) {
                float2 v = make_float2(0.5f * (acc[mt][nt][2] + bx), 0.5f * (acc[mt][nt][3] + by2));
                *(float2*)&out[(size_t)(row + 8) * 128 + col] = v;
            }
        }
    }
}

// ---------------- kvs[h] += ks^T @ prev (bf16 mma) ; vs_sum (fp32) ----------------
__global__ void __launch_bounds__(256) kvs_reduce_kernel(const __nv_bfloat16* __restrict__ prev, int n) {
    int h = blockIdx.y;
    int c0 = blockIdx.x * 1024;
    int c1 = min(c0 + 1024, n);
    __shared__ uint32_t ksS[16][132];
    __shared__ uint32_t pvS[16][132];
    int t = threadIdx.x;
    int lane = t & 31, wid = t >> 5;
    int m0 = (wid & 1) * 64, n0 = (wid >> 1) * 32;
    float acc[4][4][4];
#pragma unroll
    for (int i = 0; i < 4; i++)
#pragma unroll
        for (int j = 0; j < 4; j++)
#pragma unroll
            for (int r = 0; r < 4; r++) acc[i][j][r] = 0.f;
    float colsum = 0.f;
    int myc = t & 127, hb = (t >> 7) * 8;

    for (int s = c0; s < c1; s += 32) {
        __syncthreads();
#pragma unroll
        for (int i = 0; i < 4; i++) {
            int u = t + 256 * i;
            int nn = u >> 6, m2 = u & 63;
            int nd0 = s + 2 * nn, nd1 = nd0 + 1;
            uint32_t k0 = 0, k1 = 0, p0 = 0, p1 = 0;
            if (nd0 < c1) {
                k0 = *(const uint32_t*)(g_k16 + (size_t)nd0 * 256 + h * 128 + 2 * m2);
                p0 = *(const uint32_t*)(prev  + (size_t)nd0 * 256 + h * 128 + 2 * m2);
            }
            if (nd1 < c1) {
                k1 = *(const uint32_t*)(g_k16 + (size_t)nd1 * 256 + h * 128 + 2 * m2);
                p1 = *(const uint32_t*)(prev  + (size_t)nd1 * 256 + h * 128 + 2 * m2);
            }
            ksS[nn][2 * m2]     = __byte_perm(k0, k1, 0x5410);
            ksS[nn][2 * m2 + 1] = __byte_perm(k0, k1, 0x7632);
            pvS[nn][2 * m2]     = __byte_perm(p0, p1, 0x5410);
            pvS[nn][2 * m2 + 1] = __byte_perm(p0, p1, 0x7632);
        }
        __syncthreads();
        ktile_mma16(ksS, pvS, m0, n0, lane, acc, 2);
#pragma unroll
        for (int r = 0; r < 8; r++) {
            float2 f = unpackbf(pvS[hb + r][myc]);
            colsum += f.x + f.y;
        }
    }
    atomicAdd(&g_vssum[h * 128 + myc], colsum);
    float* kv = g_kvs + h * 16384;
#pragma unroll
    for (int mt = 0; mt < 4; mt++) {
        int m = m0 + mt * 16 + (lane >> 2);
#pragma unroll
        for (int nt = 0; nt < 4; nt++) {
            int c = n0 + nt * 8 + 2 * (lane & 3);
            atomicAdd(&kv[m * 128 + c],           acc[mt][nt][0]);
            atomicAdd(&kv[m * 128 + c + 1],       acc[mt][nt][1]);
            atomicAdd(&kv[(m + 8) * 128 + c],     acc[mt][nt][2]);
            atomicAdd(&kv[(m + 8) * 128 + c + 1], acc[mt][nt][3]);
        }
    }
}

// ---------------- nxt += (qs @ kvs + vs_sum) / den  (bf16 mma, RMW-add) ----------------
__global__ void __launch_bounds__(256) qkv_combine_kernel(__nv_bfloat16* __restrict__ nxt, int n) {
    int h = blockIdx.y;
    __shared__ uint32_t As[32][132];
    __shared__ uint32_t Bs[32][132];
    int t = threadIdx.x;
    int lane = t & 31, wid = t >> 5;
    int m0 = (wid & 1) * 64, n0 = (wid >> 1) * 32;
    int bm0 = blockIdx.x * 128;
    const float* kvp = g_kvs + h * 16384;
    float acc[4][4][4];
#pragma unroll
    for (int i = 0; i < 4; i++)
#pragma unroll
        for (int j = 0; j < 4; j++)
#pragma unroll
            for (int r = 0; r < 4; r++) acc[i][j][r] = 0.f;

#pragma unroll
    for (int kc = 0; kc < 2; kc++) {
        int kb = kc * 64;
        __syncthreads();
#pragma unroll
        for (int i = 0; i < 4; i++) {
            int u = t + 256 * i;
            int row = u >> 3, q = u & 7;
            uint4 v = make_uint4(0, 0, 0, 0);
            if (bm0 + row < n)
                v = *(const uint4*)(g_q16 + (size_t)(bm0 + row) * 256 + h * 128 + kb + q * 8);
            As[q * 4 + 0][row] = v.x; As[q * 4 + 1][row] = v.y;
            As[q * 4 + 2][row] = v.z; As[q * 4 + 3][row] = v.w;
        }
#pragma unroll
        for (int i = 0; i < 16; i++) {
            int u = t + 256 * i;
            int d = u & 127, m2 = u >> 7;
            int m = kb + 2 * m2;
            Bs[m2][d] = packbf(kvp[m * 128 + d], kvp[(m + 1) * 128 + d]);
        }
        __syncthreads();
        ktile_mma16((const uint32_t(*)[132])As, (const uint32_t(*)[132])Bs, m0, n0, lane, acc, 4);
    }
#pragma unroll
    for (int mt = 0; mt < 4; mt++) {
        int row = bm0 + m0 + mt * 16 + (lane >> 2);
#pragma unroll
        for (int nt = 0; nt < 4; nt++) {
            int col = n0 + nt * 8 + 2 * (lane & 3);
            float vs0 = g_vssum[h * 128 + col], vs1 = g_vssum[h * 128 + col + 1];
            if (row < n) {
                float invd = 1.0f / g_den[row * 2 + h];
                uint32_t* p = (uint32_t*)(nxt + (size_t)row * 256 + h * 128 + col);
                float2 old = unpackbf(*p);
                *p = packbf(old.x + (acc[mt][nt][0] + vs0) * invd,
                            old.y + (acc[mt][nt][1] + vs1) * invd);
            }
            if (row + 8 < n) {
                float invd = 1.0f / g_den[(row + 8) * 2 + h];
                uint32_t* p = (uint32_t*)(nxt + (size_t)(row + 8) * 256 + h * 128 + col);
                float2 old = unpackbf(*p);
                *p = packbf(old.x + (acc[mt][nt][2] + vs0) * invd,
                            old.y + (acc[mt][nt][3] + vs1) * invd);
            }
        }
    }
}

// ---------------- out += 0.5 * term_k @ Wo_slice(k) (bf16 mma) ----------------
__global__ void __launch_bounds__(256) out_accum_kernel(const __nv_bfloat16* __restrict__ term,
                                 const float* __restrict__ Wo,
                                 float* __restrict__ out, int n, int ksl) {
    __shared__ uint32_t As[32][132];
    __shared__ uint32_t Bs[32][132];
    int t = threadIdx.x;
    int lane = t & 31, wid = t >> 5;
    int m0 = (wid & 1) * 64, n0 = (wid >> 1) * 32;
    int bm0 = blockIdx.x * 128;
    float acc[4][4][4];
#pragma unroll
    for (int i = 0; i < 4; i++)
#pragma unroll
        for (int j = 0; j < 4; j++)
#pragma unroll
            for (int r = 0; r < 4; r++) acc[i][j][r] = 0.f;

#pragma unroll
    for (int kc = 0; kc < 4; kc++) {
        int kb = kc * 64;
        __syncthreads();
#pragma unroll
        for (int i = 0; i < 4; i++) {
            int u = t + 256 * i;
            int row = u >> 3, q = u & 7;
            uint4 v = make_uint4(0, 0, 0, 0);
            if (bm0 + row < n)
                v = *(const uint4*)(term + (size_t)(bm0 + row) * 256 + kb + q * 8);
            As[q * 4 + 0][row] = v.x; As[q * 4 + 1][row] = v.y;
            As[q * 4 + 2][row] = v.z; As[q * 4 + 3][row] = v.w;
        }
#pragma unroll
        for (int i = 0; i < 16; i++) {
            int u = t + 256 * i;
            int c = u & 127, j2 = u >> 7;
            int j = kb + 2 * j2;
            int wrow = ((j >> 7) * 640) + ksl * 128 + (j & 127);
            Bs[j2][c] = packbf(Wo[(size_t)wrow * 128 + c], Wo[(size_t)(wrow + 1) * 128 + c]);
        }
        __syncthreads();
        ktile_mma16((const uint32_t(*)[132])As, (const uint32_t(*)[132])Bs, m0, n0, lane, acc, 4);
    }
#pragma unroll
    for (int mt = 0; mt < 4; mt++) {
        int row = bm0 + m0 + mt * 16 + (lane >> 2);
#pragma unroll
        for (int nt = 0; nt < 4; nt++) {
            int col = n0 + nt * 8 + 2 * (lane & 3);
            if (row < n) {
                float2 c = *(float2*)&out[(size_t)row * 128 + col];
                c.x += 0.5f * acc[mt][nt][0];
                c.y += 0.5f * acc[mt][nt][1];
                *(float2*)&out[(size_t)row * 128 + col] = c;
            }
            if (row + 8 < n) {
                float2 c = *(float2*)&out[(size_t)(row + 8) * 128 + col];
                c.x += 0.5f * acc[mt][nt][2];
                c.y += 0.5f * acc[mt][nt][3];
                *(float2*)&out[(size_t)(row + 8) * 128 + col] = c;
            }
        }
    }
}

// ---------------- host orchestration ----------------
extern "C" void kernel_launch(void* const* d_in, const int* in_sizes, int n_in,
                              void* d_out, int out_size) {
    const float* x   = (const float*)d_in[0];
    const void*  ei  = d_in[1];
    const float* Wqw = (const float*)d_in[2];
    const float* Wqb = (const float*)d_in[3];
    const float* Wkw = (const float*)d_in[4];
    const float* Wkb = (const float*)d_in[5];
    const float* Wow = (const float*)d_in[6];
    const float* Wob = (const float*)d_in[7];
    float* out = (float*)d_out;

    int n = in_sizes[0] / CC;
    int E = in_sizes[1] / 2;

    void *pDeg, *pKvs, *pVs, *pKs, *pA16, *pB16;
    cudaGetSymbolAddress(&pDeg, g_deg);
    cudaGetSymbolAddress(&pKvs, g_kvs);
    cudaGetSymbolAddress(&pVs,  g_vssum);
    cudaGetSymbolAddress(&pKs,  g_kssum);
    cudaGetSymbolAddress(&pA16, g_tA16);
    cudaGetSymbolAddress(&pB16, g_tB16);

    // ---- edge prep ----
    int nbScan = (n + 1023) / 1024;
    cudaMemsetAsync(pDeg, 0, (size_t)n * sizeof(int));
    detect_dtype_kernel<<<1, 256>>>((const int*)ei, in_sizes[1]);
    edge_deg_kernel<<<(E + 255) / 256, 256>>>(ei, E);
    scan_blocks_kernel<<<nbScan, 1024>>>(n);
    scan_tops_kernel<<<1, 128>>>(nbScan);
    scan_apply_kernel<<<(n + 255) / 256, 256>>>(n, E);
    csr_scatter_kernel<<<(E + 255) / 256, 256>>>(ei, E);
    gcn_gather_x_kernel<<<(n * 32 + 255) / 256, 256>>>(x, (__nv_bfloat16*)pB16, n);

    // ---- projections (fused norm, bf16 output only) + invariants ----
    dim3 gqk((n + 127) / 128, 4);
    qk_gemm_kernel<<<gqk, 256>>>(x, Wqw, Wqb, Wkw, Wkb, n);
    cudaMemsetAsync(pKs, 0, (size_t)HH * CC * sizeof(float));
    kssum_kernel<<<(n + 511) / 512, 256>>>(n);
    den_kernel<<<(n * 2 * 32 + 255) / 256, 256>>>(n);
    broadcast_kernel<<<(n * 256 + 255) / 256, 256>>>(x, n);
    out_init_kernel<<<(n + 127) / 128, 256>>>(x, Wow, Wob, out, n);

    // ---- K_ORDER iterations (round-4 structure) ----
    __nv_bfloat16* prev = (__nv_bfloat16*)pA16;
    __nv_bfloat16* nxt  = (__nv_bfloat16*)pB16;
    int nb = (n + 127) / 128;
    for (int ksl = 1; ksl <= 4; ksl++) {
        cudaMemsetAsync(pKvs, 0, (size_t)HH * CC * CC * sizeof(float));
        cudaMemsetAsync(pVs,  0, (size_t)HH * CC * sizeof(float));
        kvs_reduce_kernel<<<dim3((n + 1023) / 1024, 2), 256>>>(prev, n);
        if (ksl > 1)  // iter 1 gather already done (from x, fp32-exact)
            gcn_gather_kernel<<<(n * 32 + 255) / 256, 256>>>(nxt, prev, n);
        qkv_combine_kernel<<<dim3((n + 127) / 128, 2), 256>>>(nxt, n);
        out_accum_kernel<<<nb, 256>>>(nxt, Wow, out, n, ksl);
        __nv_bfloat16* tmp = prev; prev = nxt; nxt = tmp;
    }
}

// round 8
// speedup vs baseline: 1.1983x; 1.0515x over previous
#include <cuda_runtime.h>
#include <cuda_bf16.h>
#include <cstdint>

#define CC   128
#define HH   2
#define HC   256
#define NMAX 100000
#define EMAX 1600000

// ---------------- device scratch (static, no allocation) ----------------
__device__ __nv_bfloat16 g_q16[(size_t)NMAX * HC];
__device__ __nv_bfloat16 g_k16[(size_t)NMAX * HC];
__device__ __nv_bfloat16 g_tA16[(size_t)NMAX * HC];  // term ping (bf16)
__device__ __nv_bfloat16 g_tB16[(size_t)NMAX * HC];  // term pong (bf16)
__device__ float g_deginv[NMAX];
__device__ int   g_deg[NMAX];
__device__ int   g_csroff[NMAX + 1];
__device__ int   g_csrcur[NMAX];
__device__ int   g_csrrow[EMAX];
__device__ int   g_blocksum[128];
__device__ float g_den[NMAX * HH];
__device__ float g_kvs[HH * CC * CC];
__device__ float g_vssum[HH * CC];
__device__ float g_kssum[HH * CC];
__device__ int   g_is64;

// ---------------- helpers ----------------
__device__ __forceinline__ uint32_t f2tf(float x) {
    uint32_t r;
    asm("cvt.rna.tf32.f32 %0, %1;" : "=r"(r) : "f"(x));
    return r;
}
__device__ __forceinline__ uint32_t packbf(float lo, float hi) {
    __nv_bfloat162 h2 = __floats2bfloat162_rn(lo, hi);
    return *reinterpret_cast<uint32_t*>(&h2);
}
__device__ __forceinline__ float2 unpackbf(uint32_t u) {
    __nv_bfloat162 h2 = *reinterpret_cast<__nv_bfloat162*>(&u);
    return __bfloat1622float2(h2);
}

__device__ __forceinline__ void mma16(float* c, uint32_t a0, uint32_t a1, uint32_t a2,
                                      uint32_t a3, uint32_t b0, uint32_t b1) {
    asm volatile(
        "mma.sync.aligned.m16n8k16.row.col.f32.bf16.bf16.f32 "
        "{%0,%1,%2,%3},{%4,%5,%6,%7},{%8,%9},{%0,%1,%2,%3};"
        : "+f"(c[0]), "+f"(c[1]), "+f"(c[2]), "+f"(c[3])
        : "r"(a0), "r"(a1), "r"(a2), "r"(a3), "r"(b0), "r"(b1));
}

// tf32 m16n8k8 over a 16-deep k tile (k-major [16][128])
__device__ __forceinline__ void ktile_mma(const uint32_t (*As)[128], const uint32_t (*Bs)[128],
                                          int m0, int n0, int lane, float acc[4][4][4]) {
#pragma unroll
    for (int ks = 0; ks < 2; ks++) {
        int ar = ks * 8 + (lane & 3);
        int ac = lane >> 2;
        uint32_t a[4][4], b[4][2];
#pragma unroll
        for (int mt = 0; mt < 4; mt++) {
            int m = m0 + mt * 16 + ac;
            a[mt][0] = As[ar][m];
            a[mt][1] = As[ar][m + 8];
            a[mt][2] = As[ar + 4][m];
            a[mt][3] = As[ar + 4][m + 8];
        }
#pragma unroll
        for (int nt = 0; nt < 4; nt++) {
            int nn = n0 + nt * 8 + ac;
            b[nt][0] = Bs[ar][nn];
            b[nt][1] = Bs[ar + 4][nn];
        }
#pragma unroll
        for (int mt = 0; mt < 4; mt++)
#pragma unroll
            for (int nt = 0; nt < 4; nt++)
                asm volatile(
                    "mma.sync.aligned.m16n8k8.row.col.f32.tf32.tf32.f32 "
                    "{%0,%1,%2,%3},{%4,%5,%6,%7},{%8,%9},{%0,%1,%2,%3};"
                    : "+f"(acc[mt][nt][0]), "+f"(acc[mt][nt][1]),
                      "+f"(acc[mt][nt][2]), "+f"(acc[mt][nt][3])
                    : "r"(a[mt][0]), "r"(a[mt][1]), "r"(a[mt][2]), "r"(a[mt][3]),
                      "r"(b[nt][0]), "r"(b[nt][1]));
    }
}

// bf16 m16n8k16, smem pair-packed along k: S[k2][m], stride 132
__device__ __forceinline__ void ktile_mma16(const uint32_t (*As)[132], const uint32_t (*Bs)[132],
                                            int m0, int n0, int lane, float acc[4][4][4], int ksteps) {
    for (int ks = 0; ks < ksteps; ks++) {
        int ar = ks * 8 + (lane & 3);
        int ac = lane >> 2;
        uint32_t a[4][4], b[4][2];
#pragma unroll
        for (int mt = 0; mt < 4; mt++) {
            int m = m0 + mt * 16 + ac;
            a[mt][0] = As[ar][m];
            a[mt][1] = As[ar][m + 8];
            a[mt][2] = As[ar + 4][m];
            a[mt][3] = As[ar + 4][m + 8];
        }
#pragma unroll
        for (int nt = 0; nt < 4; nt++) {
            int nn = n0 + nt * 8 + ac;
            b[nt][0] = Bs[ar][nn];
            b[nt][1] = Bs[ar + 4][nn];
        }
#pragma unroll
        for (int mt = 0; mt < 4; mt++)
#pragma unroll
            for (int nt = 0; nt < 4; nt++)
                mma16(acc[mt][nt], a[mt][0], a[mt][1], a[mt][2], a[mt][3], b[nt][0], b[nt][1]);
    }
}

// ---------------- edge dtype detection ----------------
__global__ void detect_dtype_kernel(const int* __restrict__ ei32, int twoE) {
    __shared__ int nz;
    if (threadIdx.x == 0) nz = 0;
    __syncthreads();
    int samples = min(1024, twoE / 2);
    int local = 0;
    for (int i = threadIdx.x; i < samples; i += blockDim.x)
        if (ei32[2 * i + 1] != 0) local++;
    if (local) atomicAdd(&nz, local);
    __syncthreads();
    if (threadIdx.x == 0) g_is64 = (nz == 0) ? 1 : 0;
}

__device__ __forceinline__ int edge_col(const void* ei, int E, int e) {
    if (g_is64) return (int)((const long long*)ei)[(size_t)E + e];
    return ((const int*)ei)[E + e];
}
__device__ __forceinline__ int edge_row(const void* ei, int E, int e) {
    if (g_is64) return (int)((const long long*)ei)[e];
    return ((const int*)ei)[e];
}

// ---------------- edge prep ----------------
__global__ void edge_deg_kernel(const void* __restrict__ ei, int E) {
    int e = blockIdx.x * blockDim.x + threadIdx.x;
    if (e < E) atomicAdd(&g_deg[edge_col(ei, E, e)], 1);
}

__global__ void scan_blocks_kernel(int n) {
    __shared__ int sh[1024];
    int i = blockIdx.x * 1024 + threadIdx.x;
    int v = (i < n) ? g_deg[i] : 0;
    sh[threadIdx.x] = v;
    __syncthreads();
    for (int off = 1; off < 1024; off <<= 1) {
        int t = (threadIdx.x >= off) ? sh[threadIdx.x - off] : 0;
        __syncthreads();
        sh[threadIdx.x] += t;
        __syncthreads();
    }
    if (i < n) g_csroff[i] = sh[threadIdx.x] - v;
    if (threadIdx.x == 1023) g_blocksum[blockIdx.x] = sh[1023];
}

__global__ void scan_tops_kernel(int nb) {
    __shared__ int sh[128];
    int v = (threadIdx.x < nb) ? g_blocksum[threadIdx.x] : 0;
    sh[threadIdx.x] = v;
    __syncthreads();
    for (int off = 1; off < 128; off <<= 1) {
        int t = (threadIdx.x >= off) ? sh[threadIdx.x - off] : 0;
        __syncthreads();
        sh[threadIdx.x] += t;
        __syncthreads();
    }
    if (threadIdx.x < nb) g_blocksum[threadIdx.x] = sh[threadIdx.x] - v;
}

__global__ void scan_apply_kernel(int n, int E) {
    int i = blockIdx.x * blockDim.x + threadIdx.x;
    if (i < n) {
        int off = g_csroff[i] + g_blocksum[i >> 10];
        g_csroff[i] = off;
        g_csrcur[i] = off;
        int d = g_deg[i];
        g_deginv[i] = (d > 0) ? 1.0f / (float)d : 0.0f;
    }
    if (i == 0) g_csroff[n] = E;
}

__global__ void csr_scatter_kernel(const void* __restrict__ ei, int E) {
    int e = blockIdx.x * blockDim.x + threadIdx.x;
    if (e < E) {
        int c = edge_col(ei, E, e);
        int pos = atomicAdd(&g_csrcur[c], 1);
        g_csrrow[pos] = edge_row(ei, E, e);
    }
}

// ---------------- iter-1 GCN gather from fp32 x ----------------
__global__ void gcn_gather_x_kernel(const float* __restrict__ x, __nv_bfloat16* __restrict__ nxt, int n) {
    int gw = (blockIdx.x * blockDim.x + threadIdx.x) >> 5;
    int lane = threadIdx.x & 31;
    if (gw >= n) return;
    int beg = g_csroff[gw], end = g_csroff[gw + 1];
    float s = 0.5f * g_deginv[gw];
    float4 a = make_float4(0, 0, 0, 0);
    int e = beg;
    for (; e + 4 <= end; e += 4) {
        int s0 = g_csrrow[e], s1 = g_csrrow[e + 1], s2 = g_csrrow[e + 2], s3 = g_csrrow[e + 3];
        float4 v0 = ((const float4*)(x + (size_t)s0 * 128))[lane];
        float4 v1 = ((const float4*)(x + (size_t)s1 * 128))[lane];
        float4 v2 = ((const float4*)(x + (size_t)s2 * 128))[lane];
        float4 v3 = ((const float4*)(x + (size_t)s3 * 128))[lane];
        a.x += (v0.x + v1.x) + (v2.x + v3.x);
        a.y += (v0.y + v1.y) + (v2.y + v3.y);
        a.z += (v0.z + v1.z) + (v2.z + v3.z);
        a.w += (v0.w + v1.w) + (v2.w + v3.w);
    }
    for (; e < end; e++) {
        float4 v0 = ((const float4*)(x + (size_t)g_csrrow[e] * 128))[lane];
        a.x += v0.x; a.y += v0.y; a.z += v0.z; a.w += v0.w;
    }
    uint2 o;
    o.x = packbf(s * a.x, s * a.y);
    o.y = packbf(s * a.z, s * a.w);
    *(uint2*)(nxt + (size_t)gw * 256 + lane * 4)       = o;
    *(uint2*)(nxt + (size_t)gw * 256 + 128 + lane * 4) = o;
}

// ---------------- GCN gather bf16 (high occupancy, 1 warp/row) ----------------
__global__ void gcn_gather_kernel(__nv_bfloat16* __restrict__ nxt, const __nv_bfloat16* __restrict__ prev, int n) {
    int gw = (blockIdx.x * blockDim.x + threadIdx.x) >> 5;
    int lane = threadIdx.x & 31;
    if (gw >= n) return;
    int beg = g_csroff[gw], end = g_csroff[gw + 1];
    float s = 0.5f * g_deginv[gw];
    float a[8];
#pragma unroll
    for (int i = 0; i < 8; i++) a[i] = 0.f;
    int e = beg;
    for (; e + 4 <= end; e += 4) {
        uint4 v0 = *(const uint4*)(prev + (size_t)g_csrrow[e]     * 256 + lane * 8);
        uint4 v1 = *(const uint4*)(prev + (size_t)g_csrrow[e + 1] * 256 + lane * 8);
        uint4 v2 = *(const uint4*)(prev + (size_t)g_csrrow[e + 2] * 256 + lane * 8);
        uint4 v3 = *(const uint4*)(prev + (size_t)g_csrrow[e + 3] * 256 + lane * 8);
#pragma unroll
        for (int p = 0; p < 4; p++) {
            float2 f0 = unpackbf((&v0.x)[p]);
            float2 f1 = unpackbf((&v1.x)[p]);
            float2 f2 = unpackbf((&v2.x)[p]);
            float2 f3 = unpackbf((&v3.x)[p]);
            a[2 * p]     += (f0.x + f1.x) + (f2.x + f3.x);
            a[2 * p + 1] += (f0.y + f1.y) + (f2.y + f3.y);
        }
    }
    for (; e < end; e++) {
        uint4 v0 = *(const uint4*)(prev + (size_t)g_csrrow[e] * 256 + lane * 8);
#pragma unroll
        for (int p = 0; p < 4; p++) {
            float2 f0 = unpackbf((&v0.x)[p]);
            a[2 * p] += f0.x; a[2 * p + 1] += f0.y;
        }
    }
    uint4 o;
    o.x = packbf(s * a[0], s * a[1]);
    o.y = packbf(s * a[2], s * a[3]);
    o.z = packbf(s * a[4], s * a[5]);
    o.w = packbf(s * a[6], s * a[7]);
    *(uint4*)(nxt + (size_t)gw * 256 + lane * 8) = o;
}

// ---------------- q/k projection GEMM (tf32) + fused L2 norm -> bf16 only ----------------
__global__ void __launch_bounds__(256) qk_gemm_kernel(const float* __restrict__ x,
                               const float* __restrict__ Wq, const float* __restrict__ Wqb,
                               const float* __restrict__ Wk, const float* __restrict__ Wkb,
                               int n) {
    __shared__ uint32_t As[16][128];
    __shared__ uint32_t Bs[16][128];
    __shared__ float rowss[128];
    int t = threadIdx.x;
    int lane = t & 31, wid = t >> 5;
    int m0 = (wid & 1) * 64, n0 = (wid >> 1) * 32;
    int bm0 = blockIdx.x * 128;
    int by = blockIdx.y;
    const float* B   = (by < 2) ? Wq  : Wk;
    const float* bia = (by < 2) ? Wqb : Wkb;
    __nv_bfloat16* dst = (by < 2) ? g_q16 : g_k16;
    int coff = (by & 1) * 128;
    int am = t >> 1, akq = (t & 1) * 8;
    int bk = t >> 4, bnq = (t & 15) * 8;
    float acc[4][4][4];
#pragma unroll
    for (int i = 0; i < 4; i++)
#pragma unroll
        for (int j = 0; j < 4; j++)
#pragma unroll
            for (int r = 0; r < 4; r++) acc[i][j][r] = 0.f;
    if (t < 128) rowss[t] = 0.f;

    for (int k0 = 0; k0 < 128; k0 += 16) {
        float4 a0 = make_float4(0, 0, 0, 0), a1 = a0;
        int row = bm0 + am;
        if (row < n) {
            const float4* ap = (const float4*)(x + (size_t)row * 128 + k0 + akq);
            a0 = ap[0]; a1 = ap[1];
        }
        const float4* bp = (const float4*)(B + (size_t)(k0 + bk) * 256 + coff + bnq);
        float4 b0 = bp[0], b1 = bp[1];
        __syncthreads();
        As[akq + 0][am] = f2tf(a0.x); As[akq + 1][am] = f2tf(a0.y);
        As[akq + 2][am] = f2tf(a0.z); As[akq + 3][am] = f2tf(a0.w);
        As[akq + 4][am] = f2tf(a1.x); As[akq + 5][am] = f2tf(a1.y);
        As[akq + 6][am] = f2tf(a1.z); As[akq + 7][am] = f2tf(a1.w);
        Bs[bk][bnq + 0] = f2tf(b0.x); Bs[bk][bnq + 1] = f2tf(b0.y);
        Bs[bk][bnq + 2] = f2tf(b0.z); Bs[bk][bnq + 3] = f2tf(b0.w);
        Bs[bk][bnq + 4] = f2tf(b1.x); Bs[bk][bnq + 5] = f2tf(b1.y);
        Bs[bk][bnq + 6] = f2tf(b1.z); Bs[bk][bnq + 7] = f2tf(b1.w);
        __syncthreads();
        ktile_mma(As, Bs, m0, n0, lane, acc);
    }

#pragma unroll
    for (int mt = 0; mt < 4; mt++) {
        float ss0 = 0.f, ss1 = 0.f;
#pragma unroll
        for (int nt = 0; nt < 4; nt++) {
            int col = coff + n0 + nt * 8 + 2 * (lane & 3);
            float bx = bia[col], by2 = bia[col + 1];
            acc[mt][nt][0] += bx; acc[mt][nt][1] += by2;
            acc[mt][nt][2] += bx; acc[mt][nt][3] += by2;
            ss0 += acc[mt][nt][0] * acc[mt][nt][0] + acc[mt][nt][1] * acc[mt][nt][1];
            ss1 += acc[mt][nt][2] * acc[mt][nt][2] + acc[mt][nt][3] * acc[mt][nt][3];
        }
        ss0 += __shfl_xor_sync(0xffffffffu, ss0, 1);
        ss0 += __shfl_xor_sync(0xffffffffu, ss0, 2);
        ss1 += __shfl_xor_sync(0xffffffffu, ss1, 1);
        ss1 += __shfl_xor_sync(0xffffffffu, ss1, 2);
        if ((lane & 3) == 0) {
            int r = m0 + mt * 16 + (lane >> 2);
            atomicAdd(&rowss[r], ss0);
            atomicAdd(&rowss[r + 8], ss1);
        }
    }
    __syncthreads();

#pragma unroll
    for (int mt = 0; mt < 4; mt++) {
        int r = m0 + mt * 16 + (lane >> 2);
        float inv0 = rsqrtf(rowss[r]);
        float inv1 = rsqrtf(rowss[r + 8]);
        int row = bm0 + r;
#pragma unroll
        for (int nt = 0; nt < 4; nt++) {
            int col = coff + n0 + nt * 8 + 2 * (lane & 3);
            if (row < n)
                *(uint32_t*)(dst + (size_t)row * 256 + col) =
                    packbf(acc[mt][nt][0] * inv0, acc[mt][nt][1] * inv0);
            if (row + 8 < n)
                *(uint32_t*)(dst + (size_t)(row + 8) * 256 + col) =
                    packbf(acc[mt][nt][2] * inv1, acc[mt][nt][3] * inv1);
        }
    }
}

// ---------------- ks_sum from bf16 (fp32 accumulate) ----------------
__global__ void kssum_kernel(int n) {
    int col = threadIdx.x;
    int start = blockIdx.x * 512;
    int end = min(start + 512, n);
    float s = 0.f;
    for (int node = start; node < end; node++)
        s += __bfloat162float(g_k16[(size_t)node * 256 + col]);
    atomicAdd(&g_kssum[col], s);
}

// ---------------- den = q16 . ks_sum + n ----------------
__global__ void den_kernel(int n) {
    int gw = (blockIdx.x * blockDim.x + threadIdx.x) >> 5;
    int lane = threadIdx.x & 31;
    if (gw >= n * 2) return;
    int node = gw >> 1, h = gw & 1;
    uint2 qu = *(const uint2*)(g_q16 + (size_t)node * 256 + h * 128 + lane * 4);
    float2 qa = unpackbf(qu.x), qb = unpackbf(qu.y);
    float4 kv = ((const float4*)(g_kssum + h * 128))[lane];
    float d = qa.x * kv.x + qa.y * kv.y + qb.x * kv.z + qb.y * kv.w;
#pragma unroll
    for (int o = 16; o; o >>= 1) d += __shfl_xor_sync(0xffffffffu, d, o);
    if (lane == 0) g_den[node * 2 + h] = d + (float)n;
}

// ---------------- out init (tf32): 0.5*(x @ (Wo[h0,k0]+Wo[h1,k0]) + b) ----------------
__global__ void __launch_bounds__(256) out_init_kernel(const float* __restrict__ x, const float* __restrict__ Wo,
                                const float* __restrict__ Wob, float* __restrict__ out, int n) {
    __shared__ uint32_t As[16][128];
    __shared__ uint32_t Bs[16][128];
    int t = threadIdx.x;
    int lane = t & 31, wid = t >> 5;
    int m0 = (wid & 1) * 64, n0 = (wid >> 1) * 32;
    int bm0 = blockIdx.x * 128;
    int am = t >> 1, akq = (t & 1) * 8;
    int bk = t >> 4, bnq = (t & 15) * 8;
    float acc[4][4][4];
#pragma unroll
    for (int i = 0; i < 4; i++)
#pragma unroll
        for (int j = 0; j < 4; j++)
#pragma unroll
            for (int r = 0; r < 4; r++) acc[i][j][r] = 0.f;

    for (int k0 = 0; k0 < 128; k0 += 16) {
        float4 a0 = make_float4(0, 0, 0, 0), a1 = a0;
        int row = bm0 + am;
        if (row < n) {
            const float4* ap = (const float4*)(x + (size_t)row * 128 + k0 + akq);
            a0 = ap[0]; a1 = ap[1];
        }
        int wr = k0 + bk;
        const float4* p0 = (const float4*)(Wo + (size_t)wr * 128 + bnq);
        const float4* p1 = (const float4*)(Wo + (size_t)(640 + wr) * 128 + bnq);
        float4 u0 = p0[0], u1 = p0[1], v0 = p1[0], v1 = p1[1];
        __syncthreads();
        As[akq + 0][am] = f2tf(a0.x); As[akq + 1][am] = f2tf(a0.y);
        As[akq + 2][am] = f2tf(a0.z); As[akq + 3][am] = f2tf(a0.w);
        As[akq + 4][am] = f2tf(a1.x); As[akq + 5][am] = f2tf(a1.y);
        As[akq + 6][am] = f2tf(a1.z); As[akq + 7][am] = f2tf(a1.w);
        Bs[bk][bnq + 0] = f2tf(u0.x + v0.x); Bs[bk][bnq + 1] = f2tf(u0.y + v0.y);
        Bs[bk][bnq + 2] = f2tf(u0.z + v0.z); Bs[bk][bnq + 3] = f2tf(u0.w + v0.w);
        Bs[bk][bnq + 4] = f2tf(u1.x + v1.x); Bs[bk][bnq + 5] = f2tf(u1.y + v1.y);
        Bs[bk][bnq + 6] = f2tf(u1.z + v1.z); Bs[bk][bnq + 7] = f2tf(u1.w + v1.w);
        __syncthreads();
        ktile_mma(As, Bs, m0, n0, lane, acc);
    }
#pragma unroll
    for (int mt = 0; mt < 4; mt++) {
        int row = bm0 + m0 + mt * 16 + (lane >> 2);
#pragma unroll
        for (int nt = 0; nt < 4; nt++) {
            int col = n0 + nt * 8 + 2 * (lane & 3);
            float bx = Wob[col], by2 = Wob[col + 1];
            if (row < n) {
                float2 v = make_float2(0.5f * (acc[mt][nt][0] + bx), 0.5f * (acc[mt][nt][1] + by2));
                *(float2*)&out[(size_t)row * 128 + col] = v;
            }
            if (row + 8 < n) {
                float2 v = make_float2(0.5f * (acc[mt][nt][2] + bx), 0.5f * (acc[mt][nt][3] + by2));
                *(float2*)&out[(size_t)(row + 8) * 128 + col] = v;
            }
        }
    }
}

// ---------------- kvs[h] += ks^T @ prev (bf16 mma) ; vs_sum (fp32) ----------------
// TermSrc=0: prev is bf16 term buffer. TermSrc=1: prev is fp32 x (term0 broadcast).
template <int TermSrc>
__global__ void __launch_bounds__(256) kvs_reduce_t_kernel(const void* __restrict__ prevv, int n) {
    int h = blockIdx.y;
    int c0 = blockIdx.x * 1024;
    int c1 = min(c0 + 1024, n);
    __shared__ uint32_t ksS[16][132];
    __shared__ uint32_t pvS[16][132];
    int t = threadIdx.x;
    int lane = t & 31, wid = t >> 5;
    int m0 = (wid & 1) * 64, n0 = (wid >> 1) * 32;
    float acc[4][4][4];
#pragma unroll
    for (int i = 0; i < 4; i++)
#pragma unroll
        for (int j = 0; j < 4; j++)
#pragma unroll
            for (int r = 0; r < 4; r++) acc[i][j][r] = 0.f;
    float colsum = 0.f;
    int myc = t & 127, hb = (t >> 7) * 8;

    for (int s = c0; s < c1; s += 32) {
        __syncthreads();
#pragma unroll
        for (int i = 0; i < 4; i++) {
            int u = t + 256 * i;
            int nn = u >> 6, m2 = u & 63;
            int nd0 = s + 2 * nn, nd1 = nd0 + 1;
            uint32_t k0 = 0, k1 = 0, p0 = 0, p1 = 0;
            if (nd0 < c1) {
                k0 = *(const uint32_t*)(g_k16 + (size_t)nd0 * 256 + h * 128 + 2 * m2);
                if (TermSrc) {
                    float2 xv = *(const float2*)((const float*)prevv + (size_t)nd0 * 128 + 2 * m2);
                    p0 = packbf(xv.x, xv.y);
                } else {
                    p0 = *(const uint32_t*)((const __nv_bfloat16*)prevv + (size_t)nd0 * 256 + h * 128 + 2 * m2);
                }
            }
            if (nd1 < c1) {
                k1 = *(const uint32_t*)(g_k16 + (size_t)nd1 * 256 + h * 128 + 2 * m2);
                if (TermSrc) {
                    float2 xv = *(const float2*)((const float*)prevv + (size_t)nd1 * 128 + 2 * m2);
                    p1 = packbf(xv.x, xv.y);
                } else {
                    p1 = *(const uint32_t*)((const __nv_bfloat16*)prevv + (size_t)nd1 * 256 + h * 128 + 2 * m2);
                }
            }
            ksS[nn][2 * m2]     = __byte_perm(k0, k1, 0x5410);
            ksS[nn][2 * m2 + 1] = __byte_perm(k0, k1, 0x7632);
            pvS[nn][2 * m2]     = __byte_perm(p0, p1, 0x5410);
            pvS[nn][2 * m2 + 1] = __byte_perm(p0, p1, 0x7632);
        }
        __syncthreads();
        ktile_mma16(ksS, pvS, m0, n0, lane, acc, 2);
#pragma unroll
        for (int r = 0; r < 8; r++) {
            float2 f = unpackbf(pvS[hb + r][myc]);
            colsum += f.x + f.y;
        }
    }
    atomicAdd(&g_vssum[h * 128 + myc], colsum);
    float* kv = g_kvs + h * 16384;
#pragma unroll
    for (int mt = 0; mt < 4; mt++) {
        int m = m0 + mt * 16 + (lane >> 2);
#pragma unroll
        for (int nt = 0; nt < 4; nt++) {
            int c = n0 + nt * 8 + 2 * (lane & 3);
            atomicAdd(&kv[m * 128 + c],           acc[mt][nt][0]);
            atomicAdd(&kv[m * 128 + c + 1],       acc[mt][nt][1]);
            atomicAdd(&kv[(m + 8) * 128 + c],     acc[mt][nt][2]);
            atomicAdd(&kv[(m + 8) * 128 + c + 1], acc[mt][nt][3]);
        }
    }
}

// ---------------- nxt += (qs @ kvs + vs_sum) / den  (bf16 mma, RMW-add) ----------------
__global__ void __launch_bounds__(256) qkv_combine_kernel(__nv_bfloat16* __restrict__ nxt, int n) {
    int h = blockIdx.y;
    __shared__ uint32_t As[32][132];
    __shared__ uint32_t Bs[32][132];
    int t = threadIdx.x;
    int lane = t & 31, wid = t >> 5;
    int m0 = (wid & 1) * 64, n0 = (wid >> 1) * 32;
    int bm0 = blockIdx.x * 128;
    const float* kvp = g_kvs + h * 16384;
    float acc[4][4][4];
#pragma unroll
    for (int i = 0; i < 4; i++)
#pragma unroll
        for (int j = 0; j < 4; j++)
#pragma unroll
            for (int r = 0; r < 4; r++) acc[i][j][r] = 0.f;

#pragma unroll
    for (int kc = 0; kc < 2; kc++) {
        int kb = kc * 64;
        __syncthreads();
#pragma unroll
        for (int i = 0; i < 4; i++) {
            int u = t + 256 * i;
            int row = u >> 3, q = u & 7;
            uint4 v = make_uint4(0, 0, 0, 0);
            if (bm0 + row < n)
                v = *(const uint4*)(g_q16 + (size_t)(bm0 + row) * 256 + h * 128 + kb + q * 8);
            As[q * 4 + 0][row] = v.x; As[q * 4 + 1][row] = v.y;
            As[q * 4 + 2][row] = v.z; As[q * 4 + 3][row] = v.w;
        }
#pragma unroll
        for (int i = 0; i < 16; i++) {
            int u = t + 256 * i;
            int d = u & 127, m2 = u >> 7;
            int m = kb + 2 * m2;
            Bs[m2][d] = packbf(kvp[m * 128 + d], kvp[(m + 1) * 128 + d]);
        }
        __syncthreads();
        ktile_mma16((const uint32_t(*)[132])As, (const uint32_t(*)[132])Bs, m0, n0, lane, acc, 4);
    }
#pragma unroll
    for (int mt = 0; mt < 4; mt++) {
        int row = bm0 + m0 + mt * 16 + (lane >> 2);
#pragma unroll
        for (int nt = 0; nt < 4; nt++) {
            int col = n0 + nt * 8 + 2 * (lane & 3);
            float vs0 = g_vssum[h * 128 + col], vs1 = g_vssum[h * 128 + col + 1];
            if (row < n) {
                float invd = 1.0f / g_den[row * 2 + h];
                uint32_t* p = (uint32_t*)(nxt + (size_t)row * 256 + h * 128 + col);
                float2 old = unpackbf(*p);
                *p = packbf(old.x + (acc[mt][nt][0] + vs0) * invd,
                            old.y + (acc[mt][nt][1] + vs1) * invd);
            }
            if (row + 8 < n) {
                float invd = 1.0f / g_den[(row + 8) * 2 + h];
                uint32_t* p = (uint32_t*)(nxt + (size_t)(row + 8) * 256 + h * 128 + col);
                float2 old = unpackbf(*p);
                *p = packbf(old.x + (acc[mt][nt][2] + vs0) * invd,
                            old.y + (acc[mt][nt][3] + vs1) * invd);
            }
        }
    }
}

// ---------------- out += 0.5 * term_k @ Wo_slice(k) (bf16 mma) ----------------
__global__ void __launch_bounds__(256) out_accum_kernel(const __nv_bfloat16* __restrict__ term,
                                 const float* __restrict__ Wo,
                                 float* __restrict__ out, int n, int ksl) {
    __shared__ uint32_t As[32][132];
    __shared__ uint32_t Bs[32][132];
    int t = threadIdx.x;
    int lane = t & 31, wid = t >> 5;
    int m0 = (wid & 1) * 64, n0 = (wid >> 1) * 32;
    int bm0 = blockIdx.x * 128;
    float acc[4][4][4];
#pragma unroll
    for (int i = 0; i < 4; i++)
#pragma unroll
        for (int j = 0; j < 4; j++)
#pragma unroll
            for (int r = 0; r < 4; r++) acc[i][j][r] = 0.f;

#pragma unroll
    for (int kc = 0; kc < 4; kc++) {
        int kb = kc * 64;
        __syncthreads();
#pragma unroll
        for (int i = 0; i < 4; i++) {
            int u = t + 256 * i;
            int row = u >> 3, q = u & 7;
            uint4 v = make_uint4(0, 0, 0, 0);
            if (bm0 + row < n)
                v = *(const uint4*)(term + (size_t)(bm0 + row) * 256 + kb + q * 8);
            As[q * 4 + 0][row] = v.x; As[q * 4 + 1][row] = v.y;
            As[q * 4 + 2][row] = v.z; As[q * 4 + 3][row] = v.w;
        }
#pragma unroll
        for (int i = 0; i < 16; i++) {
            int u = t + 256 * i;
            int c = u & 127, j2 = u >> 7;
            int j = kb + 2 * j2;
            int wrow = ((j >> 7) * 640) + ksl * 128 + (j & 127);
            Bs[j2][c] = packbf(Wo[(size_t)wrow * 128 + c], Wo[(size_t)(wrow + 1) * 128 + c]);
        }
        __syncthreads();
        ktile_mma16((const uint32_t(*)[132])As, (const uint32_t(*)[132])Bs, m0, n0, lane, acc, 4);
    }
#pragma unroll
    for (int mt = 0; mt < 4; mt++) {
        int row = bm0 + m0 + mt * 16 + (lane >> 2);
#pragma unroll
        for (int nt = 0; nt < 4; nt++) {
            int col = n0 + nt * 8 + 2 * (lane & 3);
            if (row < n) {
                float2 c = *(float2*)&out[(size_t)row * 128 + col];
                c.x += 0.5f * acc[mt][nt][0];
                c.y += 0.5f * acc[mt][nt][1];
                *(float2*)&out[(size_t)row * 128 + col] = c;
            }
            if (row + 8 < n) {
                float2 c = *(float2*)&out[(size_t)(row + 8) * 128 + col];
                c.x += 0.5f * acc[mt][nt][2];
                c.y += 0.5f * acc[mt][nt][3];
                *(float2*)&out[(size_t)(row + 8) * 128 + col] = c;
            }
        }
    }
}

// ---------------- host orchestration ----------------
extern "C" void kernel_launch(void* const* d_in, const int* in_sizes, int n_in,
                              void* d_out, int out_size) {
    const float* x   = (const float*)d_in[0];
    const void*  ei  = d_in[1];
    const float* Wqw = (const float*)d_in[2];
    const float* Wqb = (const float*)d_in[3];
    const float* Wkw = (const float*)d_in[4];
    const float* Wkb = (const float*)d_in[5];
    const float* Wow = (const float*)d_in[6];
    const float* Wob = (const float*)d_in[7];
    float* out = (float*)d_out;

    int n = in_sizes[0] / CC;
    int E = in_sizes[1] / 2;

    void *pDeg, *pKvs, *pVs, *pKs, *pA16, *pB16;
    cudaGetSymbolAddress(&pDeg, g_deg);
    cudaGetSymbolAddress(&pKvs, g_kvs);
    cudaGetSymbolAddress(&pVs,  g_vssum);
    cudaGetSymbolAddress(&pKs,  g_kssum);
    cudaGetSymbolAddress(&pA16, g_tA16);
    cudaGetSymbolAddress(&pB16, g_tB16);

    // streams/events created once (host-side resources, not device allocations)
    static int inited = 0;
    static cudaStream_t sB, sC;
    static cudaEvent_t evQ[5], evB[5], evC[5];
    if (!inited) {
        cudaStreamCreateWithFlags(&sB, cudaStreamNonBlocking);
        cudaStreamCreateWithFlags(&sC, cudaStreamNonBlocking);
        for (int i = 0; i < 5; i++) {
            cudaEventCreateWithFlags(&evQ[i], cudaEventDisableTiming);
            cudaEventCreateWithFlags(&evB[i], cudaEventDisableTiming);
            cudaEventCreateWithFlags(&evC[i], cudaEventDisableTiming);
        }
        inited = 1;
    }

    // ---- edge prep (stream 0) ----
    int nbScan = (n + 1023) / 1024;
    cudaMemsetAsync(pDeg, 0, (size_t)n * sizeof(int));
    detect_dtype_kernel<<<1, 256>>>((const int*)ei, in_sizes[1]);
    edge_deg_kernel<<<(E + 255) / 256, 256>>>(ei, E);
    scan_blocks_kernel<<<nbScan, 1024>>>(n);
    scan_tops_kernel<<<1, 128>>>(nbScan);
    scan_apply_kernel<<<(n + 255) / 256, 256>>>(n, E);
    csr_scatter_kernel<<<(E + 255) / 256, 256>>>(ei, E);
    gcn_gather_x_kernel<<<(n * 32 + 255) / 256, 256>>>(x, (__nv_bfloat16*)pB16, n);

    // ---- projections + invariants (stream 0) ----
    dim3 gqk((n + 127) / 128, 4);
    qk_gemm_kernel<<<gqk, 256>>>(x, Wqw, Wqb, Wkw, Wkb, n);
    cudaMemsetAsync(pKs, 0, (size_t)HH * CC * sizeof(float));
    kssum_kernel<<<(n + 511) / 512, 256>>>(n);
    den_kernel<<<(n * 2 * 32 + 255) / 256, 256>>>(n);
    out_init_kernel<<<(n + 127) / 128, 256>>>(x, Wow, Wob, out, n);

    int nb  = (n + 127) / 128;
    int nkv = (n + 1023) / 1024;

    // ---- iter 1: kvs from x directly (term0 == broadcast x), gather done in prologue ----
    cudaMemsetAsync(pKvs, 0, (size_t)HH * CC * CC * sizeof(float));
    cudaMemsetAsync(pVs,  0, (size_t)HH * CC * sizeof(float));
    kvs_reduce_t_kernel<1><<<dim3(nkv, 2), 256>>>(x, n);
    qkv_combine_kernel<<<dim3(nb, 2), 256>>>((__nv_bfloat16*)pB16, n);
    cudaEventRecord(evQ[1], 0);
    cudaStreamWaitEvent(sB, evQ[1], 0);
    out_accum_kernel<<<nb, 256, 0, sB>>>((const __nv_bfloat16*)pB16, Wow, out, n, 1);
    cudaEventRecord(evB[1], sB);

    // ---- iters 2..4: gather on sC || kvs_reduce on 0 ; out_accum on sB ----
    __nv_bfloat16* prev = (__nv_bfloat16*)pB16;
    __nv_bfloat16* nxt  = (__nv_bfloat16*)pA16;
    for (int ksl = 2; ksl <= 4; ksl++) {
        cudaStreamWaitEvent(sC, evQ[ksl - 1], 0);
        if (ksl >= 3)  // WAR: gather(k) overwrites the buffer out_accum(k-2) read
            cudaStreamWaitEvent(sC, evB[ksl - 2], 0);
        gcn_gather_kernel<<<(n * 32 + 255) / 256, 256, 0, sC>>>(nxt, prev, n);
        cudaEventRecord(evC[ksl], sC);

        cudaMemsetAsync(pKvs, 0, (size_t)HH * CC * CC * sizeof(float));
        cudaMemsetAsync(pVs,  0, (size_t)HH * CC * sizeof(float));
        kvs_reduce_t_kernel<0><<<dim3(nkv, 2), 256>>>(prev, n);

        cudaStreamWaitEvent(0, evC[ksl], 0);
        qkv_combine_kernel<<<dim3(nb, 2), 256>>>(nxt, n);
        cudaEventRecord(evQ[ksl], 0);

        cudaStreamWaitEvent(sB, evQ[ksl], 0);
        out_accum_kernel<<<nb, 256, 0, sB>>>(nxt, Wow, out, n, ksl);
        cudaEventRecord(evB[ksl], sB);

        __nv_bfloat16* tmp = prev; prev = nxt; nxt = tmp;
    }

    // join all forked work back to stream 0 before capture ends
    cudaStreamWaitEvent(0, evB[4], 0);
}

// round 9
// speedup vs baseline: 1.2084x; 1.0084x over previous
#include <cuda_runtime.h>
#include <cuda_bf16.h>
#include <cstdint>

#define CC   128
#define HH   2
#define HC   256
#define NMAX 100000
#define EMAX 1600000

// ---------------- device scratch (static, no allocation) ----------------
__device__ __nv_bfloat16 g_q16[(size_t)NMAX * HC];
__device__ __nv_bfloat16 g_k16[(size_t)NMAX * HC];
__device__ __nv_bfloat16 g_tA16[(size_t)NMAX * HC];  // term ping (bf16)
__device__ __nv_bfloat16 g_tB16[(size_t)NMAX * HC];  // term pong (bf16)
__device__ float g_deginv[NMAX];
__device__ int   g_deg[NMAX];
__device__ int   g_csroff[NMAX + 1];
__device__ int   g_csrcur[NMAX];
__device__ int   g_csrrow[EMAX];
__device__ int   g_blocksum[128];
__device__ float g_den[NMAX * HH];
__device__ float g_kvs[HH * CC * CC];
__device__ float g_vssum[HH * CC];
__device__ float g_kssum[HH * CC];
__device__ int   g_is64;

// ---------------- helpers ----------------
__device__ __forceinline__ uint32_t f2tf(float x) {
    uint32_t r;
    asm("cvt.rna.tf32.f32 %0, %1;" : "=r"(r) : "f"(x));
    return r;
}
__device__ __forceinline__ uint32_t packbf(float lo, float hi) {
    __nv_bfloat162 h2 = __floats2bfloat162_rn(lo, hi);
    return *reinterpret_cast<uint32_t*>(&h2);
}
__device__ __forceinline__ float2 unpackbf(uint32_t u) {
    __nv_bfloat162 h2 = *reinterpret_cast<__nv_bfloat162*>(&u);
    return __bfloat1622float2(h2);
}

__device__ __forceinline__ void mma16(float* c, uint32_t a0, uint32_t a1, uint32_t a2,
                                      uint32_t a3, uint32_t b0, uint32_t b1) {
    asm volatile(
        "mma.sync.aligned.m16n8k16.row.col.f32.bf16.bf16.f32 "
        "{%0,%1,%2,%3},{%4,%5,%6,%7},{%8,%9},{%0,%1,%2,%3};"
        : "+f"(c[0]), "+f"(c[1]), "+f"(c[2]), "+f"(c[3])
        : "r"(a0), "r"(a1), "r"(a2), "r"(a3), "r"(b0), "r"(b1));
}

// tf32 m16n8k8 over a 16-deep k tile (k-major [16][128])
__device__ __forceinline__ void ktile_mma(const uint32_t (*As)[128], const uint32_t (*Bs)[128],
                                          int m0, int n0, int lane, float acc[4][4][4]) {
#pragma unroll
    for (int ks = 0; ks < 2; ks++) {
        int ar = ks * 8 + (lane & 3);
        int ac = lane >> 2;
        uint32_t a[4][4], b[4][2];
#pragma unroll
        for (int mt = 0; mt < 4; mt++) {
            int m = m0 + mt * 16 + ac;
            a[mt][0] = As[ar][m];
            a[mt][1] = As[ar][m + 8];
            a[mt][2] = As[ar + 4][m];
            a[mt][3] = As[ar + 4][m + 8];
        }
#pragma unroll
        for (int nt = 0; nt < 4; nt++) {
            int nn = n0 + nt * 8 + ac;
            b[nt][0] = Bs[ar][nn];
            b[nt][1] = Bs[ar + 4][nn];
        }
#pragma unroll
        for (int mt = 0; mt < 4; mt++)
#pragma unroll
            for (int nt = 0; nt < 4; nt++)
                asm volatile(
                    "mma.sync.aligned.m16n8k8.row.col.f32.tf32.tf32.f32 "
                    "{%0,%1,%2,%3},{%4,%5,%6,%7},{%8,%9},{%0,%1,%2,%3};"
                    : "+f"(acc[mt][nt][0]), "+f"(acc[mt][nt][1]),
                      "+f"(acc[mt][nt][2]), "+f"(acc[mt][nt][3])
                    : "r"(a[mt][0]), "r"(a[mt][1]), "r"(a[mt][2]), "r"(a[mt][3]),
                      "r"(b[nt][0]), "r"(b[nt][1]));
    }
}

// bf16 m16n8k16, smem pair-packed along k: S[k2][m], stride 132
__device__ __forceinline__ void ktile_mma16(const uint32_t (*As)[132], const uint32_t (*Bs)[132],
                                            int m0, int n0, int lane, float acc[4][4][4], int ksteps) {
    for (int ks = 0; ks < ksteps; ks++) {
        int ar = ks * 8 + (lane & 3);
        int ac = lane >> 2;
        uint32_t a[4][4], b[4][2];
#pragma unroll
        for (int mt = 0; mt < 4; mt++) {
            int m = m0 + mt * 16 + ac;
            a[mt][0] = As[ar][m];
            a[mt][1] = As[ar][m + 8];
            a[mt][2] = As[ar + 4][m];
            a[mt][3] = As[ar + 4][m + 8];
        }
#pragma unroll
        for (int nt = 0; nt < 4; nt++) {
            int nn = n0 + nt * 8 + ac;
            b[nt][0] = Bs[ar][nn];
            b[nt][1] = Bs[ar + 4][nn];
        }
#pragma unroll
        for (int mt = 0; mt < 4; mt++)
#pragma unroll
            for (int nt = 0; nt < 4; nt++)
                mma16(acc[mt][nt], a[mt][0], a[mt][1], a[mt][2], a[mt][3], b[nt][0], b[nt][1]);
    }
}

// ---------------- edge dtype detection ----------------
__global__ void detect_dtype_kernel(const int* __restrict__ ei32, int twoE) {
    __shared__ int nz;
    if (threadIdx.x == 0) nz = 0;
    __syncthreads();
    int samples = min(1024, twoE / 2);
    int local = 0;
    for (int i = threadIdx.x; i < samples; i += blockDim.x)
        if (ei32[2 * i + 1] != 0) local++;
    if (local) atomicAdd(&nz, local);
    __syncthreads();
    if (threadIdx.x == 0) g_is64 = (nz == 0) ? 1 : 0;
}

__device__ __forceinline__ int edge_col(const void* ei, int E, int e) {
    if (g_is64) return (int)((const long long*)ei)[(size_t)E + e];
    return ((const int*)ei)[E + e];
}
__device__ __forceinline__ int edge_row(const void* ei, int E, int e) {
    if (g_is64) return (int)((const long long*)ei)[e];
    return ((const int*)ei)[e];
}

// ---------------- edge prep ----------------
__global__ void edge_deg_kernel(const void* __restrict__ ei, int E) {
    int e = blockIdx.x * blockDim.x + threadIdx.x;
    if (e < E) atomicAdd(&g_deg[edge_col(ei, E, e)], 1);
}

__global__ void scan_blocks_kernel(int n) {
    __shared__ int sh[1024];
    int i = blockIdx.x * 1024 + threadIdx.x;
    int v = (i < n) ? g_deg[i] : 0;
    sh[threadIdx.x] = v;
    __syncthreads();
    for (int off = 1; off < 1024; off <<= 1) {
        int t = (threadIdx.x >= off) ? sh[threadIdx.x - off] : 0;
        __syncthreads();
        sh[threadIdx.x] += t;
        __syncthreads();
    }
    if (i < n) g_csroff[i] = sh[threadIdx.x] - v;
    if (threadIdx.x == 1023) g_blocksum[blockIdx.x] = sh[1023];
}

__global__ void scan_tops_kernel(int nb) {
    __shared__ int sh[128];
    int v = (threadIdx.x < nb) ? g_blocksum[threadIdx.x] : 0;
    sh[threadIdx.x] = v;
    __syncthreads();
    for (int off = 1; off < 128; off <<= 1) {
        int t = (threadIdx.x >= off) ? sh[threadIdx.x - off] : 0;
        __syncthreads();
        sh[threadIdx.x] += t;
        __syncthreads();
    }
    if (threadIdx.x < nb) g_blocksum[threadIdx.x] = sh[threadIdx.x] - v;
}

__global__ void scan_apply_kernel(int n, int E) {
    int i = blockIdx.x * blockDim.x + threadIdx.x;
    if (i < n) {
        int off = g_csroff[i] + g_blocksum[i >> 10];
        g_csroff[i] = off;
        g_csrcur[i] = off;
        int d = g_deg[i];
        g_deginv[i] = (d > 0) ? 1.0f / (float)d : 0.0f;
    }
    if (i == 0) g_csroff[n] = E;
}

__global__ void csr_scatter_kernel(const void* __restrict__ ei, int E) {
    int e = blockIdx.x * blockDim.x + threadIdx.x;
    if (e < E) {
        int c = edge_col(ei, E, e);
        int pos = atomicAdd(&g_csrcur[c], 1);
        g_csrrow[pos] = edge_row(ei, E, e);
    }
}

// ---------------- iter-1 GCN gather from fp32 x ----------------
__global__ void gcn_gather_x_kernel(const float* __restrict__ x, __nv_bfloat16* __restrict__ nxt, int n) {
    int gw = (blockIdx.x * blockDim.x + threadIdx.x) >> 5;
    int lane = threadIdx.x & 31;
    if (gw >= n) return;
    int beg = g_csroff[gw], end = g_csroff[gw + 1];
    float s = 0.5f * g_deginv[gw];
    float4 a = make_float4(0, 0, 0, 0);
    int e = beg;
    for (; e + 4 <= end; e += 4) {
        int s0 = g_csrrow[e], s1 = g_csrrow[e + 1], s2 = g_csrrow[e + 2], s3 = g_csrrow[e + 3];
        float4 v0 = ((const float4*)(x + (size_t)s0 * 128))[lane];
        float4 v1 = ((const float4*)(x + (size_t)s1 * 128))[lane];
        float4 v2 = ((const float4*)(x + (size_t)s2 * 128))[lane];
        float4 v3 = ((const float4*)(x + (size_t)s3 * 128))[lane];
        a.x += (v0.x + v1.x) + (v2.x + v3.x);
        a.y += (v0.y + v1.y) + (v2.y + v3.y);
        a.z += (v0.z + v1.z) + (v2.z + v3.z);
        a.w += (v0.w + v1.w) + (v2.w + v3.w);
    }
    for (; e < end; e++) {
        float4 v0 = ((const float4*)(x + (size_t)g_csrrow[e] * 128))[lane];
        a.x += v0.x; a.y += v0.y; a.z += v0.z; a.w += v0.w;
    }
    uint2 o;
    o.x = packbf(s * a.x, s * a.y);
    o.y = packbf(s * a.z, s * a.w);
    *(uint2*)(nxt + (size_t)gw * 256 + lane * 4)       = o;
    *(uint2*)(nxt + (size_t)gw * 256 + 128 + lane * 4) = o;
}

// ---------------- GCN gather bf16 (high occupancy, 1 warp/row) ----------------
__global__ void gcn_gather_kernel(__nv_bfloat16* __restrict__ nxt, const __nv_bfloat16* __restrict__ prev, int n) {
    int gw = (blockIdx.x * blockDim.x + threadIdx.x) >> 5;
    int lane = threadIdx.x & 31;
    if (gw >= n) return;
    int beg = g_csroff[gw], end = g_csroff[gw + 1];
    float s = 0.5f * g_deginv[gw];
    float a[8];
#pragma unroll
    for (int i = 0; i < 8; i++) a[i] = 0.f;
    int e = beg;
    for (; e + 4 <= end; e += 4) {
        uint4 v0 = *(const uint4*)(prev + (size_t)g_csrrow[e]     * 256 + lane * 8);
        uint4 v1 = *(const uint4*)(prev + (size_t)g_csrrow[e + 1] * 256 + lane * 8);
        uint4 v2 = *(const uint4*)(prev + (size_t)g_csrrow[e + 2] * 256 + lane * 8);
        uint4 v3 = *(const uint4*)(prev + (size_t)g_csrrow[e + 3] * 256 + lane * 8);
#pragma unroll
        for (int p = 0; p < 4; p++) {
            float2 f0 = unpackbf((&v0.x)[p]);
            float2 f1 = unpackbf((&v1.x)[p]);
            float2 f2 = unpackbf((&v2.x)[p]);
            float2 f3 = unpackbf((&v3.x)[p]);
            a[2 * p]     += (f0.x + f1.x) + (f2.x + f3.x);
            a[2 * p + 1] += (f0.y + f1.y) + (f2.y + f3.y);
        }
    }
    for (; e < end; e++) {
        uint4 v0 = *(const uint4*)(prev + (size_t)g_csrrow[e] * 256 + lane * 8);
#pragma unroll
        for (int p = 0; p < 4; p++) {
            float2 f0 = unpackbf((&v0.x)[p]);
            a[2 * p] += f0.x; a[2 * p + 1] += f0.y;
        }
    }
    uint4 o;
    o.x = packbf(s * a[0], s * a[1]);
    o.y = packbf(s * a[2], s * a[3]);
    o.z = packbf(s * a[4], s * a[5]);
    o.w = packbf(s * a[6], s * a[7]);
    *(uint4*)(nxt + (size_t)gw * 256 + lane * 8) = o;
}

// ---------------- q/k projection GEMM (tf32) + fused L2 norm -> bf16 only ----------------
__global__ void __launch_bounds__(256) qk_gemm_kernel(const float* __restrict__ x,
                               const float* __restrict__ Wq, const float* __restrict__ Wqb,
                               const float* __restrict__ Wk, const float* __restrict__ Wkb,
                               int n) {
    __shared__ uint32_t As[16][128];
    __shared__ uint32_t Bs[16][128];
    __shared__ float rowss[128];
    int t = threadIdx.x;
    int lane = t & 31, wid = t >> 5;
    int m0 = (wid & 1) * 64, n0 = (wid >> 1) * 32;
    int bm0 = blockIdx.x * 128;
    int by = blockIdx.y;
    const float* B   = (by < 2) ? Wq  : Wk;
    const float* bia = (by < 2) ? Wqb : Wkb;
    __nv_bfloat16* dst = (by < 2) ? g_q16 : g_k16;
    int coff = (by & 1) * 128;
    int am = t >> 1, akq = (t & 1) * 8;
    int bk = t >> 4, bnq = (t & 15) * 8;
    float acc[4][4][4];
#pragma unroll
    for (int i = 0; i < 4; i++)
#pragma unroll
        for (int j = 0; j < 4; j++)
#pragma unroll
            for (int r = 0; r < 4; r++) acc[i][j][r] = 0.f;
    if (t < 128) rowss[t] = 0.f;

    for (int k0 = 0; k0 < 128; k0 += 16) {
        float4 a0 = make_float4(0, 0, 0, 0), a1 = a0;
        int row = bm0 + am;
        if (row < n) {
            const float4* ap = (const float4*)(x + (size_t)row * 128 + k0 + akq);
            a0 = ap[0]; a1 = ap[1];
        }
        const float4* bp = (const float4*)(B + (size_t)(k0 + bk) * 256 + coff + bnq);
        float4 b0 = bp[0], b1 = bp[1];
        __syncthreads();
        As[akq + 0][am] = f2tf(a0.x); As[akq + 1][am] = f2tf(a0.y);
        As[akq + 2][am] = f2tf(a0.z); As[akq + 3][am] = f2tf(a0.w);
        As[akq + 4][am] = f2tf(a1.x); As[akq + 5][am] = f2tf(a1.y);
        As[akq + 6][am] = f2tf(a1.z); As[akq + 7][am] = f2tf(a1.w);
        Bs[bk][bnq + 0] = f2tf(b0.x); Bs[bk][bnq + 1] = f2tf(b0.y);
        Bs[bk][bnq + 2] = f2tf(b0.z); Bs[bk][bnq + 3] = f2tf(b0.w);
        Bs[bk][bnq + 4] = f2tf(b1.x); Bs[bk][bnq + 5] = f2tf(b1.y);
        Bs[bk][bnq + 6] = f2tf(b1.z); Bs[bk][bnq + 7] = f2tf(b1.w);
        __syncthreads();
        ktile_mma(As, Bs, m0, n0, lane, acc);
    }

#pragma unroll
    for (int mt = 0; mt < 4; mt++) {
        float ss0 = 0.f, ss1 = 0.f;
#pragma unroll
        for (int nt = 0; nt < 4; nt++) {
            int col = coff + n0 + nt * 8 + 2 * (lane & 3);
            float bx = bia[col], by2 = bia[col + 1];
            acc[mt][nt][0] += bx; acc[mt][nt][1] += by2;
            acc[mt][nt][2] += bx; acc[mt][nt][3] += by2;
            ss0 += acc[mt][nt][0] * acc[mt][nt][0] + acc[mt][nt][1] * acc[mt][nt][1];
            ss1 += acc[mt][nt][2] * acc[mt][nt][2] + acc[mt][nt][3] * acc[mt][nt][3];
        }
        ss0 += __shfl_xor_sync(0xffffffffu, ss0, 1);
        ss0 += __shfl_xor_sync(0xffffffffu, ss0, 2);
        ss1 += __shfl_xor_sync(0xffffffffu, ss1, 1);
        ss1 += __shfl_xor_sync(0xffffffffu, ss1, 2);
        if ((lane & 3) == 0) {
            int r = m0 + mt * 16 + (lane >> 2);
            atomicAdd(&rowss[r], ss0);
            atomicAdd(&rowss[r + 8], ss1);
        }
    }
    __syncthreads();

#pragma unroll
    for (int mt = 0; mt < 4; mt++) {
        int r = m0 + mt * 16 + (lane >> 2);
        float inv0 = rsqrtf(rowss[r]);
        float inv1 = rsqrtf(rowss[r + 8]);
        int row = bm0 + r;
#pragma unroll
        for (int nt = 0; nt < 4; nt++) {
            int col = coff + n0 + nt * 8 + 2 * (lane & 3);
            if (row < n)
                *(uint32_t*)(dst + (size_t)row * 256 + col) =
                    packbf(acc[mt][nt][0] * inv0, acc[mt][nt][1] * inv0);
            if (row + 8 < n)
                *(uint32_t*)(dst + (size_t)(row + 8) * 256 + col) =
                    packbf(acc[mt][nt][2] * inv1, acc[mt][nt][3] * inv1);
        }
    }
}

// ---------------- ks_sum from bf16 (fp32 accumulate) ----------------
__global__ void kssum_kernel(int n) {
    int col = threadIdx.x;
    int start = blockIdx.x * 512;
    int end = min(start + 512, n);
    float s = 0.f;
    for (int node = start; node < end; node++)
        s += __bfloat162float(g_k16[(size_t)node * 256 + col]);
    atomicAdd(&g_kssum[col], s);
}

// ---------------- den = q16 . ks_sum + n ----------------
__global__ void den_kernel(int n) {
    int gw = (blockIdx.x * blockDim.x + threadIdx.x) >> 5;
    int lane = threadIdx.x & 31;
    if (gw >= n * 2) return;
    int node = gw >> 1, h = gw & 1;
    uint2 qu = *(const uint2*)(g_q16 + (size_t)node * 256 + h * 128 + lane * 4);
    float2 qa = unpackbf(qu.x), qb = unpackbf(qu.y);
    float4 kv = ((const float4*)(g_kssum + h * 128))[lane];
    float d = qa.x * kv.x + qa.y * kv.y + qb.x * kv.z + qb.y * kv.w;
#pragma unroll
    for (int o = 16; o; o >>= 1) d += __shfl_xor_sync(0xffffffffu, d, o);
    if (lane == 0) g_den[node * 2 + h] = d + (float)n;
}

// ---------------- out init (tf32): 0.5*(x @ (Wo[h0,k0]+Wo[h1,k0]) + b) ----------------
__global__ void __launch_bounds__(256) out_init_kernel(const float* __restrict__ x, const float* __restrict__ Wo,
                                const float* __restrict__ Wob, float* __restrict__ out, int n) {
    __shared__ uint32_t As[16][128];
    __shared__ uint32_t Bs[16][128];
    int t = threadIdx.x;
    int lane = t & 31, wid = t >> 5;
    int m0 = (wid & 1) * 64, n0 = (wid >> 1) * 32;
    int bm0 = blockIdx.x * 128;
    int am = t >> 1, akq = (t & 1) * 8;
    int bk = t >> 4, bnq = (t & 15) * 8;
    float acc[4][4][4];
#pragma unroll
    for (int i = 0; i < 4; i++)
#pragma unroll
        for (int j = 0; j < 4; j++)
#pragma unroll
            for (int r = 0; r < 4; r++) acc[i][j][r] = 0.f;

    for (int k0 = 0; k0 < 128; k0 += 16) {
        float4 a0 = make_float4(0, 0, 0, 0), a1 = a0;
        int row = bm0 + am;
        if (row < n) {
            const float4* ap = (const float4*)(x + (size_t)row * 128 + k0 + akq);
            a0 = ap[0]; a1 = ap[1];
        }
        int wr = k0 + bk;
        const float4* p0 = (const float4*)(Wo + (size_t)wr * 128 + bnq);
        const float4* p1 = (const float4*)(Wo + (size_t)(640 + wr) * 128 + bnq);
        float4 u0 = p0[0], u1 = p0[1], v0 = p1[0], v1 = p1[1];
        __syncthreads();
        As[akq + 0][am] = f2tf(a0.x); As[akq + 1][am] = f2tf(a0.y);
        As[akq + 2][am] = f2tf(a0.z); As[akq + 3][am] = f2tf(a0.w);
        As[akq + 4][am] = f2tf(a1.x); As[akq + 5][am] = f2tf(a1.y);
        As[akq + 6][am] = f2tf(a1.z); As[akq + 7][am] = f2tf(a1.w);
        Bs[bk][bnq + 0] = f2tf(u0.x + v0.x); Bs[bk][bnq + 1] = f2tf(u0.y + v0.y);
        Bs[bk][bnq + 2] = f2tf(u0.z + v0.z); Bs[bk][bnq + 3] = f2tf(u0.w + v0.w);
        Bs[bk][bnq + 4] = f2tf(u1.x + v1.x); Bs[bk][bnq + 5] = f2tf(u1.y + v1.y);
        Bs[bk][bnq + 6] = f2tf(u1.z + v1.z); Bs[bk][bnq + 7] = f2tf(u1.w + v1.w);
        __syncthreads();
        ktile_mma(As, Bs, m0, n0, lane, acc);
    }
#pragma unroll
    for (int mt = 0; mt < 4; mt++) {
        int row = bm0 + m0 + mt * 16 + (lane >> 2);
#pragma unroll
        for (int nt = 0; nt < 4; nt++) {
            int col = n0 + nt * 8 + 2 * (lane & 3);
            float bx = Wob[col], by2 = Wob[col + 1];
            if (row < n) {
                float2 v = make_float2(0.5f * (acc[mt][nt][0] + bx), 0.5f * (acc[mt][nt][1] + by2));
                *(float2*)&out[(size_t)row * 128 + col] = v;
            }
            if (row + 8 < n) {
                float2 v = make_float2(0.5f * (acc[mt][nt][2] + bx), 0.5f * (acc[mt][nt][3] + by2));
                *(float2*)&out[(size_t)(row + 8) * 128 + col] = v;
            }
        }
    }
}

// ---------------- kvs[h] += ks^T @ prev (bf16 mma) ; vs_sum (fp32) ----------------
template <int TermSrc>
__global__ void __launch_bounds__(256) kvs_reduce_t_kernel(const void* __restrict__ prevv, int n) {
    int h = blockIdx.y;
    int c0 = blockIdx.x * 1024;
    int c1 = min(c0 + 1024, n);
    __shared__ uint32_t ksS[16][132];
    __shared__ uint32_t pvS[16][132];
    int t = threadIdx.x;
    int lane = t & 31, wid = t >> 5;
    int m0 = (wid & 1) * 64, n0 = (wid >> 1) * 32;
    float acc[4][4][4];
#pragma unroll
    for (int i = 0; i < 4; i++)
#pragma unroll
        for (int j = 0; j < 4; j++)
#pragma unroll
            for (int r = 0; r < 4; r++) acc[i][j][r] = 0.f;
    float colsum = 0.f;
    int myc = t & 127, hb = (t >> 7) * 8;

    for (int s = c0; s < c1; s += 32) {
        __syncthreads();
#pragma unroll
        for (int i = 0; i < 4; i++) {
            int u = t + 256 * i;
            int nn = u >> 6, m2 = u & 63;
            int nd0 = s + 2 * nn, nd1 = nd0 + 1;
            uint32_t k0 = 0, k1 = 0, p0 = 0, p1 = 0;
            if (nd0 < c1) {
                k0 = *(const uint32_t*)(g_k16 + (size_t)nd0 * 256 + h * 128 + 2 * m2);
                if (TermSrc) {
                    float2 xv = *(const float2*)((const float*)prevv + (size_t)nd0 * 128 + 2 * m2);
                    p0 = packbf(xv.x, xv.y);
                } else {
                    p0 = *(const uint32_t*)((const __nv_bfloat16*)prevv + (size_t)nd0 * 256 + h * 128 + 2 * m2);
                }
            }
            if (nd1 < c1) {
                k1 = *(const uint32_t*)(g_k16 + (size_t)nd1 * 256 + h * 128 + 2 * m2);
                if (TermSrc) {
                    float2 xv = *(const float2*)((const float*)prevv + (size_t)nd1 * 128 + 2 * m2);
                    p1 = packbf(xv.x, xv.y);
                } else {
                    p1 = *(const uint32_t*)((const __nv_bfloat16*)prevv + (size_t)nd1 * 256 + h * 128 + 2 * m2);
                }
            }
            ksS[nn][2 * m2]     = __byte_perm(k0, k1, 0x5410);
            ksS[nn][2 * m2 + 1] = __byte_perm(k0, k1, 0x7632);
            pvS[nn][2 * m2]     = __byte_perm(p0, p1, 0x5410);
            pvS[nn][2 * m2 + 1] = __byte_perm(p0, p1, 0x7632);
        }
        __syncthreads();
        ktile_mma16(ksS, pvS, m0, n0, lane, acc, 2);
#pragma unroll
        for (int r = 0; r < 8; r++) {
            float2 f = unpackbf(pvS[hb + r][myc]);
            colsum += f.x + f.y;
        }
    }
    atomicAdd(&g_vssum[h * 128 + myc], colsum);
    float* kv = g_kvs + h * 16384;
#pragma unroll
    for (int mt = 0; mt < 4; mt++) {
        int m = m0 + mt * 16 + (lane >> 2);
#pragma unroll
        for (int nt = 0; nt < 4; nt++) {
            int c = n0 + nt * 8 + 2 * (lane & 3);
            atomicAdd(&kv[m * 128 + c],           acc[mt][nt][0]);
            atomicAdd(&kv[m * 128 + c + 1],       acc[mt][nt][1]);
            atomicAdd(&kv[(m + 8) * 128 + c],     acc[mt][nt][2]);
            atomicAdd(&kv[(m + 8) * 128 + c + 1], acc[mt][nt][3]);
        }
    }
}

// ---------------- nxt += (qs @ kvs + vs_sum) / den  (bf16 mma, RMW-add) ----------------
__global__ void __launch_bounds__(256) qkv_combine_kernel(__nv_bfloat16* __restrict__ nxt, int n) {
    int h = blockIdx.y;
    __shared__ uint32_t As[32][132];
    __shared__ uint32_t Bs[32][132];
    int t = threadIdx.x;
    int lane = t & 31, wid = t >> 5;
    int m0 = (wid & 1) * 64, n0 = (wid >> 1) * 32;
    int bm0 = blockIdx.x * 128;
    const float* kvp = g_kvs + h * 16384;
    float acc[4][4][4];
#pragma unroll
    for (int i = 0; i < 4; i++)
#pragma unroll
        for (int j = 0; j < 4; j++)
#pragma unroll
            for (int r = 0; r < 4; r++) acc[i][j][r] = 0.f;

#pragma unroll
    for (int kc = 0; kc < 2; kc++) {
        int kb = kc * 64;
        __syncthreads();
#pragma unroll
        for (int i = 0; i < 4; i++) {
            int u = t + 256 * i;
            int row = u >> 3, q = u & 7;
            uint4 v = make_uint4(0, 0, 0, 0);
            if (bm0 + row < n)
                v = *(const uint4*)(g_q16 + (size_t)(bm0 + row) * 256 + h * 128 + kb + q * 8);
            As[q * 4 + 0][row] = v.x; As[q * 4 + 1][row] = v.y;
            As[q * 4 + 2][row] = v.z; As[q * 4 + 3][row] = v.w;
        }
#pragma unroll
        for (int i = 0; i < 16; i++) {
            int u = t + 256 * i;
            int d = u & 127, m2 = u >> 7;
            int m = kb + 2 * m2;
            Bs[m2][d] = packbf(kvp[m * 128 + d], kvp[(m + 1) * 128 + d]);
        }
        __syncthreads();
        ktile_mma16((const uint32_t(*)[132])As, (const uint32_t(*)[132])Bs, m0, n0, lane, acc, 4);
    }
#pragma unroll
    for (int mt = 0; mt < 4; mt++) {
        int row = bm0 + m0 + mt * 16 + (lane >> 2);
#pragma unroll
        for (int nt = 0; nt < 4; nt++) {
            int col = n0 + nt * 8 + 2 * (lane & 3);
            float vs0 = g_vssum[h * 128 + col], vs1 = g_vssum[h * 128 + col + 1];
            if (row < n) {
                float invd = 1.0f / g_den[row * 2 + h];
                uint32_t* p = (uint32_t*)(nxt + (size_t)row * 256 + h * 128 + col);
                float2 old = unpackbf(*p);
                *p = packbf(old.x + (acc[mt][nt][0] + vs0) * invd,
                            old.y + (acc[mt][nt][1] + vs1) * invd);
            }
            if (row + 8 < n) {
                float invd = 1.0f / g_den[(row + 8) * 2 + h];
                uint32_t* p = (uint32_t*)(nxt + (size_t)(row + 8) * 256 + h * 128 + col);
                float2 old = unpackbf(*p);
                *p = packbf(old.x + (acc[mt][nt][2] + vs0) * invd,
                            old.y + (acc[mt][nt][3] + vs1) * invd);
            }
        }
    }
}

// ---------------- out += 0.5 * term_k @ Wo_slice(k) (bf16 mma) ----------------
__global__ void __launch_bounds__(256) out_accum_kernel(const __nv_bfloat16* __restrict__ term,
                                 const float* __restrict__ Wo,
                                 float* __restrict__ out, int n, int ksl) {
    __shared__ uint32_t As[32][132];
    __shared__ uint32_t Bs[32][132];
    int t = threadIdx.x;
    int lane = t & 31, wid = t >> 5;
    int m0 = (wid & 1) * 64, n0 = (wid >> 1) * 32;
    int bm0 = blockIdx.x * 128;
    float acc[4][4][4];
#pragma unroll
    for (int i = 0; i < 4; i++)
#pragma unroll
        for (int j = 0; j < 4; j++)
#pragma unroll
            for (int r = 0; r < 4; r++) acc[i][j][r] = 0.f;

#pragma unroll
    for (int kc = 0; kc < 4; kc++) {
        int kb = kc * 64;
        __syncthreads();
#pragma unroll
        for (int i = 0; i < 4; i++) {
            int u = t + 256 * i;
            int row = u >> 3, q = u & 7;
            uint4 v = make_uint4(0, 0, 0, 0);
            if (bm0 + row < n)
                v = *(const uint4*)(term + (size_t)(bm0 + row) * 256 + kb + q * 8);
            As[q * 4 + 0][row] = v.x; As[q * 4 + 1][row] = v.y;
            As[q * 4 + 2][row] = v.z; As[q * 4 + 3][row] = v.w;
        }
#pragma unroll
        for (int i = 0; i < 16; i++) {
            int u = t + 256 * i;
            int c = u & 127, j2 = u >> 7;
            int j = kb + 2 * j2;
            int wrow = ((j >> 7) * 640) + ksl * 128 + (j & 127);
            Bs[j2][c] = packbf(Wo[(size_t)wrow * 128 + c], Wo[(size_t)(wrow + 1) * 128 + c]);
        }
        __syncthreads();
        ktile_mma16((const uint32_t(*)[132])As, (const uint32_t(*)[132])Bs, m0, n0, lane, acc, 4);
    }
#pragma unroll
    for (int mt = 0; mt < 4; mt++) {
        int row = bm0 + m0 + mt * 16 + (lane >> 2);
#pragma unroll
        for (int nt = 0; nt < 4; nt++) {
            int col = n0 + nt * 8 + 2 * (lane & 3);
            if (row < n) {
                float2 c = *(float2*)&out[(size_t)row * 128 + col];
                c.x += 0.5f * acc[mt][nt][0];
                c.y += 0.5f * acc[mt][nt][1];
                *(float2*)&out[(size_t)row * 128 + col] = c;
            }
            if (row + 8 < n) {
                float2 c = *(float2*)&out[(size_t)(row + 8) * 128 + col];
                c.x += 0.5f * acc[mt][nt][2];
                c.y += 0.5f * acc[mt][nt][3];
                *(float2*)&out[(size_t)(row + 8) * 128 + col] = c;
            }
        }
    }
}

// ---------------- host orchestration ----------------
extern "C" void kernel_launch(void* const* d_in, const int* in_sizes, int n_in,
                              void* d_out, int out_size) {
    const float* x   = (const float*)d_in[0];
    const void*  ei  = d_in[1];
    const float* Wqw = (const float*)d_in[2];
    const float* Wqb = (const float*)d_in[3];
    const float* Wkw = (const float*)d_in[4];
    const float* Wkb = (const float*)d_in[5];
    const float* Wow = (const float*)d_in[6];
    const float* Wob = (const float*)d_in[7];
    float* out = (float*)d_out;

    int n = in_sizes[0] / CC;
    int E = in_sizes[1] / 2;

    void *pDeg, *pKvs, *pVs, *pKs, *pA16, *pB16;
    cudaGetSymbolAddress(&pDeg, g_deg);
    cudaGetSymbolAddress(&pKvs, g_kvs);
    cudaGetSymbolAddress(&pVs,  g_vssum);
    cudaGetSymbolAddress(&pKs,  g_kssum);
    cudaGetSymbolAddress(&pA16, g_tA16);
    cudaGetSymbolAddress(&pB16, g_tB16);

    static int inited = 0;
    static cudaStream_t sB, sC;
    static cudaEvent_t evQ[5], evB[5], evC[5];
    if (!inited) {
        cudaStreamCreateWithFlags(&sB, cudaStreamNonBlocking);
        cudaStreamCreateWithFlags(&sC, cudaStreamNonBlocking);
        for (int i = 0; i < 5; i++) {
            cudaEventCreateWithFlags(&evQ[i], cudaEventDisableTiming);
            cudaEventCreateWithFlags(&evB[i], cudaEventDisableTiming);
            cudaEventCreateWithFlags(&evC[i], cudaEventDisableTiming);
        }
        inited = 1;
    }

    int nb  = (n + 127) / 128;
    int nkv = (n + 1023) / 1024;
    int nbScan = (n + 1023) / 1024;

    // fork sC off stream 0 at capture start
    cudaEventRecord(evC[0], 0);
    cudaStreamWaitEvent(sC, evC[0], 0);

    // ---- edge chain on sC (independent of projections) ----
    cudaMemsetAsync(pDeg, 0, (size_t)n * sizeof(int), sC);
    detect_dtype_kernel<<<1, 256, 0, sC>>>((const int*)ei, in_sizes[1]);
    edge_deg_kernel<<<(E + 255) / 256, 256, 0, sC>>>(ei, E);
    scan_blocks_kernel<<<nbScan, 1024, 0, sC>>>(n);
    scan_tops_kernel<<<1, 128, 0, sC>>>(nbScan);
    scan_apply_kernel<<<(n + 255) / 256, 256, 0, sC>>>(n, E);
    csr_scatter_kernel<<<(E + 255) / 256, 256, 0, sC>>>(ei, E);
    gcn_gather_x_kernel<<<(n * 32 + 255) / 256, 256, 0, sC>>>(x, (__nv_bfloat16*)pB16, n);
    cudaEventRecord(evC[1], sC);

    // ---- projection chain on stream 0 (concurrent with sC) ----
    dim3 gqk((n + 127) / 128, 4);
    qk_gemm_kernel<<<gqk, 256>>>(x, Wqw, Wqb, Wkw, Wkb, n);
    cudaMemsetAsync(pKs, 0, (size_t)HH * CC * sizeof(float));
    kssum_kernel<<<(n + 511) / 512, 256>>>(n);
    den_kernel<<<(n * 2 * 32 + 255) / 256, 256>>>(n);
    out_init_kernel<<<(n + 127) / 128, 256>>>(x, Wow, Wob, out, n);

    // ---- iter 1: kvs from x directly (needs only k16 + x) ----
    cudaMemsetAsync(pKvs, 0, (size_t)HH * CC * CC * sizeof(float));
    cudaMemsetAsync(pVs,  0, (size_t)HH * CC * sizeof(float));
    kvs_reduce_t_kernel<1><<<dim3(nkv, 2), 256>>>(x, n);
    cudaStreamWaitEvent(0, evC[1], 0);  // join: gather_x result needed now
    qkv_combine_kernel<<<dim3(nb, 2), 256>>>((__nv_bfloat16*)pB16, n);
    cudaEventRecord(evQ[1], 0);
    cudaStreamWaitEvent(sB, evQ[1], 0);
    out_accum_kernel<<<nb, 256, 0, sB>>>((const __nv_bfloat16*)pB16, Wow, out, n, 1);
    cudaEventRecord(evB[1], sB);

    // ---- iters 2..4: gather on sC || kvs_reduce on 0 ; out_accum on sB ----
    __nv_bfloat16* prev = (__nv_bfloat16*)pB16;
    __nv_bfloat16* nxt  = (__nv_bfloat16*)pA16;
    for (int ksl = 2; ksl <= 4; ksl++) {
        cudaStreamWaitEvent(sC, evQ[ksl - 1], 0);
        if (ksl >= 3)  // WAR: gather(k) overwrites the buffer out_accum(k-2) read
            cudaStreamWaitEvent(sC, evB[ksl - 2], 0);
        gcn_gather_kernel<<<(n * 32 + 255) / 256, 256, 0, sC>>>(nxt, prev, n);
        cudaEventRecord(evC[ksl], sC);

        cudaMemsetAsync(pKvs, 0, (size_t)HH * CC * CC * sizeof(float));
        cudaMemsetAsync(pVs,  0, (size_t)HH * CC * sizeof(float));
        kvs_reduce_t_kernel<0><<<dim3(nkv, 2), 256>>>(prev, n);

        cudaStreamWaitEvent(0, evC[ksl], 0);
        qkv_combine_kernel<<<dim3(nb, 2), 256>>>(nxt, n);
        cudaEventRecord(evQ[ksl], 0);

        cudaStreamWaitEvent(sB, evQ[ksl], 0);
        out_accum_kernel<<<nb, 256, 0, sB>>>(nxt, Wow, out, n, ksl);
        cudaEventRecord(evB[ksl], sB);

        __nv_bfloat16* tmp = prev; prev = nxt; nxt = tmp;
    }

    // join all forked work back to stream 0 before capture ends
    cudaStreamWaitEvent(0, evB[4], 0);
}

// round 10
// speedup vs baseline: 1.2759x; 1.0559x over previous
#include <cuda_runtime.h>
#include <cuda_bf16.h>
#include <cstdint>

#define CC   128
#define HH   2
#define HC   256
#define NMAX 100000
#define EMAX 1600000

// ---------------- device scratch (static, no allocation) ----------------
__device__ __nv_bfloat16 g_q16[(size_t)NMAX * HC];
__device__ __nv_bfloat16 g_k16[(size_t)NMAX * HC];
__device__ __nv_bfloat16 g_x16[(size_t)NMAX * CC];      // bf16 copy of x
__device__ __nv_bfloat16 g_t1[(size_t)NMAX * HC];       // term 1..4 (bf16)
__device__ __nv_bfloat16 g_t2[(size_t)NMAX * HC];
__device__ __nv_bfloat16 g_t3[(size_t)NMAX * HC];
__device__ __nv_bfloat16 g_t4[(size_t)NMAX * HC];
__device__ float g_deginv[NMAX];
__device__ int   g_deg[NMAX];
__device__ int   g_csroff[NMAX + 1];
__device__ int   g_csrcur[NMAX];
__device__ int   g_csrrow[EMAX];
__device__ int   g_blocksum[128];
__device__ float g_den[NMAX * HH];
__device__ float g_kvs[HH * CC * CC];
__device__ float g_vssum[HH * CC];
__device__ float g_kssum[HH * CC];
__device__ int   g_is64;

// ---------------- helpers ----------------
__device__ __forceinline__ uint32_t f2tf(float x) {
    uint32_t r;
    asm("cvt.rna.tf32.f32 %0, %1;" : "=r"(r) : "f"(x));
    return r;
}
__device__ __forceinline__ uint32_t packbf(float lo, float hi) {
    __nv_bfloat162 h2 = __floats2bfloat162_rn(lo, hi);
    return *reinterpret_cast<uint32_t*>(&h2);
}
__device__ __forceinline__ float2 unpackbf(uint32_t u) {
    __nv_bfloat162 h2 = *reinterpret_cast<__nv_bfloat162*>(&u);
    return __bfloat1622float2(h2);
}

__device__ __forceinline__ void mma16(float* c, uint32_t a0, uint32_t a1, uint32_t a2,
                                      uint32_t a3, uint32_t b0, uint32_t b1) {
    asm volatile(
        "mma.sync.aligned.m16n8k16.row.col.f32.bf16.bf16.f32 "
        "{%0,%1,%2,%3},{%4,%5,%6,%7},{%8,%9},{%0,%1,%2,%3};"
        : "+f"(c[0]), "+f"(c[1]), "+f"(c[2]), "+f"(c[3])
        : "r"(a0), "r"(a1), "r"(a2), "r"(a3), "r"(b0), "r"(b1));
}

// tf32 m16n8k8 over a 16-deep k tile, stride-128 smem
__device__ __forceinline__ void ktile_mma(const uint32_t (*As)[128], const uint32_t (*Bs)[128],
                                          int m0, int n0, int lane, float acc[4][4][4]) {
#pragma unroll
    for (int ks = 0; ks < 2; ks++) {
        int ar = ks * 8 + (lane & 3);
        int ac = lane >> 2;
        uint32_t a[4][4], b[4][2];
#pragma unroll
        for (int mt = 0; mt < 4; mt++) {
            int m = m0 + mt * 16 + ac;
            a[mt][0] = As[ar][m];
            a[mt][1] = As[ar][m + 8];
            a[mt][2] = As[ar + 4][m];
            a[mt][3] = As[ar + 4][m + 8];
        }
#pragma unroll
        for (int nt = 0; nt < 4; nt++) {
            int nn = n0 + nt * 8 + ac;
            b[nt][0] = Bs[ar][nn];
            b[nt][1] = Bs[ar + 4][nn];
        }
#pragma unroll
        for (int mt = 0; mt < 4; mt++)
#pragma unroll
            for (int nt = 0; nt < 4; nt++)
                asm volatile(
                    "mma.sync.aligned.m16n8k8.row.col.f32.tf32.tf32.f32 "
                    "{%0,%1,%2,%3},{%4,%5,%6,%7},{%8,%9},{%0,%1,%2,%3};"
                    : "+f"(acc[mt][nt][0]), "+f"(acc[mt][nt][1]),
                      "+f"(acc[mt][nt][2]), "+f"(acc[mt][nt][3])
                    : "r"(a[mt][0]), "r"(a[mt][1]), "r"(a[mt][2]), "r"(a[mt][3]),
                      "r"(b[nt][0]), "r"(b[nt][1]));
    }
}

// tf32 m16n8k8, stride-132 smem (for out_final shared buffers)
__device__ __forceinline__ void ktile_mma132(const uint32_t (*As)[132], const uint32_t (*Bs)[132],
                                             int m0, int n0, int lane, float acc[4][4][4]) {
#pragma unroll
    for (int ks = 0; ks < 2; ks++) {
        int ar = ks * 8 + (lane & 3);
        int ac = lane >> 2;
        uint32_t a[4][4], b[4][2];
#pragma unroll
        for (int mt = 0; mt < 4; mt++) {
            int m = m0 + mt * 16 + ac;
            a[mt][0] = As[ar][m];
            a[mt][1] = As[ar][m + 8];
            a[mt][2] = As[ar + 4][m];
            a[mt][3] = As[ar + 4][m + 8];
        }
#pragma unroll
        for (int nt = 0; nt < 4; nt++) {
            int nn = n0 + nt * 8 + ac;
            b[nt][0] = Bs[ar][nn];
            b[nt][1] = Bs[ar + 4][nn];
        }
#pragma unroll
        for (int mt = 0; mt < 4; mt++)
#pragma unroll
            for (int nt = 0; nt < 4; nt++)
                asm volatile(
                    "mma.sync.aligned.m16n8k8.row.col.f32.tf32.tf32.f32 "
                    "{%0,%1,%2,%3},{%4,%5,%6,%7},{%8,%9},{%0,%1,%2,%3};"
                    : "+f"(acc[mt][nt][0]), "+f"(acc[mt][nt][1]),
                      "+f"(acc[mt][nt][2]), "+f"(acc[mt][nt][3])
                    : "r"(a[mt][0]), "r"(a[mt][1]), "r"(a[mt][2]), "r"(a[mt][3]),
                      "r"(b[nt][0]), "r"(b[nt][1]));
    }
}

// bf16 m16n8k16, smem pair-packed along k, stride 132
__device__ __forceinline__ void ktile_mma16(const uint32_t (*As)[132], const uint32_t (*Bs)[132],
                                            int m0, int n0, int lane, float acc[4][4][4], int ksteps) {
    for (int ks = 0; ks < ksteps; ks++) {
        int ar = ks * 8 + (lane & 3);
        int ac = lane >> 2;
        uint32_t a[4][4], b[4][2];
#pragma unroll
        for (int mt = 0; mt < 4; mt++) {
            int m = m0 + mt * 16 + ac;
            a[mt][0] = As[ar][m];
            a[mt][1] = As[ar][m + 8];
            a[mt][2] = As[ar + 4][m];
            a[mt][3] = As[ar + 4][m + 8];
        }
#pragma unroll
        for (int nt = 0; nt < 4; nt++) {
            int nn = n0 + nt * 8 + ac;
            b[nt][0] = Bs[ar][nn];
            b[nt][1] = Bs[ar + 4][nn];
        }
#pragma unroll
        for (int mt = 0; mt < 4; mt++)
#pragma unroll
            for (int nt = 0; nt < 4; nt++)
                mma16(acc[mt][nt], a[mt][0], a[mt][1], a[mt][2], a[mt][3], b[nt][0], b[nt][1]);
    }
}

// ---------------- edge dtype detection ----------------
__global__ void detect_dtype_kernel(const int* __restrict__ ei32, int twoE) {
    __shared__ int nz;
    if (threadIdx.x == 0) nz = 0;
    __syncthreads();
    int samples = min(1024, twoE / 2);
    int local = 0;
    for (int i = threadIdx.x; i < samples; i += blockDim.x)
        if (ei32[2 * i + 1] != 0) local++;
    if (local) atomicAdd(&nz, local);
    __syncthreads();
    if (threadIdx.x == 0) g_is64 = (nz == 0) ? 1 : 0;
}

__device__ __forceinline__ int edge_col(const void* ei, int E, int e) {
    if (g_is64) return (int)((const long long*)ei)[(size_t)E + e];
    return ((const int*)ei)[E + e];
}
__device__ __forceinline__ int edge_row(const void* ei, int E, int e) {
    if (g_is64) return (int)((const long long*)ei)[e];
    return ((const int*)ei)[e];
}

// ---------------- edge prep ----------------
__global__ void edge_deg_kernel(const void* __restrict__ ei, int E) {
    int e = blockIdx.x * blockDim.x + threadIdx.x;
    if (e < E) atomicAdd(&g_deg[edge_col(ei, E, e)], 1);
}

__global__ void scan_blocks_kernel(int n) {
    __shared__ int sh[1024];
    int i = blockIdx.x * 1024 + threadIdx.x;
    int v = (i < n) ? g_deg[i] : 0;
    sh[threadIdx.x] = v;
    __syncthreads();
    for (int off = 1; off < 1024; off <<= 1) {
        int t = (threadIdx.x >= off) ? sh[threadIdx.x - off] : 0;
        __syncthreads();
        sh[threadIdx.x] += t;
        __syncthreads();
    }
    if (i < n) g_csroff[i] = sh[threadIdx.x] - v;
    if (threadIdx.x == 1023) g_blocksum[blockIdx.x] = sh[1023];
}

__global__ void scan_tops_kernel(int nb) {
    __shared__ int sh[128];
    int v = (threadIdx.x < nb) ? g_blocksum[threadIdx.x] : 0;
    sh[threadIdx.x] = v;
    __syncthreads();
    for (int off = 1; off < 128; off <<= 1) {
        int t = (threadIdx.x >= off) ? sh[threadIdx.x - off] : 0;
        __syncthreads();
        sh[threadIdx.x] += t;
        __syncthreads();
    }
    if (threadIdx.x < nb) g_blocksum[threadIdx.x] = sh[threadIdx.x] - v;
}

__global__ void scan_apply_kernel(int n, int E) {
    int i = blockIdx.x * blockDim.x + threadIdx.x;
    if (i < n) {
        int off = g_csroff[i] + g_blocksum[i >> 10];
        g_csroff[i] = off;
        g_csrcur[i] = off;
        int d = g_deg[i];
        g_deginv[i] = (d > 0) ? 1.0f / (float)d : 0.0f;
    }
    if (i == 0) g_csroff[n] = E;
}

__global__ void csr_scatter_kernel(const void* __restrict__ ei, int E) {
    int e = blockIdx.x * blockDim.x + threadIdx.x;
    if (e < E) {
        int c = edge_col(ei, E, e);
        int pos = atomicAdd(&g_csrcur[c], 1);
        g_csrrow[pos] = edge_row(ei, E, e);
    }
}

// ---------------- x -> bf16 copy ----------------
__global__ void x_to_bf16_kernel(const float* __restrict__ x, int n) {
    int i = blockIdx.x * blockDim.x + threadIdx.x;  // one per 4 elems
    if (i < n * 32) {
        float4 v = ((const float4*)x)[i];
        uint2 o;
        o.x = packbf(v.x, v.y);
        o.y = packbf(v.z, v.w);
        ((uint2*)g_x16)[i] = o;
    }
}

// ---------------- iter-1 GCN gather from bf16 x16, dup heads ----------------
__global__ void gcn_gather_x16_kernel(__nv_bfloat16* __restrict__ nxt, int n) {
    int gw = (blockIdx.x * blockDim.x + threadIdx.x) >> 5;
    int lane = threadIdx.x & 31;
    if (gw >= n) return;
    int beg = g_csroff[gw], end = g_csroff[gw + 1];
    float s = 0.5f * g_deginv[gw];
    float a[4];
#pragma unroll
    for (int i = 0; i < 4; i++) a[i] = 0.f;
    int e = beg;
    for (; e + 4 <= end; e += 4) {
        uint2 v0 = *(const uint2*)(g_x16 + (size_t)g_csrrow[e]     * 128 + lane * 4);
        uint2 v1 = *(const uint2*)(g_x16 + (size_t)g_csrrow[e + 1] * 128 + lane * 4);
        uint2 v2 = *(const uint2*)(g_x16 + (size_t)g_csrrow[e + 2] * 128 + lane * 4);
        uint2 v3 = *(const uint2*)(g_x16 + (size_t)g_csrrow[e + 3] * 128 + lane * 4);
#pragma unroll
        for (int p = 0; p < 2; p++) {
            float2 f0 = unpackbf((&v0.x)[p]);
            float2 f1 = unpackbf((&v1.x)[p]);
            float2 f2 = unpackbf((&v2.x)[p]);
            float2 f3 = unpackbf((&v3.x)[p]);
            a[2 * p]     += (f0.x + f1.x) + (f2.x + f3.x);
            a[2 * p + 1] += (f0.y + f1.y) + (f2.y + f3.y);
        }
    }
    for (; e < end; e++) {
        uint2 v0 = *(const uint2*)(g_x16 + (size_t)g_csrrow[e] * 128 + lane * 4);
#pragma unroll
        for (int p = 0; p < 2; p++) {
            float2 f0 = unpackbf((&v0.x)[p]);
            a[2 * p] += f0.x; a[2 * p + 1] += f0.y;
        }
    }
    uint2 o;
    o.x = packbf(s * a[0], s * a[1]);
    o.y = packbf(s * a[2], s * a[3]);
    *(uint2*)(nxt + (size_t)gw * 256 + lane * 4)       = o;
    *(uint2*)(nxt + (size_t)gw * 256 + 128 + lane * 4) = o;
}

// ---------------- GCN gather bf16 (high occupancy, 1 warp/row) ----------------
__global__ void gcn_gather_kernel(__nv_bfloat16* __restrict__ nxt, const __nv_bfloat16* __restrict__ prev, int n) {
    int gw = (blockIdx.x * blockDim.x + threadIdx.x) >> 5;
    int lane = threadIdx.x & 31;
    if (gw >= n) return;
    int beg = g_csroff[gw], end = g_csroff[gw + 1];
    float s = 0.5f * g_deginv[gw];
    float a[8];
#pragma unroll
    for (int i = 0; i < 8; i++) a[i] = 0.f;
    int e = beg;
    for (; e + 4 <= end; e += 4) {
        uint4 v0 = *(const uint4*)(prev + (size_t)g_csrrow[e]     * 256 + lane * 8);
        uint4 v1 = *(const uint4*)(prev + (size_t)g_csrrow[e + 1] * 256 + lane * 8);
        uint4 v2 = *(const uint4*)(prev + (size_t)g_csrrow[e + 2] * 256 + lane * 8);
        uint4 v3 = *(const uint4*)(prev + (size_t)g_csrrow[e + 3] * 256 + lane * 8);
#pragma unroll
        for (int p = 0; p < 4; p++) {
            float2 f0 = unpackbf((&v0.x)[p]);
            float2 f1 = unpackbf((&v1.x)[p]);
            float2 f2 = unpackbf((&v2.x)[p]);
            float2 f3 = unpackbf((&v3.x)[p]);
            a[2 * p]     += (f0.x + f1.x) + (f2.x + f3.x);
            a[2 * p + 1] += (f0.y + f1.y) + (f2.y + f3.y);
        }
    }
    for (; e < end; e++) {
        uint4 v0 = *(const uint4*)(prev + (size_t)g_csrrow[e] * 256 + lane * 8);
#pragma unroll
        for (int p = 0; p < 4; p++) {
            float2 f0 = unpackbf((&v0.x)[p]);
            a[2 * p] += f0.x; a[2 * p + 1] += f0.y;
        }
    }
    uint4 o;
    o.x = packbf(s * a[0], s * a[1]);
    o.y = packbf(s * a[2], s * a[3]);
    o.z = packbf(s * a[4], s * a[5]);
    o.w = packbf(s * a[6], s * a[7]);
    *(uint4*)(nxt + (size_t)gw * 256 + lane * 8) = o;
}

// ---------------- q/k projection GEMM (tf32) + fused L2 norm -> bf16 only ----------------
__global__ void __launch_bounds__(256) qk_gemm_kernel(const float* __restrict__ x,
                               const float* __restrict__ Wq, const float* __restrict__ Wqb,
                               const float* __restrict__ Wk, const float* __restrict__ Wkb,
                               int n) {
    __shared__ uint32_t As[16][128];
    __shared__ uint32_t Bs[16][128];
    __shared__ float rowss[128];
    int t = threadIdx.x;
    int lane = t & 31, wid = t >> 5;
    int m0 = (wid & 1) * 64, n0 = (wid >> 1) * 32;
    int bm0 = blockIdx.x * 128;
    int by = blockIdx.y;
    const float* B   = (by < 2) ? Wq  : Wk;
    const float* bia = (by < 2) ? Wqb : Wkb;
    __nv_bfloat16* dst = (by < 2) ? g_q16 : g_k16;
    int coff = (by & 1) * 128;
    int am = t >> 1, akq = (t & 1) * 8;
    int bk = t >> 4, bnq = (t & 15) * 8;
    float acc[4][4][4];
#pragma unroll
    for (int i = 0; i < 4; i++)
#pragma unroll
        for (int j = 0; j < 4; j++)
#pragma unroll
            for (int r = 0; r < 4; r++) acc[i][j][r] = 0.f;
    if (t < 128) rowss[t] = 0.f;

    for (int k0 = 0; k0 < 128; k0 += 16) {
        float4 a0 = make_float4(0, 0, 0, 0), a1 = a0;
        int row = bm0 + am;
        if (row < n) {
            const float4* ap = (const float4*)(x + (size_t)row * 128 + k0 + akq);
            a0 = ap[0]; a1 = ap[1];
        }
        const float4* bp = (const float4*)(B + (size_t)(k0 + bk) * 256 + coff + bnq);
        float4 b0 = bp[0], b1 = bp[1];
        __syncthreads();
        As[akq + 0][am] = f2tf(a0.x); As[akq + 1][am] = f2tf(a0.y);
        As[akq + 2][am] = f2tf(a0.z); As[akq + 3][am] = f2tf(a0.w);
        As[akq + 4][am] = f2tf(a1.x); As[akq + 5][am] = f2tf(a1.y);
        As[akq + 6][am] = f2tf(a1.z); As[akq + 7][am] = f2tf(a1.w);
        Bs[bk][bnq + 0] = f2tf(b0.x); Bs[bk][bnq + 1] = f2tf(b0.y);
        Bs[bk][bnq + 2] = f2tf(b0.z); Bs[bk][bnq + 3] = f2tf(b0.w);
        Bs[bk][bnq + 4] = f2tf(b1.x); Bs[bk][bnq + 5] = f2tf(b1.y);
        Bs[bk][bnq + 6] = f2tf(b1.z); Bs[bk][bnq + 7] = f2tf(b1.w);
        __syncthreads();
        ktile_mma(As, Bs, m0, n0, lane, acc);
    }

#pragma unroll
    for (int mt = 0; mt < 4; mt++) {
        float ss0 = 0.f, ss1 = 0.f;
#pragma unroll
        for (int nt = 0; nt < 4; nt++) {
            int col = coff + n0 + nt * 8 + 2 * (lane & 3);
            float bx = bia[col], by2 = bia[col + 1];
            acc[mt][nt][0] += bx; acc[mt][nt][1] += by2;
            acc[mt][nt][2] += bx; acc[mt][nt][3] += by2;
            ss0 += acc[mt][nt][0] * acc[mt][nt][0] + acc[mt][nt][1] * acc[mt][nt][1];
            ss1 += acc[mt][nt][2] * acc[mt][nt][2] + acc[mt][nt][3] * acc[mt][nt][3];
        }
        ss0 += __shfl_xor_sync(0xffffffffu, ss0, 1);
        ss0 += __shfl_xor_sync(0xffffffffu, ss0, 2);
        ss1 += __shfl_xor_sync(0xffffffffu, ss1, 1);
        ss1 += __shfl_xor_sync(0xffffffffu, ss1, 2);
        if ((lane & 3) == 0) {
            int r = m0 + mt * 16 + (lane >> 2);
            atomicAdd(&rowss[r], ss0);
            atomicAdd(&rowss[r + 8], ss1);
        }
    }
    __syncthreads();

#pragma unroll
    for (int mt = 0; mt < 4; mt++) {
        int r = m0 + mt * 16 + (lane >> 2);
        float inv0 = rsqrtf(rowss[r]);
        float inv1 = rsqrtf(rowss[r + 8]);
        int row = bm0 + r;
#pragma unroll
        for (int nt = 0; nt < 4; nt++) {
            int col = coff + n0 + nt * 8 + 2 * (lane & 3);
            if (row < n)
                *(uint32_t*)(dst + (size_t)row * 256 + col) =
                    packbf(acc[mt][nt][0] * inv0, acc[mt][nt][1] * inv0);
            if (row + 8 < n)
                *(uint32_t*)(dst + (size_t)(row + 8) * 256 + col) =
                    packbf(acc[mt][nt][2] * inv1, acc[mt][nt][3] * inv1);
        }
    }
}

// ---------------- ks_sum from bf16 (fp32 accumulate) ----------------
__global__ void kssum_kernel(int n) {
    int col = threadIdx.x;
    int start = blockIdx.x * 512;
    int end = min(start + 512, n);
    float s = 0.f;
    for (int node = start; node < end; node++)
        s += __bfloat162float(g_k16[(size_t)node * 256 + col]);
    atomicAdd(&g_kssum[col], s);
}

// ---------------- den = q16 . ks_sum + n ----------------
__global__ void den_kernel(int n) {
    int gw = (blockIdx.x * blockDim.x + threadIdx.x) >> 5;
    int lane = threadIdx.x & 31;
    if (gw >= n * 2) return;
    int node = gw >> 1, h = gw & 1;
    uint2 qu = *(const uint2*)(g_q16 + (size_t)node * 256 + h * 128 + lane * 4);
    float2 qa = unpackbf(qu.x), qb = unpackbf(qu.y);
    float4 kv = ((const float4*)(g_kssum + h * 128))[lane];
    float d = qa.x * kv.x + qa.y * kv.y + qb.x * kv.z + qb.y * kv.w;
#pragma unroll
    for (int o = 16; o; o >>= 1) d += __shfl_xor_sync(0xffffffffu, d, o);
    if (lane == 0) g_den[node * 2 + h] = d + (float)n;
}

// ---------------- kvs[h] += ks^T @ prev (bf16 mma) ; vs_sum (fp32) ----------------
template <int TermSrc>
__global__ void __launch_bounds__(256) kvs_reduce_t_kernel(const void* __restrict__ prevv, int n) {
    int h = blockIdx.y;
    int c0 = blockIdx.x * 1024;
    int c1 = min(c0 + 1024, n);
    __shared__ uint32_t ksS[16][132];
    __shared__ uint32_t pvS[16][132];
    int t = threadIdx.x;
    int lane = t & 31, wid = t >> 5;
    int m0 = (wid & 1) * 64, n0 = (wid >> 1) * 32;
    float acc[4][4][4];
#pragma unroll
    for (int i = 0; i < 4; i++)
#pragma unroll
        for (int j = 0; j < 4; j++)
#pragma unroll
            for (int r = 0; r < 4; r++) acc[i][j][r] = 0.f;
    float colsum = 0.f;
    int myc = t & 127, hb = (t >> 7) * 8;

    for (int s = c0; s < c1; s += 32) {
        __syncthreads();
#pragma unroll
        for (int i = 0; i < 4; i++) {
            int u = t + 256 * i;
            int nn = u >> 6, m2 = u & 63;
            int nd0 = s + 2 * nn, nd1 = nd0 + 1;
            uint32_t k0 = 0, k1 = 0, p0 = 0, p1 = 0;
            if (nd0 < c1) {
                k0 = *(const uint32_t*)(g_k16 + (size_t)nd0 * 256 + h * 128 + 2 * m2);
                if (TermSrc) {
                    float2 xv = *(const float2*)((const float*)prevv + (size_t)nd0 * 128 + 2 * m2);
                    p0 = packbf(xv.x, xv.y);
                } else {
                    p0 = *(const uint32_t*)((const __nv_bfloat16*)prevv + (size_t)nd0 * 256 + h * 128 + 2 * m2);
                }
            }
            if (nd1 < c1) {
                k1 = *(const uint32_t*)(g_k16 + (size_t)nd1 * 256 + h * 128 + 2 * m2);
                if (TermSrc) {
                    float2 xv = *(const float2*)((const float*)prevv + (size_t)nd1 * 128 + 2 * m2);
                    p1 = packbf(xv.x, xv.y);
                } else {
                    p1 = *(const uint32_t*)((const __nv_bfloat16*)prevv + (size_t)nd1 * 256 + h * 128 + 2 * m2);
                }
            }
            ksS[nn][2 * m2]     = __byte_perm(k0, k1, 0x5410);
            ksS[nn][2 * m2 + 1] = __byte_perm(k0, k1, 0x7632);
            pvS[nn][2 * m2]     = __byte_perm(p0, p1, 0x5410);
            pvS[nn][2 * m2 + 1] = __byte_perm(p0, p1, 0x7632);
        }
        __syncthreads();
        ktile_mma16(ksS, pvS, m0, n0, lane, acc, 2);
#pragma unroll
        for (int r = 0; r < 8; r++) {
            float2 f = unpackbf(pvS[hb + r][myc]);
            colsum += f.x + f.y;
        }
    }
    atomicAdd(&g_vssum[h * 128 + myc], colsum);
    float* kv = g_kvs + h * 16384;
#pragma unroll
    for (int mt = 0; mt < 4; mt++) {
        int m = m0 + mt * 16 + (lane >> 2);
#pragma unroll
        for (int nt = 0; nt < 4; nt++) {
            int c = n0 + nt * 8 + 2 * (lane & 3);
            atomicAdd(&kv[m * 128 + c],           acc[mt][nt][0]);
            atomicAdd(&kv[m * 128 + c + 1],       acc[mt][nt][1]);
            atomicAdd(&kv[(m + 8) * 128 + c],     acc[mt][nt][2]);
            atomicAdd(&kv[(m + 8) * 128 + c + 1], acc[mt][nt][3]);
        }
    }
}

// ---------------- nxt += (qs @ kvs + vs_sum) / den  (bf16 mma, RMW-add) ----------------
__global__ void __launch_bounds__(256) qkv_combine_kernel(__nv_bfloat16* __restrict__ nxt, int n) {
    int h = blockIdx.y;
    __shared__ uint32_t As[32][132];
    __shared__ uint32_t Bs[32][132];
    int t = threadIdx.x;
    int lane = t & 31, wid = t >> 5;
    int m0 = (wid & 1) * 64, n0 = (wid >> 1) * 32;
    int bm0 = blockIdx.x * 128;
    const float* kvp = g_kvs + h * 16384;
    float acc[4][4][4];
#pragma unroll
    for (int i = 0; i < 4; i++)
#pragma unroll
        for (int j = 0; j < 4; j++)
#pragma unroll
            for (int r = 0; r < 4; r++) acc[i][j][r] = 0.f;

#pragma unroll
    for (int kc = 0; kc < 2; kc++) {
        int kb = kc * 64;
        __syncthreads();
#pragma unroll
        for (int i = 0; i < 4; i++) {
            int u = t + 256 * i;
            int row = u >> 3, q = u & 7;
            uint4 v = make_uint4(0, 0, 0, 0);
            if (bm0 + row < n)
                v = *(const uint4*)(g_q16 + (size_t)(bm0 + row) * 256 + h * 128 + kb + q * 8);
            As[q * 4 + 0][row] = v.x; As[q * 4 + 1][row] = v.y;
            As[q * 4 + 2][row] = v.z; As[q * 4 + 3][row] = v.w;
        }
#pragma unroll
        for (int i = 0; i < 16; i++) {
            int u = t + 256 * i;
            int d = u & 127, m2 = u >> 7;
            int m = kb + 2 * m2;
            Bs[m2][d] = packbf(kvp[m * 128 + d], kvp[(m + 1) * 128 + d]);
        }
        __syncthreads();
        ktile_mma16((const uint32_t(*)[132])As, (const uint32_t(*)[132])Bs, m0, n0, lane, acc, 4);
    }
#pragma unroll
    for (int mt = 0; mt < 4; mt++) {
        int row = bm0 + m0 + mt * 16 + (lane >> 2);
#pragma unroll
        for (int nt = 0; nt < 4; nt++) {
            int col = n0 + nt * 8 + 2 * (lane & 3);
            float vs0 = g_vssum[h * 128 + col], vs1 = g_vssum[h * 128 + col + 1];
            if (row < n) {
                float invd = 1.0f / g_den[row * 2 + h];
                uint32_t* p = (uint32_t*)(nxt + (size_t)row * 256 + h * 128 + col);
                float2 old = unpackbf(*p);
                *p = packbf(old.x + (acc[mt][nt][0] + vs0) * invd,
                            old.y + (acc[mt][nt][1] + vs1) * invd);
            }
            if (row + 8 < n) {
                float invd = 1.0f / g_den[(row + 8) * 2 + h];
                uint32_t* p = (uint32_t*)(nxt + (size_t)(row + 8) * 256 + h * 128 + col);
                float2 old = unpackbf(*p);
                *p = packbf(old.x + (acc[mt][nt][2] + vs0) * invd,
                            old.y + (acc[mt][nt][3] + vs1) * invd);
            }
        }
    }
}

// ---------------- final out GEMM: out = 0.5*(x@(Wo0h0+Wo0h1) + sum_t t@Wo_t + b) ----------------
__global__ void __launch_bounds__(256) out_final_kernel(
    const float* __restrict__ x, const float* __restrict__ Wo, const float* __restrict__ Wob,
    const __nv_bfloat16* __restrict__ t1, const __nv_bfloat16* __restrict__ t2,
    const __nv_bfloat16* __restrict__ t3, const __nv_bfloat16* __restrict__ t4,
    float* __restrict__ out, int n) {
    __shared__ uint32_t As[32][132];
    __shared__ uint32_t Bs[32][132];
    int t = threadIdx.x;
    int lane = t & 31, wid = t >> 5;
    int m0 = (wid & 1) * 64, n0 = (wid >> 1) * 32;
    int bm0 = blockIdx.x * 128;
    float acc[4][4][4];
#pragma unroll
    for (int i = 0; i < 4; i++)
#pragma unroll
        for (int j = 0; j < 4; j++)
#pragma unroll
            for (int r = 0; r < 4; r++) acc[i][j][r] = 0.f;

    // ---- phase A: tf32 over x, B = Wo[wr] + Wo[640+wr] (k-slice 0) ----
    {
        int am = t >> 1, akq = (t & 1) * 8;
        int bk = t >> 4, bnq = (t & 15) * 8;
        for (int k0 = 0; k0 < 128; k0 += 16) {
            float4 a0 = make_float4(0, 0, 0, 0), a1 = a0;
            int row = bm0 + am;
            if (row < n) {
                const float4* ap = (const float4*)(x + (size_t)row * 128 + k0 + akq);
                a0 = ap[0]; a1 = ap[1];
            }
            int wr = k0 + bk;
            const float4* p0 = (const float4*)(Wo + (size_t)wr * 128 + bnq);
            const float4* p1 = (const float4*)(Wo + (size_t)(640 + wr) * 128 + bnq);
            float4 u0 = p0[0], u1 = p0[1], v0 = p1[0], v1 = p1[1];
            __syncthreads();
            As[akq + 0][am] = f2tf(a0.x); As[akq + 1][am] = f2tf(a0.y);
            As[akq + 2][am] = f2tf(a0.z); As[akq + 3][am] = f2tf(a0.w);
            As[akq + 4][am] = f2tf(a1.x); As[akq + 5][am] = f2tf(a1.y);
            As[akq + 6][am] = f2tf(a1.z); As[akq + 7][am] = f2tf(a1.w);
            Bs[bk][bnq + 0] = f2tf(u0.x + v0.x); Bs[bk][bnq + 1] = f2tf(u0.y + v0.y);
            Bs[bk][bnq + 2] = f2tf(u0.z + v0.z); Bs[bk][bnq + 3] = f2tf(u0.w + v0.w);
            Bs[bk][bnq + 4] = f2tf(u1.x + v1.x); Bs[bk][bnq + 5] = f2tf(u1.y + v1.y);
            Bs[bk][bnq + 6] = f2tf(u1.z + v1.z); Bs[bk][bnq + 7] = f2tf(u1.w + v1.w);
            __syncthreads();
            ktile_mma132((const uint32_t(*)[132])As, (const uint32_t(*)[132])Bs, m0, n0, lane, acc);
        }
    }

    // ---- phase B: bf16 over terms 1..4 ----
    const __nv_bfloat16* terms[4] = {t1, t2, t3, t4};
#pragma unroll 1
    for (int ksl = 1; ksl <= 4; ksl++) {
        const __nv_bfloat16* term = terms[ksl - 1];
        for (int kc = 0; kc < 4; kc++) {
            int kb = kc * 64;
            __syncthreads();
#pragma unroll
            for (int i = 0; i < 4; i++) {
                int u = t + 256 * i;
                int row = u >> 3, q = u & 7;
                uint4 v = make_uint4(0, 0, 0, 0);
                if (bm0 + row < n)
                    v = *(const uint4*)(term + (size_t)(bm0 + row) * 256 + kb + q * 8);
                As[q * 4 + 0][row] = v.x; As[q * 4 + 1][row] = v.y;
                As[q * 4 + 2][row] = v.z; As[q * 4 + 3][row] = v.w;
            }
#pragma unroll
            for (int i = 0; i < 16; i++) {
                int u = t + 256 * i;
                int c = u & 127, j2 = u >> 7;
                int j = kb + 2 * j2;
                int wrow = ((j >> 7) * 640) + ksl * 128 + (j & 127);
                Bs[j2][c] = packbf(Wo[(size_t)wrow * 128 + c], Wo[(size_t)(wrow + 1) * 128 + c]);
            }
            __syncthreads();
            ktile_mma16((const uint32_t(*)[132])As, (const uint32_t(*)[132])Bs, m0, n0, lane, acc, 4);
        }
    }

    // ---- epilogue: out = 0.5*(acc + b) ----
#pragma unroll
    for (int mt = 0; mt < 4; mt++) {
        int row = bm0 + m0 + mt * 16 + (lane >> 2);
#pragma unroll
        for (int nt = 0; nt < 4; nt++) {
            int col = n0 + nt * 8 + 2 * (lane & 3);
            float bx = Wob[col], by2 = Wob[col + 1];
            if (row < n) {
                float2 v = make_float2(0.5f * (acc[mt][nt][0] + bx), 0.5f * (acc[mt][nt][1] + by2));
                *(float2*)&out[(size_t)row * 128 + col] = v;
            }
            if (row + 8 < n) {
                float2 v = make_float2(0.5f * (acc[mt][nt][2] + bx), 0.5f * (acc[mt][nt][3] + by2));
                *(float2*)&out[(size_t)(row + 8) * 128 + col] = v;
            }
        }
    }
}

// ---------------- host orchestration ----------------
extern "C" void kernel_launch(void* const* d_in, const int* in_sizes, int n_in,
                              void* d_out, int out_size) {
    const float* x   = (const float*)d_in[0];
    const void*  ei  = d_in[1];
    const float* Wqw = (const float*)d_in[2];
    const float* Wqb = (const float*)d_in[3];
    const float* Wkw = (const float*)d_in[4];
    const float* Wkb = (const float*)d_in[5];
    const float* Wow = (const float*)d_in[6];
    const float* Wob = (const float*)d_in[7];
    float* out = (float*)d_out;

    int n = in_sizes[0] / CC;
    int E = in_sizes[1] / 2;

    void *pDeg, *pKvs, *pVs, *pKs;
    void *pT[4];
    cudaGetSymbolAddress(&pDeg, g_deg);
    cudaGetSymbolAddress(&pKvs, g_kvs);
    cudaGetSymbolAddress(&pVs,  g_vssum);
    cudaGetSymbolAddress(&pKs,  g_kssum);
    cudaGetSymbolAddress(&pT[0], g_t1);
    cudaGetSymbolAddress(&pT[1], g_t2);
    cudaGetSymbolAddress(&pT[2], g_t3);
    cudaGetSymbolAddress(&pT[3], g_t4);

    static int inited = 0;
    static cudaStream_t sC;
    static cudaEvent_t evQ[5], evC[5];
    if (!inited) {
        cudaStreamCreateWithFlags(&sC, cudaStreamNonBlocking);
        for (int i = 0; i < 5; i++) {
            cudaEventCreateWithFlags(&evQ[i], cudaEventDisableTiming);
            cudaEventCreateWithFlags(&evC[i], cudaEventDisableTiming);
        }
        inited = 1;
    }

    int nb  = (n + 127) / 128;
    int nkv = (n + 1023) / 1024;
    int nbScan = (n + 1023) / 1024;

    // fork sC off stream 0 at capture start
    cudaEventRecord(evC[0], 0);
    cudaStreamWaitEvent(sC, evC[0], 0);

    // ---- edge chain on sC ----
    x_to_bf16_kernel<<<(n * 32 + 255) / 256, 256, 0, sC>>>(x, n);
    cudaMemsetAsync(pDeg, 0, (size_t)n * sizeof(int), sC);
    detect_dtype_kernel<<<1, 256, 0, sC>>>((const int*)ei, in_sizes[1]);
    edge_deg_kernel<<<(E + 255) / 256, 256, 0, sC>>>(ei, E);
    scan_blocks_kernel<<<nbScan, 1024, 0, sC>>>(n);
    scan_tops_kernel<<<1, 128, 0, sC>>>(nbScan);
    scan_apply_kernel<<<(n + 255) / 256, 256, 0, sC>>>(n, E);
    csr_scatter_kernel<<<(E + 255) / 256, 256, 0, sC>>>(ei, E);
    gcn_gather_x16_kernel<<<(n * 32 + 255) / 256, 256, 0, sC>>>((__nv_bfloat16*)pT[0], n);
    cudaEventRecord(evC[1], sC);

    // ---- projection chain on stream 0 (concurrent) ----
    dim3 gqk((n + 127) / 128, 4);
    qk_gemm_kernel<<<gqk, 256>>>(x, Wqw, Wqb, Wkw, Wkb, n);
    cudaMemsetAsync(pKs, 0, (size_t)HH * CC * sizeof(float));
    kssum_kernel<<<(n + 511) / 512, 256>>>(n);
    den_kernel<<<(n * 2 * 32 + 255) / 256, 256>>>(n);

    // ---- iter 1: kvs from x fp32 directly ----
    cudaMemsetAsync(pKvs, 0, (size_t)HH * CC * CC * sizeof(float));
    cudaMemsetAsync(pVs,  0, (size_t)HH * CC * sizeof(float));
    kvs_reduce_t_kernel<1><<<dim3(nkv, 2), 256>>>(x, n);
    cudaStreamWaitEvent(0, evC[1], 0);
    qkv_combine_kernel<<<dim3(nb, 2), 256>>>((__nv_bfloat16*)pT[0], n);
    cudaEventRecord(evQ[1], 0);

    // ---- iters 2..4: gather on sC || kvs on 0; combine joins ----
    for (int ksl = 2; ksl <= 4; ksl++) {
        __nv_bfloat16* prev = (__nv_bfloat16*)pT[ksl - 2];
        __nv_bfloat16* nxt  = (__nv_bfloat16*)pT[ksl - 1];
        cudaStreamWaitEvent(sC, evQ[ksl - 1], 0);
        gcn_gather_kernel<<<(n * 32 + 255) / 256, 256, 0, sC>>>(nxt, prev, n);
        cudaEventRecord(evC[ksl], sC);

        cudaMemsetAsync(pKvs, 0, (size_t)HH * CC * CC * sizeof(float));
        cudaMemsetAsync(pVs,  0, (size_t)HH * CC * sizeof(float));
        kvs_reduce_t_kernel<0><<<dim3(nkv, 2), 256>>>(prev, n);

        cudaStreamWaitEvent(0, evC[ksl], 0);
        qkv_combine_kernel<<<dim3(nb, 2), 256>>>(nxt, n);
        cudaEventRecord(evQ[ksl], 0);
    }

    // ---- single deferred output GEMM ----
    out_final_kernel<<<nb, 256>>>(x, Wow, Wob,
                                  (const __nv_bfloat16*)pT[0], (const __nv_bfloat16*)pT[1],
                                  (const __nv_bfloat16*)pT[2], (const __nv_bfloat16*)pT[3],
                                  out, n);
}

// round 11
// speedup vs baseline: 1.3471x; 1.0558x over previous
#include <cuda_runtime.h>
#include <cuda_bf16.h>
#include <cstdint>

#define CC   128
#define HH   2
#define HC   256
#define NMAX 100000
#define EMAX 1600000

// ---------------- device scratch (static, no allocation) ----------------
__device__ __nv_bfloat16 g_q16[(size_t)NMAX * HC];
__device__ __nv_bfloat16 g_k16[(size_t)NMAX * HC];
__device__ __nv_bfloat16 g_x16[(size_t)NMAX * CC];      // bf16 copy of x
__device__ __nv_bfloat16 g_t1[(size_t)NMAX * HC];       // term 1..4 (bf16)
__device__ __nv_bfloat16 g_t2[(size_t)NMAX * HC];
__device__ __nv_bfloat16 g_t3[(size_t)NMAX * HC];
__device__ __nv_bfloat16 g_t4[(size_t)NMAX * HC];
__device__ float g_deginv[NMAX];
__device__ int   g_deg[NMAX];
__device__ int   g_csroff[NMAX + 1];
__device__ int   g_csrcur[NMAX];
__device__ int   g_csrrow[EMAX];
__device__ int   g_blocksum[128];
__device__ float g_den[NMAX * HH];
__device__ float g_kvs[HH * CC * CC];
__device__ float g_vssum[HH * CC];
__device__ float g_kssum[HH * CC];
__device__ int   g_is64;

// ---------------- helpers ----------------
__device__ __forceinline__ uint32_t f2tf(float x) {
    uint32_t r;
    asm("cvt.rna.tf32.f32 %0, %1;" : "=r"(r) : "f"(x));
    return r;
}
__device__ __forceinline__ uint32_t packbf(float lo, float hi) {
    __nv_bfloat162 h2 = __floats2bfloat162_rn(lo, hi);
    return *reinterpret_cast<uint32_t*>(&h2);
}
__device__ __forceinline__ float2 unpackbf(uint32_t u) {
    __nv_bfloat162 h2 = *reinterpret_cast<__nv_bfloat162*>(&u);
    return __bfloat1622float2(h2);
}

__device__ __forceinline__ void mma16(float* c, uint32_t a0, uint32_t a1, uint32_t a2,
                                      uint32_t a3, uint32_t b0, uint32_t b1) {
    asm volatile(
        "mma.sync.aligned.m16n8k16.row.col.f32.bf16.bf16.f32 "
        "{%0,%1,%2,%3},{%4,%5,%6,%7},{%8,%9},{%0,%1,%2,%3};"
        : "+f"(c[0]), "+f"(c[1]), "+f"(c[2]), "+f"(c[3])
        : "r"(a0), "r"(a1), "r"(a2), "r"(a3), "r"(b0), "r"(b1));
}

// tf32 m16n8k8 over a 16-deep k tile, stride-128 smem
__device__ __forceinline__ void ktile_mma(const uint32_t (*As)[128], const uint32_t (*Bs)[128],
                                          int m0, int n0, int lane, float acc[4][4][4]) {
#pragma unroll
    for (int ks = 0; ks < 2; ks++) {
        int ar = ks * 8 + (lane & 3);
        int ac = lane >> 2;
        uint32_t a[4][4], b[4][2];
#pragma unroll
        for (int mt = 0; mt < 4; mt++) {
            int m = m0 + mt * 16 + ac;
            a[mt][0] = As[ar][m];
            a[mt][1] = As[ar][m + 8];
            a[mt][2] = As[ar + 4][m];
            a[mt][3] = As[ar + 4][m + 8];
        }
#pragma unroll
        for (int nt = 0; nt < 4; nt++) {
            int nn = n0 + nt * 8 + ac;
            b[nt][0] = Bs[ar][nn];
            b[nt][1] = Bs[ar + 4][nn];
        }
#pragma unroll
        for (int mt = 0; mt < 4; mt++)
#pragma unroll
            for (int nt = 0; nt < 4; nt++)
                asm volatile(
                    "mma.sync.aligned.m16n8k8.row.col.f32.tf32.tf32.f32 "
                    "{%0,%1,%2,%3},{%4,%5,%6,%7},{%8,%9},{%0,%1,%2,%3};"
                    : "+f"(acc[mt][nt][0]), "+f"(acc[mt][nt][1]),
                      "+f"(acc[mt][nt][2]), "+f"(acc[mt][nt][3])
                    : "r"(a[mt][0]), "r"(a[mt][1]), "r"(a[mt][2]), "r"(a[mt][3]),
                      "r"(b[nt][0]), "r"(b[nt][1]));
    }
}

// tf32 m16n8k8, stride-132 smem
__device__ __forceinline__ void ktile_mma132(const uint32_t (*As)[132], const uint32_t (*Bs)[132],
                                             int m0, int n0, int lane, float acc[4][4][4]) {
#pragma unroll
    for (int ks = 0; ks < 2; ks++) {
        int ar = ks * 8 + (lane & 3);
        int ac = lane >> 2;
        uint32_t a[4][4], b[4][2];
#pragma unroll
        for (int mt = 0; mt < 4; mt++) {
            int m = m0 + mt * 16 + ac;
            a[mt][0] = As[ar][m];
            a[mt][1] = As[ar][m + 8];
            a[mt][2] = As[ar + 4][m];
            a[mt][3] = As[ar + 4][m + 8];
        }
#pragma unroll
        for (int nt = 0; nt < 4; nt++) {
            int nn = n0 + nt * 8 + ac;
            b[nt][0] = Bs[ar][nn];
            b[nt][1] = Bs[ar + 4][nn];
        }
#pragma unroll
        for (int mt = 0; mt < 4; mt++)
#pragma unroll
            for (int nt = 0; nt < 4; nt++)
                asm volatile(
                    "mma.sync.aligned.m16n8k8.row.col.f32.tf32.tf32.f32 "
                    "{%0,%1,%2,%3},{%4,%5,%6,%7},{%8,%9},{%0,%1,%2,%3};"
                    : "+f"(acc[mt][nt][0]), "+f"(acc[mt][nt][1]),
                      "+f"(acc[mt][nt][2]), "+f"(acc[mt][nt][3])
                    : "r"(a[mt][0]), "r"(a[mt][1]), "r"(a[mt][2]), "r"(a[mt][3]),
                      "r"(b[nt][0]), "r"(b[nt][1]));
    }
}

// bf16 m16n8k16, smem pair-packed along k, stride 132
__device__ __forceinline__ void ktile_mma16(const uint32_t (*As)[132], const uint32_t (*Bs)[132],
                                            int m0, int n0, int lane, float acc[4][4][4], int ksteps) {
    for (int ks = 0; ks < ksteps; ks++) {
        int ar = ks * 8 + (lane & 3);
        int ac = lane >> 2;
        uint32_t a[4][4], b[4][2];
#pragma unroll
        for (int mt = 0; mt < 4; mt++) {
            int m = m0 + mt * 16 + ac;
            a[mt][0] = As[ar][m];
            a[mt][1] = As[ar][m + 8];
            a[mt][2] = As[ar + 4][m];
            a[mt][3] = As[ar + 4][m + 8];
        }
#pragma unroll
        for (int nt = 0; nt < 4; nt++) {
            int nn = n0 + nt * 8 + ac;
            b[nt][0] = Bs[ar][nn];
            b[nt][1] = Bs[ar + 4][nn];
        }
#pragma unroll
        for (int mt = 0; mt < 4; mt++)
#pragma unroll
            for (int nt = 0; nt < 4; nt++)
                mma16(acc[mt][nt], a[mt][0], a[mt][1], a[mt][2], a[mt][3], b[nt][0], b[nt][1]);
    }
}

// shared device helper: one bf16 term phase of the out GEMM (K=256, k-slice ksl)
__device__ __forceinline__ void out_term_phase(
    const __nv_bfloat16* __restrict__ term, const float* __restrict__ Wo,
    uint32_t (*As)[132], uint32_t (*Bs)[132],
    int bm0, int m0, int n0, int t, int lane, int n, int ksl, float acc[4][4][4]) {
    for (int kc = 0; kc < 4; kc++) {
        int kb = kc * 64;
        __syncthreads();
#pragma unroll
        for (int i = 0; i < 4; i++) {
            int u = t + 256 * i;
            int row = u >> 3, q = u & 7;
            uint4 v = make_uint4(0, 0, 0, 0);
            if (bm0 + row < n)
                v = *(const uint4*)(term + (size_t)(bm0 + row) * 256 + kb + q * 8);
            As[q * 4 + 0][row] = v.x; As[q * 4 + 1][row] = v.y;
            As[q * 4 + 2][row] = v.z; As[q * 4 + 3][row] = v.w;
        }
#pragma unroll
        for (int i = 0; i < 16; i++) {
            int u = t + 256 * i;
            int c = u & 127, j2 = u >> 7;
            int j = kb + 2 * j2;
            int wrow = ((j >> 7) * 640) + ksl * 128 + (j & 127);
            Bs[j2][c] = packbf(Wo[(size_t)wrow * 128 + c], Wo[(size_t)(wrow + 1) * 128 + c]);
        }
        __syncthreads();
        ktile_mma16((const uint32_t(*)[132])As, (const uint32_t(*)[132])Bs, m0, n0, lane, acc, 4);
    }
}

// ---------------- edge dtype detection ----------------
__global__ void detect_dtype_kernel(const int* __restrict__ ei32, int twoE) {
    __shared__ int nz;
    if (threadIdx.x == 0) nz = 0;
    __syncthreads();
    int samples = min(1024, twoE / 2);
    int local = 0;
    for (int i = threadIdx.x; i < samples; i += blockDim.x)
        if (ei32[2 * i + 1] != 0) local++;
    if (local) atomicAdd(&nz, local);
    __syncthreads();
    if (threadIdx.x == 0) g_is64 = (nz == 0) ? 1 : 0;
}

__device__ __forceinline__ int edge_col(const void* ei, int E, int e) {
    if (g_is64) return (int)((const long long*)ei)[(size_t)E + e];
    return ((const int*)ei)[E + e];
}
__device__ __forceinline__ int edge_row(const void* ei, int E, int e) {
    if (g_is64) return (int)((const long long*)ei)[e];
    return ((const int*)ei)[e];
}

// ---------------- edge prep ----------------
__global__ void edge_deg_kernel(const void* __restrict__ ei, int E) {
    int e = blockIdx.x * blockDim.x + threadIdx.x;
    if (e < E) atomicAdd(&g_deg[edge_col(ei, E, e)], 1);
}

__global__ void scan_blocks_kernel(int n) {
    __shared__ int sh[1024];
    int i = blockIdx.x * 1024 + threadIdx.x;
    int v = (i < n) ? g_deg[i] : 0;
    sh[threadIdx.x] = v;
    __syncthreads();
    for (int off = 1; off < 1024; off <<= 1) {
        int t = (threadIdx.x >= off) ? sh[threadIdx.x - off] : 0;
        __syncthreads();
        sh[threadIdx.x] += t;
        __syncthreads();
    }
    if (i < n) g_csroff[i] = sh[threadIdx.x] - v;
    if (threadIdx.x == 1023) g_blocksum[blockIdx.x] = sh[1023];
}

__global__ void scan_tops_kernel(int nb) {
    __shared__ int sh[128];
    int v = (threadIdx.x < nb) ? g_blocksum[threadIdx.x] : 0;
    sh[threadIdx.x] = v;
    __syncthreads();
    for (int off = 1; off < 128; off <<= 1) {
        int t = (threadIdx.x >= off) ? sh[threadIdx.x - off] : 0;
        __syncthreads();
        sh[threadIdx.x] += t;
        __syncthreads();
    }
    if (threadIdx.x < nb) g_blocksum[threadIdx.x] = sh[threadIdx.x] - v;
}

__global__ void scan_apply_kernel(int n, int E) {
    int i = blockIdx.x * blockDim.x + threadIdx.x;
    if (i < n) {
        int off = g_csroff[i] + g_blocksum[i >> 10];
        g_csroff[i] = off;
        g_csrcur[i] = off;
        int d = g_deg[i];
        g_deginv[i] = (d > 0) ? 1.0f / (float)d : 0.0f;
    }
    if (i == 0) g_csroff[n] = E;
}

__global__ void csr_scatter_kernel(const void* __restrict__ ei, int E) {
    int e = blockIdx.x * blockDim.x + threadIdx.x;
    if (e < E) {
        int c = edge_col(ei, E, e);
        int pos = atomicAdd(&g_csrcur[c], 1);
        g_csrrow[pos] = edge_row(ei, E, e);
    }
}

// ---------------- x -> bf16 copy ----------------
__global__ void x_to_bf16_kernel(const float* __restrict__ x, int n) {
    int i = blockIdx.x * blockDim.x + threadIdx.x;
    if (i < n * 32) {
        float4 v = ((const float4*)x)[i];
        uint2 o;
        o.x = packbf(v.x, v.y);
        o.y = packbf(v.z, v.w);
        ((uint2*)g_x16)[i] = o;
    }
}

// ---------------- iter-1 GCN gather from bf16 x16, dup heads ----------------
__global__ void gcn_gather_x16_kernel(__nv_bfloat16* __restrict__ nxt, int n) {
    int gw = (blockIdx.x * blockDim.x + threadIdx.x) >> 5;
    int lane = threadIdx.x & 31;
    if (gw >= n) return;
    int beg = g_csroff[gw], end = g_csroff[gw + 1];
    float s = 0.5f * g_deginv[gw];
    float a[4];
#pragma unroll
    for (int i = 0; i < 4; i++) a[i] = 0.f;
    int e = beg;
    for (; e + 4 <= end; e += 4) {
        uint2 v0 = *(const uint2*)(g_x16 + (size_t)g_csrrow[e]     * 128 + lane * 4);
        uint2 v1 = *(const uint2*)(g_x16 + (size_t)g_csrrow[e + 1] * 128 + lane * 4);
        uint2 v2 = *(const uint2*)(g_x16 + (size_t)g_csrrow[e + 2] * 128 + lane * 4);
        uint2 v3 = *(const uint2*)(g_x16 + (size_t)g_csrrow[e + 3] * 128 + lane * 4);
#pragma unroll
        for (int p = 0; p < 2; p++) {
            float2 f0 = unpackbf((&v0.x)[p]);
            float2 f1 = unpackbf((&v1.x)[p]);
            float2 f2 = unpackbf((&v2.x)[p]);
            float2 f3 = unpackbf((&v3.x)[p]);
            a[2 * p]     += (f0.x + f1.x) + (f2.x + f3.x);
            a[2 * p + 1] += (f0.y + f1.y) + (f2.y + f3.y);
        }
    }
    for (; e < end; e++) {
        uint2 v0 = *(const uint2*)(g_x16 + (size_t)g_csrrow[e] * 128 + lane * 4);
#pragma unroll
        for (int p = 0; p < 2; p++) {
            float2 f0 = unpackbf((&v0.x)[p]);
            a[2 * p] += f0.x; a[2 * p + 1] += f0.y;
        }
    }
    uint2 o;
    o.x = packbf(s * a[0], s * a[1]);
    o.y = packbf(s * a[2], s * a[3]);
    *(uint2*)(nxt + (size_t)gw * 256 + lane * 4)       = o;
    *(uint2*)(nxt + (size_t)gw * 256 + 128 + lane * 4) = o;
}

// ---------------- GCN gather bf16 (high occupancy, 1 warp/row) ----------------
__global__ void gcn_gather_kernel(__nv_bfloat16* __restrict__ nxt, const __nv_bfloat16* __restrict__ prev, int n) {
    int gw = (blockIdx.x * blockDim.x + threadIdx.x) >> 5;
    int lane = threadIdx.x & 31;
    if (gw >= n) return;
    int beg = g_csroff[gw], end = g_csroff[gw + 1];
    float s = 0.5f * g_deginv[gw];
    float a[8];
#pragma unroll
    for (int i = 0; i < 8; i++) a[i] = 0.f;
    int e = beg;
    for (; e + 4 <= end; e += 4) {
        uint4 v0 = *(const uint4*)(prev + (size_t)g_csrrow[e]     * 256 + lane * 8);
        uint4 v1 = *(const uint4*)(prev + (size_t)g_csrrow[e + 1] * 256 + lane * 8);
        uint4 v2 = *(const uint4*)(prev + (size_t)g_csrrow[e + 2] * 256 + lane * 8);
        uint4 v3 = *(const uint4*)(prev + (size_t)g_csrrow[e + 3] * 256 + lane * 8);
#pragma unroll
        for (int p = 0; p < 4; p++) {
            float2 f0 = unpackbf((&v0.x)[p]);
            float2 f1 = unpackbf((&v1.x)[p]);
            float2 f2 = unpackbf((&v2.x)[p]);
            float2 f3 = unpackbf((&v3.x)[p]);
            a[2 * p]     += (f0.x + f1.x) + (f2.x + f3.x);
            a[2 * p + 1] += (f0.y + f1.y) + (f2.y + f3.y);
        }
    }
    for (; e < end; e++) {
        uint4 v0 = *(const uint4*)(prev + (size_t)g_csrrow[e] * 256 + lane * 8);
#pragma unroll
        for (int p = 0; p < 4; p++) {
            float2 f0 = unpackbf((&v0.x)[p]);
            a[2 * p] += f0.x; a[2 * p + 1] += f0.y;
        }
    }
    uint4 o;
    o.x = packbf(s * a[0], s * a[1]);
    o.y = packbf(s * a[2], s * a[3]);
    o.z = packbf(s * a[4], s * a[5]);
    o.w = packbf(s * a[6], s * a[7]);
    *(uint4*)(nxt + (size_t)gw * 256 + lane * 8) = o;
}

// ---------------- q/k projection GEMM (tf32) + fused L2 norm -> bf16 only ----------------
__global__ void __launch_bounds__(256) qk_gemm_kernel(const float* __restrict__ x,
                               const float* __restrict__ Wq, const float* __restrict__ Wqb,
                               const float* __restrict__ Wk, const float* __restrict__ Wkb,
                               int n) {
    __shared__ uint32_t As[16][128];
    __shared__ uint32_t Bs[16][128];
    __shared__ float rowss[128];
    int t = threadIdx.x;
    int lane = t & 31, wid = t >> 5;
    int m0 = (wid & 1) * 64, n0 = (wid >> 1) * 32;
    int bm0 = blockIdx.x * 128;
    int by = blockIdx.y;
    const float* B   = (by < 2) ? Wq  : Wk;
    const float* bia = (by < 2) ? Wqb : Wkb;
    __nv_bfloat16* dst = (by < 2) ? g_q16 : g_k16;
    int coff = (by & 1) * 128;
    int am = t >> 1, akq = (t & 1) * 8;
    int bk = t >> 4, bnq = (t & 15) * 8;
    float acc[4][4][4];
#pragma unroll
    for (int i = 0; i < 4; i++)
#pragma unroll
        for (int j = 0; j < 4; j++)
#pragma unroll
            for (int r = 0; r < 4; r++) acc[i][j][r] = 0.f;
    if (t < 128) rowss[t] = 0.f;

    for (int k0 = 0; k0 < 128; k0 += 16) {
        float4 a0 = make_float4(0, 0, 0, 0), a1 = a0;
        int row = bm0 + am;
        if (row < n) {
            const float4* ap = (const float4*)(x + (size_t)row * 128 + k0 + akq);
            a0 = ap[0]; a1 = ap[1];
        }
        const float4* bp = (const float4*)(B + (size_t)(k0 + bk) * 256 + coff + bnq);
        float4 b0 = bp[0], b1 = bp[1];
        __syncthreads();
        As[akq + 0][am] = f2tf(a0.x); As[akq + 1][am] = f2tf(a0.y);
        As[akq + 2][am] = f2tf(a0.z); As[akq + 3][am] = f2tf(a0.w);
        As[akq + 4][am] = f2tf(a1.x); As[akq + 5][am] = f2tf(a1.y);
        As[akq + 6][am] = f2tf(a1.z); As[akq + 7][am] = f2tf(a1.w);
        Bs[bk][bnq + 0] = f2tf(b0.x); Bs[bk][bnq + 1] = f2tf(b0.y);
        Bs[bk][bnq + 2] = f2tf(b0.z); Bs[bk][bnq + 3] = f2tf(b0.w);
        Bs[bk][bnq + 4] = f2tf(b1.x); Bs[bk][bnq + 5] = f2tf(b1.y);
        Bs[bk][bnq + 6] = f2tf(b1.z); Bs[bk][bnq + 7] = f2tf(b1.w);
        __syncthreads();
        ktile_mma(As, Bs, m0, n0, lane, acc);
    }

#pragma unroll
    for (int mt = 0; mt < 4; mt++) {
        float ss0 = 0.f, ss1 = 0.f;
#pragma unroll
        for (int nt = 0; nt < 4; nt++) {
            int col = coff + n0 + nt * 8 + 2 * (lane & 3);
            float bx = bia[col], by2 = bia[col + 1];
            acc[mt][nt][0] += bx; acc[mt][nt][1] += by2;
            acc[mt][nt][2] += bx; acc[mt][nt][3] += by2;
            ss0 += acc[mt][nt][0] * acc[mt][nt][0] + acc[mt][nt][1] * acc[mt][nt][1];
            ss1 += acc[mt][nt][2] * acc[mt][nt][2] + acc[mt][nt][3] * acc[mt][nt][3];
        }
        ss0 += __shfl_xor_sync(0xffffffffu, ss0, 1);
        ss0 += __shfl_xor_sync(0xffffffffu, ss0, 2);
        ss1 += __shfl_xor_sync(0xffffffffu, ss1, 1);
        ss1 += __shfl_xor_sync(0xffffffffu, ss1, 2);
        if ((lane & 3) == 0) {
            int r = m0 + mt * 16 + (lane >> 2);
            atomicAdd(&rowss[r], ss0);
            atomicAdd(&rowss[r + 8], ss1);
        }
    }
    __syncthreads();

#pragma unroll
    for (int mt = 0; mt < 4; mt++) {
        int r = m0 + mt * 16 + (lane >> 2);
        float inv0 = rsqrtf(rowss[r]);
        float inv1 = rsqrtf(rowss[r + 8]);
        int row = bm0 + r;
#pragma unroll
        for (int nt = 0; nt < 4; nt++) {
            int col = coff + n0 + nt * 8 + 2 * (lane & 3);
            if (row < n)
                *(uint32_t*)(dst + (size_t)row * 256 + col) =
                    packbf(acc[mt][nt][0] * inv0, acc[mt][nt][1] * inv0);
            if (row + 8 < n)
                *(uint32_t*)(dst + (size_t)(row + 8) * 256 + col) =
                    packbf(acc[mt][nt][2] * inv1, acc[mt][nt][3] * inv1);
        }
    }
}

// ---------------- ks_sum from bf16 (fp32 accumulate) ----------------
__global__ void kssum_kernel(int n) {
    int col = threadIdx.x;
    int start = blockIdx.x * 512;
    int end = min(start + 512, n);
    float s = 0.f;
    for (int node = start; node < end; node++)
        s += __bfloat162float(g_k16[(size_t)node * 256 + col]);
    atomicAdd(&g_kssum[col], s);
}

// ---------------- den = q16 . ks_sum + n ----------------
__global__ void den_kernel(int n) {
    int gw = (blockIdx.x * blockDim.x + threadIdx.x) >> 5;
    int lane = threadIdx.x & 31;
    if (gw >= n * 2) return;
    int node = gw >> 1, h = gw & 1;
    uint2 qu = *(const uint2*)(g_q16 + (size_t)node * 256 + h * 128 + lane * 4);
    float2 qa = unpackbf(qu.x), qb = unpackbf(qu.y);
    float4 kv = ((const float4*)(g_kssum + h * 128))[lane];
    float d = qa.x * kv.x + qa.y * kv.y + qb.x * kv.z + qb.y * kv.w;
#pragma unroll
    for (int o = 16; o; o >>= 1) d += __shfl_xor_sync(0xffffffffu, d, o);
    if (lane == 0) g_den[node * 2 + h] = d + (float)n;
}

// ---------------- kvs[h] += ks^T @ prev (bf16 mma) ; vs_sum (fp32) ----------------
template <int TermSrc>
__global__ void __launch_bounds__(256) kvs_reduce_t_kernel(const void* __restrict__ prevv, int n) {
    int h = blockIdx.y;
    int c0 = blockIdx.x * 1024;
    int c1 = min(c0 + 1024, n);
    __shared__ uint32_t ksS[16][132];
    __shared__ uint32_t pvS[16][132];
    int t = threadIdx.x;
    int lane = t & 31, wid = t >> 5;
    int m0 = (wid & 1) * 64, n0 = (wid >> 1) * 32;
    float acc[4][4][4];
#pragma unroll
    for (int i = 0; i < 4; i++)
#pragma unroll
        for (int j = 0; j < 4; j++)
#pragma unroll
            for (int r = 0; r < 4; r++) acc[i][j][r] = 0.f;
    float colsum = 0.f;
    int myc = t & 127, hb = (t >> 7) * 8;

    for (int s = c0; s < c1; s += 32) {
        __syncthreads();
#pragma unroll
        for (int i = 0; i < 4; i++) {
            int u = t + 256 * i;
            int nn = u >> 6, m2 = u & 63;
            int nd0 = s + 2 * nn, nd1 = nd0 + 1;
            uint32_t k0 = 0, k1 = 0, p0 = 0, p1 = 0;
            if (nd0 < c1) {
                k0 = *(const uint32_t*)(g_k16 + (size_t)nd0 * 256 + h * 128 + 2 * m2);
                if (TermSrc) {
                    float2 xv = *(const float2*)((const float*)prevv + (size_t)nd0 * 128 + 2 * m2);
                    p0 = packbf(xv.x, xv.y);
                } else {
                    p0 = *(const uint32_t*)((const __nv_bfloat16*)prevv + (size_t)nd0 * 256 + h * 128 + 2 * m2);
                }
            }
            if (nd1 < c1) {
                k1 = *(const uint32_t*)(g_k16 + (size_t)nd1 * 256 + h * 128 + 2 * m2);
                if (TermSrc) {
                    float2 xv = *(const float2*)((const float*)prevv + (size_t)nd1 * 128 + 2 * m2);
                    p1 = packbf(xv.x, xv.y);
                } else {
                    p1 = *(const uint32_t*)((const __nv_bfloat16*)prevv + (size_t)nd1 * 256 + h * 128 + 2 * m2);
                }
            }
            ksS[nn][2 * m2]     = __byte_perm(k0, k1, 0x5410);
            ksS[nn][2 * m2 + 1] = __byte_perm(k0, k1, 0x7632);
            pvS[nn][2 * m2]     = __byte_perm(p0, p1, 0x5410);
            pvS[nn][2 * m2 + 1] = __byte_perm(p0, p1, 0x7632);
        }
        __syncthreads();
        ktile_mma16(ksS, pvS, m0, n0, lane, acc, 2);
#pragma unroll
        for (int r = 0; r < 8; r++) {
            float2 f = unpackbf(pvS[hb + r][myc]);
            colsum += f.x + f.y;
        }
    }
    atomicAdd(&g_vssum[h * 128 + myc], colsum);
    float* kv = g_kvs + h * 16384;
#pragma unroll
    for (int mt = 0; mt < 4; mt++) {
        int m = m0 + mt * 16 + (lane >> 2);
#pragma unroll
        for (int nt = 0; nt < 4; nt++) {
            int c = n0 + nt * 8 + 2 * (lane & 3);
            atomicAdd(&kv[m * 128 + c],           acc[mt][nt][0]);
            atomicAdd(&kv[m * 128 + c + 1],       acc[mt][nt][1]);
            atomicAdd(&kv[(m + 8) * 128 + c],     acc[mt][nt][2]);
            atomicAdd(&kv[(m + 8) * 128 + c + 1], acc[mt][nt][3]);
        }
    }
}

// ---------------- nxt += (qs @ kvs + vs_sum) / den  (bf16 mma, RMW-add) ----------------
__global__ void __launch_bounds__(256) qkv_combine_kernel(__nv_bfloat16* __restrict__ nxt, int n) {
    int h = blockIdx.y;
    __shared__ uint32_t As[32][132];
    __shared__ uint32_t Bs[32][132];
    int t = threadIdx.x;
    int lane = t & 31, wid = t >> 5;
    int m0 = (wid & 1) * 64, n0 = (wid >> 1) * 32;
    int bm0 = blockIdx.x * 128;
    const float* kvp = g_kvs + h * 16384;
    float acc[4][4][4];
#pragma unroll
    for (int i = 0; i < 4; i++)
#pragma unroll
        for (int j = 0; j < 4; j++)
#pragma unroll
            for (int r = 0; r < 4; r++) acc[i][j][r] = 0.f;

#pragma unroll
    for (int kc = 0; kc < 2; kc++) {
        int kb = kc * 64;
        __syncthreads();
#pragma unroll
        for (int i = 0; i < 4; i++) {
            int u = t + 256 * i;
            int row = u >> 3, q = u & 7;
            uint4 v = make_uint4(0, 0, 0, 0);
            if (bm0 + row < n)
                v = *(const uint4*)(g_q16 + (size_t)(bm0 + row) * 256 + h * 128 + kb + q * 8);
            As[q * 4 + 0][row] = v.x; As[q * 4 + 1][row] = v.y;
            As[q * 4 + 2][row] = v.z; As[q * 4 + 3][row] = v.w;
        }
#pragma unroll
        for (int i = 0; i < 16; i++) {
            int u = t + 256 * i;
            int d = u & 127, m2 = u >> 7;
            int m = kb + 2 * m2;
            Bs[m2][d] = packbf(kvp[m * 128 + d], kvp[(m + 1) * 128 + d]);
        }
        __syncthreads();
        ktile_mma16((const uint32_t(*)[132])As, (const uint32_t(*)[132])Bs, m0, n0, lane, acc, 4);
    }
#pragma unroll
    for (int mt = 0; mt < 4; mt++) {
        int row = bm0 + m0 + mt * 16 + (lane >> 2);
#pragma unroll
        for (int nt = 0; nt < 4; nt++) {
            int col = n0 + nt * 8 + 2 * (lane & 3);
            float vs0 = g_vssum[h * 128 + col], vs1 = g_vssum[h * 128 + col + 1];
            if (row < n) {
                float invd = 1.0f / g_den[row * 2 + h];
                uint32_t* p = (uint32_t*)(nxt + (size_t)row * 256 + h * 128 + col);
                float2 old = unpackbf(*p);
                *p = packbf(old.x + (acc[mt][nt][0] + vs0) * invd,
                            old.y + (acc[mt][nt][1] + vs1) * invd);
            }
            if (row + 8 < n) {
                float invd = 1.0f / g_den[(row + 8) * 2 + h];
                uint32_t* p = (uint32_t*)(nxt + (size_t)(row + 8) * 256 + h * 128 + col);
                float2 old = unpackbf(*p);
                *p = packbf(old.x + (acc[mt][nt][2] + vs0) * invd,
                            old.y + (acc[mt][nt][3] + vs1) * invd);
            }
        }
    }
}

// ---------------- out part A: out = 0.5*(x@(Wo0h0+Wo0h1) + t1@Wo_1 + t2@Wo_2 + b) ----------------
__global__ void __launch_bounds__(256) out_partA_kernel(
    const float* __restrict__ x, const float* __restrict__ Wo, const float* __restrict__ Wob,
    const __nv_bfloat16* __restrict__ t1, const __nv_bfloat16* __restrict__ t2,
    float* __restrict__ out, int n) {
    __shared__ uint32_t As[32][132];
    __shared__ uint32_t Bs[32][132];
    int t = threadIdx.x;
    int lane = t & 31, wid = t >> 5;
    int m0 = (wid & 1) * 64, n0 = (wid >> 1) * 32;
    int bm0 = blockIdx.x * 128;
    float acc[4][4][4];
#pragma unroll
    for (int i = 0; i < 4; i++)
#pragma unroll
        for (int j = 0; j < 4; j++)
#pragma unroll
            for (int r = 0; r < 4; r++) acc[i][j][r] = 0.f;

    // phase A: tf32 over x
    {
        int am = t >> 1, akq = (t & 1) * 8;
        int bk = t >> 4, bnq = (t & 15) * 8;
        for (int k0 = 0; k0 < 128; k0 += 16) {
            float4 a0 = make_float4(0, 0, 0, 0), a1 = a0;
            int row = bm0 + am;
            if (row < n) {
                const float4* ap = (const float4*)(x + (size_t)row * 128 + k0 + akq);
                a0 = ap[0]; a1 = ap[1];
            }
            int wr = k0 + bk;
            const float4* p0 = (const float4*)(Wo + (size_t)wr * 128 + bnq);
            const float4* p1 = (const float4*)(Wo + (size_t)(640 + wr) * 128 + bnq);
            float4 u0 = p0[0], u1 = p0[1], v0 = p1[0], v1 = p1[1];
            __syncthreads();
            As[akq + 0][am] = f2tf(a0.x); As[akq + 1][am] = f2tf(a0.y);
            As[akq + 2][am] = f2tf(a0.z); As[akq + 3][am] = f2tf(a0.w);
            As[akq + 4][am] = f2tf(a1.x); As[akq + 5][am] = f2tf(a1.y);
            As[akq + 6][am] = f2tf(a1.z); As[akq + 7][am] = f2tf(a1.w);
            Bs[bk][bnq + 0] = f2tf(u0.x + v0.x); Bs[bk][bnq + 1] = f2tf(u0.y + v0.y);
            Bs[bk][bnq + 2] = f2tf(u0.z + v0.z); Bs[bk][bnq + 3] = f2tf(u0.w + v0.w);
            Bs[bk][bnq + 4] = f2tf(u1.x + v1.x); Bs[bk][bnq + 5] = f2tf(u1.y + v1.y);
            Bs[bk][bnq + 6] = f2tf(u1.z + v1.z); Bs[bk][bnq + 7] = f2tf(u1.w + v1.w);
            __syncthreads();
            ktile_mma132((const uint32_t(*)[132])As, (const uint32_t(*)[132])Bs, m0, n0, lane, acc);
        }
    }
    // phases t1, t2
    out_term_phase(t1, Wo, As, Bs, bm0, m0, n0, t, lane, n, 1, acc);
    out_term_phase(t2, Wo, As, Bs, bm0, m0, n0, t, lane, n, 2, acc);

#pragma unroll
    for (int mt = 0; mt < 4; mt++) {
        int row = bm0 + m0 + mt * 16 + (lane >> 2);
#pragma unroll
        for (int nt = 0; nt < 4; nt++) {
            int col = n0 + nt * 8 + 2 * (lane & 3);
            float bx = Wob[col], by2 = Wob[col + 1];
            if (row < n) {
                float2 v = make_float2(0.5f * (acc[mt][nt][0] + bx), 0.5f * (acc[mt][nt][1] + by2));
                *(float2*)&out[(size_t)row * 128 + col] = v;
            }
            if (row + 8 < n) {
                float2 v = make_float2(0.5f * (acc[mt][nt][2] + bx), 0.5f * (acc[mt][nt][3] + by2));
                *(float2*)&out[(size_t)(row + 8) * 128 + col] = v;
            }
        }
    }
}

// ---------------- out part B: out += 0.5*(t3@Wo_3 + t4@Wo_4) ----------------
__global__ void __launch_bounds__(256) out_partB_kernel(
    const float* __restrict__ Wo,
    const __nv_bfloat16* __restrict__ t3, const __nv_bfloat16* __restrict__ t4,
    float* __restrict__ out, int n) {
    __shared__ uint32_t As[32][132];
    __shared__ uint32_t Bs[32][132];
    int t = threadIdx.x;
    int lane = t & 31, wid = t >> 5;
    int m0 = (wid & 1) * 64, n0 = (wid >> 1) * 32;
    int bm0 = blockIdx.x * 128;
    float acc[4][4][4];
#pragma unroll
    for (int i = 0; i < 4; i++)
#pragma unroll
        for (int j = 0; j < 4; j++)
#pragma unroll
            for (int r = 0; r < 4; r++) acc[i][j][r] = 0.f;

    out_term_phase(t3, Wo, As, Bs, bm0, m0, n0, t, lane, n, 3, acc);
    out_term_phase(t4, Wo, As, Bs, bm0, m0, n0, t, lane, n, 4, acc);

#pragma unroll
    for (int mt = 0; mt < 4; mt++) {
        int row = bm0 + m0 + mt * 16 + (lane >> 2);
#pragma unroll
        for (int nt = 0; nt < 4; nt++) {
            int col = n0 + nt * 8 + 2 * (lane & 3);
            if (row < n) {
                float2 c = *(float2*)&out[(size_t)row * 128 + col];
                c.x += 0.5f * acc[mt][nt][0];
                c.y += 0.5f * acc[mt][nt][1];
                *(float2*)&out[(size_t)row * 128 + col] = c;
            }
            if (row + 8 < n) {
                float2 c = *(float2*)&out[(size_t)(row + 8) * 128 + col];
                c.x += 0.5f * acc[mt][nt][2];
                c.y += 0.5f * acc[mt][nt][3];
                *(float2*)&out[(size_t)(row + 8) * 128 + col] = c;
            }
        }
    }
}

// ---------------- host orchestration ----------------
extern "C" void kernel_launch(void* const* d_in, const int* in_sizes, int n_in,
                              void* d_out, int out_size) {
    const float* x   = (const float*)d_in[0];
    const void*  ei  = d_in[1];
    const float* Wqw = (const float*)d_in[2];
    const float* Wqb = (const float*)d_in[3];
    const float* Wkw = (const float*)d_in[4];
    const float* Wkb = (const float*)d_in[5];
    const float* Wow = (const float*)d_in[6];
    const float* Wob = (const float*)d_in[7];
    float* out = (float*)d_out;

    int n = in_sizes[0] / CC;
    int E = in_sizes[1] / 2;

    void *pDeg, *pKvs, *pVs, *pKs;
    void *pT[4];
    cudaGetSymbolAddress(&pDeg, g_deg);
    cudaGetSymbolAddress(&pKvs, g_kvs);
    cudaGetSymbolAddress(&pVs,  g_vssum);
    cudaGetSymbolAddress(&pKs,  g_kssum);
    cudaGetSymbolAddress(&pT[0], g_t1);
    cudaGetSymbolAddress(&pT[1], g_t2);
    cudaGetSymbolAddress(&pT[2], g_t3);
    cudaGetSymbolAddress(&pT[3], g_t4);

    static int inited = 0;
    static cudaStream_t sB, sC;
    static cudaEvent_t evQ[5], evC[5], evA;
    if (!inited) {
        cudaStreamCreateWithFlags(&sB, cudaStreamNonBlocking);
        cudaStreamCreateWithFlags(&sC, cudaStreamNonBlocking);
        for (int i = 0; i < 5; i++) {
            cudaEventCreateWithFlags(&evQ[i], cudaEventDisableTiming);
            cudaEventCreateWithFlags(&evC[i], cudaEventDisableTiming);
        }
        cudaEventCreateWithFlags(&evA, cudaEventDisableTiming);
        inited = 1;
    }

    int nb  = (n + 127) / 128;
    int nkv = (n + 1023) / 1024;
    int nbScan = (n + 1023) / 1024;

    // fork sC off stream 0 at capture start
    cudaEventRecord(evC[0], 0);
    cudaStreamWaitEvent(sC, evC[0], 0);

    // ---- edge chain on sC ----
    x_to_bf16_kernel<<<(n * 32 + 255) / 256, 256, 0, sC>>>(x, n);
    cudaMemsetAsync(pDeg, 0, (size_t)n * sizeof(int), sC);
    detect_dtype_kernel<<<1, 256, 0, sC>>>((const int*)ei, in_sizes[1]);
    edge_deg_kernel<<<(E + 255) / 256, 256, 0, sC>>>(ei, E);
    scan_blocks_kernel<<<nbScan, 1024, 0, sC>>>(n);
    scan_tops_kernel<<<1, 128, 0, sC>>>(nbScan);
    scan_apply_kernel<<<(n + 255) / 256, 256, 0, sC>>>(n, E);
    csr_scatter_kernel<<<(E + 255) / 256, 256, 0, sC>>>(ei, E);
    gcn_gather_x16_kernel<<<(n * 32 + 255) / 256, 256, 0, sC>>>((__nv_bfloat16*)pT[0], n);
    cudaEventRecord(evC[1], sC);

    // ---- projection chain on stream 0 (concurrent) ----
    dim3 gqk((n + 127) / 128, 4);
    qk_gemm_kernel<<<gqk, 256>>>(x, Wqw, Wqb, Wkw, Wkb, n);
    cudaMemsetAsync(pKs, 0, (size_t)HH * CC * sizeof(float));
    kssum_kernel<<<(n + 511) / 512, 256>>>(n);
    den_kernel<<<(n * 2 * 32 + 255) / 256, 256>>>(n);

    // ---- iter 1: kvs from x fp32 directly ----
    cudaMemsetAsync(pKvs, 0, (size_t)HH * CC * CC * sizeof(float));
    cudaMemsetAsync(pVs,  0, (size_t)HH * CC * sizeof(float));
    kvs_reduce_t_kernel<1><<<dim3(nkv, 2), 256>>>(x, n);
    cudaStreamWaitEvent(0, evC[1], 0);
    qkv_combine_kernel<<<dim3(nb, 2), 256>>>((__nv_bfloat16*)pT[0], n);
    cudaEventRecord(evQ[1], 0);

    // ---- iters 2..4: gather on sC || kvs on 0; combine joins ----
    for (int ksl = 2; ksl <= 4; ksl++) {
        __nv_bfloat16* prev = (__nv_bfloat16*)pT[ksl - 2];
        __nv_bfloat16* nxt  = (__nv_bfloat16*)pT[ksl - 1];
        cudaStreamWaitEvent(sC, evQ[ksl - 1], 0);
        gcn_gather_kernel<<<(n * 32 + 255) / 256, 256, 0, sC>>>(nxt, prev, n);
        cudaEventRecord(evC[ksl], sC);

        cudaMemsetAsync(pKvs, 0, (size_t)HH * CC * CC * sizeof(float));
        cudaMemsetAsync(pVs,  0, (size_t)HH * CC * sizeof(float));
        kvs_reduce_t_kernel<0><<<dim3(nkv, 2), 256>>>(prev, n);

        cudaStreamWaitEvent(0, evC[ksl], 0);
        qkv_combine_kernel<<<dim3(nb, 2), 256>>>(nxt, n);
        cudaEventRecord(evQ[ksl], 0);

        // after combine2: t1,t2 final -> launch out part A overlapped with iters 3-4
        if (ksl == 2) {
            cudaStreamWaitEvent(sB, evQ[2], 0);
            out_partA_kernel<<<nb, 256, 0, sB>>>(x, Wow, Wob,
                                                 (const __nv_bfloat16*)pT[0],
                                                 (const __nv_bfloat16*)pT[1], out, n);
            cudaEventRecord(evA, sB);
        }
    }

    // ---- tail: out += t3,t4 contributions (needs partA done + combine4 done) ----
    cudaStreamWaitEvent(0, evA, 0);
    out_partB_kernel<<<nb, 256>>>(Wow, (const __nv_bfloat16*)pT[2],
                                  (const __nv_bfloat16*)pT[3], out, n);
}

// round 12
// speedup vs baseline: 1.3788x; 1.0236x over previous
#include <cuda_runtime.h>
#include <cuda_bf16.h>
#include <cstdint>

#define CC   128
#define HH   2
#define HC   256
#define NMAX 100000
#define EMAX 1600000

// ---------------- device scratch (static, no allocation) ----------------
__device__ __nv_bfloat16 g_q16[(size_t)NMAX * HC];
__device__ __nv_bfloat16 g_k16[(size_t)NMAX * HC];
__device__ __nv_bfloat16 g_x16[(size_t)NMAX * CC];      // bf16 copy of x
__device__ __nv_bfloat16 g_t1[(size_t)NMAX * HC];       // term 1..4 (bf16)
__device__ __nv_bfloat16 g_t2[(size_t)NMAX * HC];
__device__ __nv_bfloat16 g_t3[(size_t)NMAX * HC];
__device__ __nv_bfloat16 g_t4[(size_t)NMAX * HC];
__device__ __nv_bfloat16 g_G[(size_t)NMAX * HC];        // gcn part
__device__ __nv_bfloat16 g_A[(size_t)NMAX * HC];        // attn part
__device__ float g_deginv[NMAX];
__device__ int   g_deg[NMAX];
__device__ int   g_csroff[NMAX + 1];
__device__ int   g_csrcur[NMAX];
__device__ int   g_csrrow[EMAX];
__device__ int   g_blocksum[128];
__device__ float g_den[NMAX * HH];
__device__ float g_kvs[HH * CC * CC];
__device__ float g_vssum[HH * CC];
__device__ float g_kssum[HH * CC];
__device__ int   g_is64;

// ---------------- helpers ----------------
__device__ __forceinline__ uint32_t f2tf(float x) {
    uint32_t r;
    asm("cvt.rna.tf32.f32 %0, %1;" : "=r"(r) : "f"(x));
    return r;
}
__device__ __forceinline__ uint32_t packbf(float lo, float hi) {
    __nv_bfloat162 h2 = __floats2bfloat162_rn(lo, hi);
    return *reinterpret_cast<uint32_t*>(&h2);
}
__device__ __forceinline__ float2 unpackbf(uint32_t u) {
    __nv_bfloat162 h2 = *reinterpret_cast<__nv_bfloat162*>(&u);
    return __bfloat1622float2(h2);
}

__device__ __forceinline__ void mma16(float* c, uint32_t a0, uint32_t a1, uint32_t a2,
                                      uint32_t a3, uint32_t b0, uint32_t b1) {
    asm volatile(
        "mma.sync.aligned.m16n8k16.row.col.f32.bf16.bf16.f32 "
        "{%0,%1,%2,%3},{%4,%5,%6,%7},{%8,%9},{%0,%1,%2,%3};"
        : "+f"(c[0]), "+f"(c[1]), "+f"(c[2]), "+f"(c[3])
        : "r"(a0), "r"(a1), "r"(a2), "r"(a3), "r"(b0), "r"(b1));
}

// tf32 m16n8k8 over a 16-deep k tile, stride-128 smem
__device__ __forceinline__ void ktile_mma(const uint32_t (*As)[128], const uint32_t (*Bs)[128],
                                          int m0, int n0, int lane, float acc[4][4][4]) {
#pragma unroll
    for (int ks = 0; ks < 2; ks++) {
        int ar = ks * 8 + (lane & 3);
        int ac = lane >> 2;
        uint32_t a[4][4], b[4][2];
#pragma unroll
        for (int mt = 0; mt < 4; mt++) {
            int m = m0 + mt * 16 + ac;
            a[mt][0] = As[ar][m];
            a[mt][1] = As[ar][m + 8];
            a[mt][2] = As[ar + 4][m];
            a[mt][3] = As[ar + 4][m + 8];
        }
#pragma unroll
        for (int nt = 0; nt < 4; nt++) {
            int nn = n0 + nt * 8 + ac;
            b[nt][0] = Bs[ar][nn];
            b[nt][1] = Bs[ar + 4][nn];
        }
#pragma unroll
        for (int mt = 0; mt < 4; mt++)
#pragma unroll
            for (int nt = 0; nt < 4; nt++)
                asm volatile(
                    "mma.sync.aligned.m16n8k8.row.col.f32.tf32.tf32.f32 "
                    "{%0,%1,%2,%3},{%4,%5,%6,%7},{%8,%9},{%0,%1,%2,%3};"
                    : "+f"(acc[mt][nt][0]), "+f"(acc[mt][nt][1]),
                      "+f"(acc[mt][nt][2]), "+f"(acc[mt][nt][3])
                    : "r"(a[mt][0]), "r"(a[mt][1]), "r"(a[mt][2]), "r"(a[mt][3]),
                      "r"(b[nt][0]), "r"(b[nt][1]));
    }
}

// tf32 m16n8k8, stride-132 smem
__device__ __forceinline__ void ktile_mma132(const uint32_t (*As)[132], const uint32_t (*Bs)[132],
                                             int m0, int n0, int lane, float acc[4][4][4]) {
#pragma unroll
    for (int ks = 0; ks < 2; ks++) {
        int ar = ks * 8 + (lane & 3);
        int ac = lane >> 2;
        uint32_t a[4][4], b[4][2];
#pragma unroll
        for (int mt = 0; mt < 4; mt++) {
            int m = m0 + mt * 16 + ac;
            a[mt][0] = As[ar][m];
            a[mt][1] = As[ar][m + 8];
            a[mt][2] = As[ar + 4][m];
            a[mt][3] = As[ar + 4][m + 8];
        }
#pragma unroll
        for (int nt = 0; nt < 4; nt++) {
            int nn = n0 + nt * 8 + ac;
            b[nt][0] = Bs[ar][nn];
            b[nt][1] = Bs[ar + 4][nn];
        }
#pragma unroll
        for (int mt = 0; mt < 4; mt++)
#pragma unroll
            for (int nt = 0; nt < 4; nt++)
                asm volatile(
                    "mma.sync.aligned.m16n8k8.row.col.f32.tf32.tf32.f32 "
                    "{%0,%1,%2,%3},{%4,%5,%6,%7},{%8,%9},{%0,%1,%2,%3};"
                    : "+f"(acc[mt][nt][0]), "+f"(acc[mt][nt][1]),
                      "+f"(acc[mt][nt][2]), "+f"(acc[mt][nt][3])
                    : "r"(a[mt][0]), "r"(a[mt][1]), "r"(a[mt][2]), "r"(a[mt][3]),
                      "r"(b[nt][0]), "r"(b[nt][1]));
    }
}

// bf16 m16n8k16, smem pair-packed along k, stride 132
__device__ __forceinline__ void ktile_mma16(const uint32_t (*As)[132], const uint32_t (*Bs)[132],
                                            int m0, int n0, int lane, float acc[4][4][4], int ksteps) {
    for (int ks = 0; ks < ksteps; ks++) {
        int ar = ks * 8 + (lane & 3);
        int ac = lane >> 2;
        uint32_t a[4][4], b[4][2];
#pragma unroll
        for (int mt = 0; mt < 4; mt++) {
            int m = m0 + mt * 16 + ac;
            a[mt][0] = As[ar][m];
            a[mt][1] = As[ar][m + 8];
            a[mt][2] = As[ar + 4][m];
            a[mt][3] = As[ar + 4][m + 8];
        }
#pragma unroll
        for (int nt = 0; nt < 4; nt++) {
            int nn = n0 + nt * 8 + ac;
            b[nt][0] = Bs[ar][nn];
            b[nt][1] = Bs[ar + 4][nn];
        }
#pragma unroll
        for (int mt = 0; mt < 4; mt++)
#pragma unroll
            for (int nt = 0; nt < 4; nt++)
                mma16(acc[mt][nt], a[mt][0], a[mt][1], a[mt][2], a[mt][3], b[nt][0], b[nt][1]);
    }
}

// one bf16 term phase of the out GEMM (K=256, k-slice ksl)
__device__ __forceinline__ void out_term_phase(
    const __nv_bfloat16* __restrict__ term, const float* __restrict__ Wo,
    uint32_t (*As)[132], uint32_t (*Bs)[132],
    int bm0, int m0, int n0, int t, int lane, int n, int ksl, float acc[4][4][4]) {
    for (int kc = 0; kc < 4; kc++) {
        int kb = kc * 64;
        __syncthreads();
#pragma unroll
        for (int i = 0; i < 4; i++) {
            int u = t + 256 * i;
            int row = u >> 3, q = u & 7;
            uint4 v = make_uint4(0, 0, 0, 0);
            if (bm0 + row < n)
                v = *(const uint4*)(term + (size_t)(bm0 + row) * 256 + kb + q * 8);
            As[q * 4 + 0][row] = v.x; As[q * 4 + 1][row] = v.y;
            As[q * 4 + 2][row] = v.z; As[q * 4 + 3][row] = v.w;
        }
#pragma unroll
        for (int i = 0; i < 16; i++) {
            int u = t + 256 * i;
            int c = u & 127, j2 = u >> 7;
            int j = kb + 2 * j2;
            int wrow = ((j >> 7) * 640) + ksl * 128 + (j & 127);
            Bs[j2][c] = packbf(Wo[(size_t)wrow * 128 + c], Wo[(size_t)(wrow + 1) * 128 + c]);
        }
        __syncthreads();
        ktile_mma16((const uint32_t(*)[132])As, (const uint32_t(*)[132])Bs, m0, n0, lane, acc, 4);
    }
}

// ---------------- edge dtype detection ----------------
__global__ void detect_dtype_kernel(const int* __restrict__ ei32, int twoE) {
    __shared__ int nz;
    if (threadIdx.x == 0) nz = 0;
    __syncthreads();
    int samples = min(1024, twoE / 2);
    int local = 0;
    for (int i = threadIdx.x; i < samples; i += blockDim.x)
        if (ei32[2 * i + 1] != 0) local++;
    if (local) atomicAdd(&nz, local);
    __syncthreads();
    if (threadIdx.x == 0) g_is64 = (nz == 0) ? 1 : 0;
}

__device__ __forceinline__ int edge_col(const void* ei, int E, int e) {
    if (g_is64) return (int)((const long long*)ei)[(size_t)E + e];
    return ((const int*)ei)[E + e];
}
__device__ __forceinline__ int edge_row(const void* ei, int E, int e) {
    if (g_is64) return (int)((const long long*)ei)[e];
    return ((const int*)ei)[e];
}

// ---------------- edge prep ----------------
__global__ void edge_deg_kernel(const void* __restrict__ ei, int E) {
    int e = blockIdx.x * blockDim.x + threadIdx.x;
    if (e < E) atomicAdd(&g_deg[edge_col(ei, E, e)], 1);
}

__global__ void scan_blocks_kernel(int n) {
    __shared__ int sh[1024];
    int i = blockIdx.x * 1024 + threadIdx.x;
    int v = (i < n) ? g_deg[i] : 0;
    sh[threadIdx.x] = v;
    __syncthreads();
    for (int off = 1; off < 1024; off <<= 1) {
        int t = (threadIdx.x >= off) ? sh[threadIdx.x - off] : 0;
        __syncthreads();
        sh[threadIdx.x] += t;
        __syncthreads();
    }
    if (i < n) g_csroff[i] = sh[threadIdx.x] - v;
    if (threadIdx.x == 1023) g_blocksum[blockIdx.x] = sh[1023];
}

__global__ void scan_tops_kernel(int nb) {
    __shared__ int sh[128];
    int v = (threadIdx.x < nb) ? g_blocksum[threadIdx.x] : 0;
    sh[threadIdx.x] = v;
    __syncthreads();
    for (int off = 1; off < 128; off <<= 1) {
        int t = (threadIdx.x >= off) ? sh[threadIdx.x - off] : 0;
        __syncthreads();
        sh[threadIdx.x] += t;
        __syncthreads();
    }
    if (threadIdx.x < nb) g_blocksum[threadIdx.x] = sh[threadIdx.x] - v;
}

__global__ void scan_apply_kernel(int n, int E) {
    int i = blockIdx.x * blockDim.x + threadIdx.x;
    if (i < n) {
        int off = g_csroff[i] + g_blocksum[i >> 10];
        g_csroff[i] = off;
        g_csrcur[i] = off;
        int d = g_deg[i];
        g_deginv[i] = (d > 0) ? 1.0f / (float)d : 0.0f;
    }
    if (i == 0) g_csroff[n] = E;
}

__global__ void csr_scatter_kernel(const void* __restrict__ ei, int E) {
    int e = blockIdx.x * blockDim.x + threadIdx.x;
    if (e < E) {
        int c = edge_col(ei, E, e);
        int pos = atomicAdd(&g_csrcur[c], 1);
        g_csrrow[pos] = edge_row(ei, E, e);
    }
}

// ---------------- x -> bf16 copy ----------------
__global__ void x_to_bf16_kernel(const float* __restrict__ x, int n) {
    int i = blockIdx.x * blockDim.x + threadIdx.x;
    if (i < n * 32) {
        float4 v = ((const float4*)x)[i];
        uint2 o;
        o.x = packbf(v.x, v.y);
        o.y = packbf(v.z, v.w);
        ((uint2*)g_x16)[i] = o;
    }
}

// ---------------- iter-1 GCN gather from bf16 x16, dup heads -> G ----------------
__global__ void gcn_gather_x16_kernel(__nv_bfloat16* __restrict__ G, int n) {
    int gw = (blockIdx.x * blockDim.x + threadIdx.x) >> 5;
    int lane = threadIdx.x & 31;
    if (gw >= n) return;
    int beg = g_csroff[gw], end = g_csroff[gw + 1];
    float s = 0.5f * g_deginv[gw];
    float a[4];
#pragma unroll
    for (int i = 0; i < 4; i++) a[i] = 0.f;
    int e = beg;
    for (; e + 4 <= end; e += 4) {
        uint2 v0 = *(const uint2*)(g_x16 + (size_t)g_csrrow[e]     * 128 + lane * 4);
        uint2 v1 = *(const uint2*)(g_x16 + (size_t)g_csrrow[e + 1] * 128 + lane * 4);
        uint2 v2 = *(const uint2*)(g_x16 + (size_t)g_csrrow[e + 2] * 128 + lane * 4);
        uint2 v3 = *(const uint2*)(g_x16 + (size_t)g_csrrow[e + 3] * 128 + lane * 4);
#pragma unroll
        for (int p = 0; p < 2; p++) {
            float2 f0 = unpackbf((&v0.x)[p]);
            float2 f1 = unpackbf((&v1.x)[p]);
            float2 f2 = unpackbf((&v2.x)[p]);
            float2 f3 = unpackbf((&v3.x)[p]);
            a[2 * p]     += (f0.x + f1.x) + (f2.x + f3.x);
            a[2 * p + 1] += (f0.y + f1.y) + (f2.y + f3.y);
        }
    }
    for (; e < end; e++) {
        uint2 v0 = *(const uint2*)(g_x16 + (size_t)g_csrrow[e] * 128 + lane * 4);
#pragma unroll
        for (int p = 0; p < 2; p++) {
            float2 f0 = unpackbf((&v0.x)[p]);
            a[2 * p] += f0.x; a[2 * p + 1] += f0.y;
        }
    }
    uint2 o;
    o.x = packbf(s * a[0], s * a[1]);
    o.y = packbf(s * a[2], s * a[3]);
    *(uint2*)(G + (size_t)gw * 256 + lane * 4)       = o;
    *(uint2*)(G + (size_t)gw * 256 + 128 + lane * 4) = o;
}

// ---------------- GCN gather bf16 (1 warp/row) prev -> G ----------------
__global__ void gcn_gather_kernel(__nv_bfloat16* __restrict__ G, const __nv_bfloat16* __restrict__ prev, int n) {
    int gw = (blockIdx.x * blockDim.x + threadIdx.x) >> 5;
    int lane = threadIdx.x & 31;
    if (gw >= n) return;
    int beg = g_csroff[gw], end = g_csroff[gw + 1];
    float s = 0.5f * g_deginv[gw];
    float a[8];
#pragma unroll
    for (int i = 0; i < 8; i++) a[i] = 0.f;
    int e = beg;
    for (; e + 4 <= end; e += 4) {
        uint4 v0 = *(const uint4*)(prev + (size_t)g_csrrow[e]     * 256 + lane * 8);
        uint4 v1 = *(const uint4*)(prev + (size_t)g_csrrow[e + 1] * 256 + lane * 8);
        uint4 v2 = *(const uint4*)(prev + (size_t)g_csrrow[e + 2] * 256 + lane * 8);
        uint4 v3 = *(const uint4*)(prev + (size_t)g_csrrow[e + 3] * 256 + lane * 8);
#pragma unroll
        for (int p = 0; p < 4; p++) {
            float2 f0 = unpackbf((&v0.x)[p]);
            float2 f1 = unpackbf((&v1.x)[p]);
            float2 f2 = unpackbf((&v2.x)[p]);
            float2 f3 = unpackbf((&v3.x)[p]);
            a[2 * p]     += (f0.x + f1.x) + (f2.x + f3.x);
            a[2 * p + 1] += (f0.y + f1.y) + (f2.y + f3.y);
        }
    }
    for (; e < end; e++) {
        uint4 v0 = *(const uint4*)(prev + (size_t)g_csrrow[e] * 256 + lane * 8);
#pragma unroll
        for (int p = 0; p < 4; p++) {
            float2 f0 = unpackbf((&v0.x)[p]);
            a[2 * p] += f0.x; a[2 * p + 1] += f0.y;
        }
    }
    uint4 o;
    o.x = packbf(s * a[0], s * a[1]);
    o.y = packbf(s * a[2], s * a[3]);
    o.z = packbf(s * a[4], s * a[5]);
    o.w = packbf(s * a[6], s * a[7]);
    *(uint4*)(G + (size_t)gw * 256 + lane * 8) = o;
}

// ---------------- merge: t = G + A (bf16) ----------------
__global__ void merge_kernel(__nv_bfloat16* __restrict__ t, const __nv_bfloat16* __restrict__ G,
                             const __nv_bfloat16* __restrict__ A, int n) {
    int i = blockIdx.x * blockDim.x + threadIdx.x;  // per uint4 = 8 bf16
    if (i < n * 32) {
        uint4 g = ((const uint4*)G)[i];
        uint4 a = ((const uint4*)A)[i];
        uint4 o;
#pragma unroll
        for (int p = 0; p < 4; p++) {
            float2 fg = unpackbf((&g.x)[p]);
            float2 fa = unpackbf((&a.x)[p]);
            (&o.x)[p] = packbf(fg.x + fa.x, fg.y + fa.y);
        }
        ((uint4*)t)[i] = o;
    }
}

// ---------------- q/k projection GEMM (tf32) + fused L2 norm -> bf16 only ----------------
__global__ void __launch_bounds__(256) qk_gemm_kernel(const float* __restrict__ x,
                               const float* __restrict__ Wq, const float* __restrict__ Wqb,
                               const float* __restrict__ Wk, const float* __restrict__ Wkb,
                               int n) {
    __shared__ uint32_t As[16][128];
    __shared__ uint32_t Bs[16][128];
    __shared__ float rowss[128];
    int t = threadIdx.x;
    int lane = t & 31, wid = t >> 5;
    int m0 = (wid & 1) * 64, n0 = (wid >> 1) * 32;
    int bm0 = blockIdx.x * 128;
    int by = blockIdx.y;
    const float* B   = (by < 2) ? Wq  : Wk;
    const float* bia = (by < 2) ? Wqb : Wkb;
    __nv_bfloat16* dst = (by < 2) ? g_q16 : g_k16;
    int coff = (by & 1) * 128;
    int am = t >> 1, akq = (t & 1) * 8;
    int bk = t >> 4, bnq = (t & 15) * 8;
    float acc[4][4][4];
#pragma unroll
    for (int i = 0; i < 4; i++)
#pragma unroll
        for (int j = 0; j < 4; j++)
#pragma unroll
            for (int r = 0; r < 4; r++) acc[i][j][r] = 0.f;
    if (t < 128) rowss[t] = 0.f;

    for (int k0 = 0; k0 < 128; k0 += 16) {
        float4 a0 = make_float4(0, 0, 0, 0), a1 = a0;
        int row = bm0 + am;
        if (row < n) {
            const float4* ap = (const float4*)(x + (size_t)row * 128 + k0 + akq);
            a0 = ap[0]; a1 = ap[1];
        }
        const float4* bp = (const float4*)(B + (size_t)(k0 + bk) * 256 + coff + bnq);
        float4 b0 = bp[0], b1 = bp[1];
        __syncthreads();
        As[akq + 0][am] = f2tf(a0.x); As[akq + 1][am] = f2tf(a0.y);
        As[akq + 2][am] = f2tf(a0.z); As[akq + 3][am] = f2tf(a0.w);
        As[akq + 4][am] = f2tf(a1.x); As[akq + 5][am] = f2tf(a1.y);
        As[akq + 6][am] = f2tf(a1.z); As[akq + 7][am] = f2tf(a1.w);
        Bs[bk][bnq + 0] = f2tf(b0.x); Bs[bk][bnq + 1] = f2tf(b0.y);
        Bs[bk][bnq + 2] = f2tf(b0.z); Bs[bk][bnq + 3] = f2tf(b0.w);
        Bs[bk][bnq + 4] = f2tf(b1.x); Bs[bk][bnq + 5] = f2tf(b1.y);
        Bs[bk][bnq + 6] = f2tf(b1.z); Bs[bk][bnq + 7] = f2tf(b1.w);
        __syncthreads();
        ktile_mma(As, Bs, m0, n0, lane, acc);
    }

#pragma unroll
    for (int mt = 0; mt < 4; mt++) {
        float ss0 = 0.f, ss1 = 0.f;
#pragma unroll
        for (int nt = 0; nt < 4; nt++) {
            int col = coff + n0 + nt * 8 + 2 * (lane & 3);
            float bx = bia[col], by2 = bia[col + 1];
            acc[mt][nt][0] += bx; acc[mt][nt][1] += by2;
            acc[mt][nt][2] += bx; acc[mt][nt][3] += by2;
            ss0 += acc[mt][nt][0] * acc[mt][nt][0] + acc[mt][nt][1] * acc[mt][nt][1];
            ss1 += acc[mt][nt][2] * acc[mt][nt][2] + acc[mt][nt][3] * acc[mt][nt][3];
        }
        ss0 += __shfl_xor_sync(0xffffffffu, ss0, 1);
        ss0 += __shfl_xor_sync(0xffffffffu, ss0, 2);
        ss1 += __shfl_xor_sync(0xffffffffu, ss1, 1);
        ss1 += __shfl_xor_sync(0xffffffffu, ss1, 2);
        if ((lane & 3) == 0) {
            int r = m0 + mt * 16 + (lane >> 2);
            atomicAdd(&rowss[r], ss0);
            atomicAdd(&rowss[r + 8], ss1);
        }
    }
    __syncthreads();

#pragma unroll
    for (int mt = 0; mt < 4; mt++) {
        int r = m0 + mt * 16 + (lane >> 2);
        float inv0 = rsqrtf(rowss[r]);
        float inv1 = rsqrtf(rowss[r + 8]);
        int row = bm0 + r;
#pragma unroll
        for (int nt = 0; nt < 4; nt++) {
            int col = coff + n0 + nt * 8 + 2 * (lane & 3);
            if (row < n)
                *(uint32_t*)(dst + (size_t)row * 256 + col) =
                    packbf(acc[mt][nt][0] * inv0, acc[mt][nt][1] * inv0);
            if (row + 8 < n)
                *(uint32_t*)(dst + (size_t)(row + 8) * 256 + col) =
                    packbf(acc[mt][nt][2] * inv1, acc[mt][nt][3] * inv1);
        }
    }
}

// ---------------- ks_sum from bf16 (fp32 accumulate) ----------------
__global__ void kssum_kernel(int n) {
    int col = threadIdx.x;
    int start = blockIdx.x * 512;
    int end = min(start + 512, n);
    float s = 0.f;
    for (int node = start; node < end; node++)
        s += __bfloat162float(g_k16[(size_t)node * 256 + col]);
    atomicAdd(&g_kssum[col], s);
}

// ---------------- den = q16 . ks_sum + n ----------------
__global__ void den_kernel(int n) {
    int gw = (blockIdx.x * blockDim.x + threadIdx.x) >> 5;
    int lane = threadIdx.x & 31;
    if (gw >= n * 2) return;
    int node = gw >> 1, h = gw & 1;
    uint2 qu = *(const uint2*)(g_q16 + (size_t)node * 256 + h * 128 + lane * 4);
    float2 qa = unpackbf(qu.x), qb = unpackbf(qu.y);
    float4 kv = ((const float4*)(g_kssum + h * 128))[lane];
    float d = qa.x * kv.x + qa.y * kv.y + qb.x * kv.z + qb.y * kv.w;
#pragma unroll
    for (int o = 16; o; o >>= 1) d += __shfl_xor_sync(0xffffffffu, d, o);
    if (lane == 0) g_den[node * 2 + h] = d + (float)n;
}

// ---------------- kvs[h] += ks^T @ prev (bf16 mma) ; vs_sum (fp32) ----------------
template <int TermSrc>
__global__ void __launch_bounds__(256) kvs_reduce_t_kernel(const void* __restrict__ prevv, int n) {
    int h = blockIdx.y;
    int c0 = blockIdx.x * 1024;
    int c1 = min(c0 + 1024, n);
    __shared__ uint32_t ksS[16][132];
    __shared__ uint32_t pvS[16][132];
    int t = threadIdx.x;
    int lane = t & 31, wid = t >> 5;
    int m0 = (wid & 1) * 64, n0 = (wid >> 1) * 32;
    float acc[4][4][4];
#pragma unroll
    for (int i = 0; i < 4; i++)
#pragma unroll
        for (int j = 0; j < 4; j++)
#pragma unroll
            for (int r = 0; r < 4; r++) acc[i][j][r] = 0.f;
    float colsum = 0.f;
    int myc = t & 127, hb = (t >> 7) * 8;

    for (int s = c0; s < c1; s += 32) {
        __syncthreads();
#pragma unroll
        for (int i = 0; i < 4; i++) {
            int u = t + 256 * i;
            int nn = u >> 6, m2 = u & 63;
            int nd0 = s + 2 * nn, nd1 = nd0 + 1;
            uint32_t k0 = 0, k1 = 0, p0 = 0, p1 = 0;
            if (nd0 < c1) {
                k0 = *(const uint32_t*)(g_k16 + (size_t)nd0 * 256 + h * 128 + 2 * m2);
                if (TermSrc) {
                    float2 xv = *(const float2*)((const float*)prevv + (size_t)nd0 * 128 + 2 * m2);
                    p0 = packbf(xv.x, xv.y);
                } else {
                    p0 = *(const uint32_t*)((const __nv_bfloat16*)prevv + (size_t)nd0 * 256 + h * 128 + 2 * m2);
                }
            }
            if (nd1 < c1) {
                k1 = *(const uint32_t*)(g_k16 + (size_t)nd1 * 256 + h * 128 + 2 * m2);
                if (TermSrc) {
                    float2 xv = *(const float2*)((const float*)prevv + (size_t)nd1 * 128 + 2 * m2);
                    p1 = packbf(xv.x, xv.y);
                } else {
                    p1 = *(const uint32_t*)((const __nv_bfloat16*)prevv + (size_t)nd1 * 256 + h * 128 + 2 * m2);
                }
            }
            ksS[nn][2 * m2]     = __byte_perm(k0, k1, 0x5410);
            ksS[nn][2 * m2 + 1] = __byte_perm(k0, k1, 0x7632);
            pvS[nn][2 * m2]     = __byte_perm(p0, p1, 0x5410);
            pvS[nn][2 * m2 + 1] = __byte_perm(p0, p1, 0x7632);
        }
        __syncthreads();
        ktile_mma16(ksS, pvS, m0, n0, lane, acc, 2);
#pragma unroll
        for (int r = 0; r < 8; r++) {
            float2 f = unpackbf(pvS[hb + r][myc]);
            colsum += f.x + f.y;
        }
    }
    atomicAdd(&g_vssum[h * 128 + myc], colsum);
    float* kv = g_kvs + h * 16384;
#pragma unroll
    for (int mt = 0; mt < 4; mt++) {
        int m = m0 + mt * 16 + (lane >> 2);
#pragma unroll
        for (int nt = 0; nt < 4; nt++) {
            int c = n0 + nt * 8 + 2 * (lane & 3);
            atomicAdd(&kv[m * 128 + c],           acc[mt][nt][0]);
            atomicAdd(&kv[m * 128 + c + 1],       acc[mt][nt][1]);
            atomicAdd(&kv[(m + 8) * 128 + c],     acc[mt][nt][2]);
            atomicAdd(&kv[(m + 8) * 128 + c + 1], acc[mt][nt][3]);
        }
    }
}

// ---------------- A = (qs @ kvs + vs_sum) / den  (bf16 mma, pure write) ----------------
__global__ void __launch_bounds__(256) combine_attn_kernel(__nv_bfloat16* __restrict__ A, int n) {
    int h = blockIdx.y;
    __shared__ uint32_t As[32][132];
    __shared__ uint32_t Bs[32][132];
    int t = threadIdx.x;
    int lane = t & 31, wid = t >> 5;
    int m0 = (wid & 1) * 64, n0 = (wid >> 1) * 32;
    int bm0 = blockIdx.x * 128;
    const float* kvp = g_kvs + h * 16384;
    float acc[4][4][4];
#pragma unroll
    for (int i = 0; i < 4; i++)
#pragma unroll
        for (int j = 0; j < 4; j++)
#pragma unroll
            for (int r = 0; r < 4; r++) acc[i][j][r] = 0.f;

#pragma unroll
    for (int kc = 0; kc < 2; kc++) {
        int kb = kc * 64;
        __syncthreads();
#pragma unroll
        for (int i = 0; i < 4; i++) {
            int u = t + 256 * i;
            int row = u >> 3, q = u & 7;
            uint4 v = make_uint4(0, 0, 0, 0);
            if (bm0 + row < n)
                v = *(const uint4*)(g_q16 + (size_t)(bm0 + row) * 256 + h * 128 + kb + q * 8);
            As[q * 4 + 0][row] = v.x; As[q * 4 + 1][row] = v.y;
            As[q * 4 + 2][row] = v.z; As[q * 4 + 3][row] = v.w;
        }
#pragma unroll
        for (int i = 0; i < 16; i++) {
            int u = t + 256 * i;
            int d = u & 127, m2 = u >> 7;
            int m = kb + 2 * m2;
            Bs[m2][d] = packbf(kvp[m * 128 + d], kvp[(m + 1) * 128 + d]);
        }
        __syncthreads();
        ktile_mma16((const uint32_t(*)[132])As, (const uint32_t(*)[132])Bs, m0, n0, lane, acc, 4);
    }
#pragma unroll
    for (int mt = 0; mt < 4; mt++) {
        int row = bm0 + m0 + mt * 16 + (lane >> 2);
#pragma unroll
        for (int nt = 0; nt < 4; nt++) {
            int col = n0 + nt * 8 + 2 * (lane & 3);
            float vs0 = g_vssum[h * 128 + col], vs1 = g_vssum[h * 128 + col + 1];
            if (row < n) {
                float invd = 1.0f / g_den[row * 2 + h];
                *(uint32_t*)(A + (size_t)row * 256 + h * 128 + col) =
                    packbf((acc[mt][nt][0] + vs0) * invd, (acc[mt][nt][1] + vs1) * invd);
            }
            if (row + 8 < n) {
                float invd = 1.0f / g_den[(row + 8) * 2 + h];
                *(uint32_t*)(A + (size_t)(row + 8) * 256 + h * 128 + col) =
                    packbf((acc[mt][nt][2] + vs0) * invd, (acc[mt][nt][3] + vs1) * invd);
            }
        }
    }
}

// ---------------- out part A: out = 0.5*(x@(Wo0h0+Wo0h1) + t1@Wo_1 + t2@Wo_2 + b) ----------------
__global__ void __launch_bounds__(256) out_partA_kernel(
    const float* __restrict__ x, const float* __restrict__ Wo, const float* __restrict__ Wob,
    const __nv_bfloat16* __restrict__ t1, const __nv_bfloat16* __restrict__ t2,
    float* __restrict__ out, int n) {
    __shared__ uint32_t As[32][132];
    __shared__ uint32_t Bs[32][132];
    int t = threadIdx.x;
    int lane = t & 31, wid = t >> 5;
    int m0 = (wid & 1) * 64, n0 = (wid >> 1) * 32;
    int bm0 = blockIdx.x * 128;
    float acc[4][4][4];
#pragma unroll
    for (int i = 0; i < 4; i++)
#pragma unroll
        for (int j = 0; j < 4; j++)
#pragma unroll
            for (int r = 0; r < 4; r++) acc[i][j][r] = 0.f;

    // phase A: tf32 over x
    {
        int am = t >> 1, akq = (t & 1) * 8;
        int bk = t >> 4, bnq = (t & 15) * 8;
        for (int k0 = 0; k0 < 128; k0 += 16) {
            float4 a0 = make_float4(0, 0, 0, 0), a1 = a0;
            int row = bm0 + am;
            if (row < n) {
                const float4* ap = (const float4*)(x + (size_t)row * 128 + k0 + akq);
                a0 = ap[0]; a1 = ap[1];
            }
            int wr = k0 + bk;
            const float4* p0 = (const float4*)(Wo + (size_t)wr * 128 + bnq);
            const float4* p1 = (const float4*)(Wo + (size_t)(640 + wr) * 128 + bnq);
            float4 u0 = p0[0], u1 = p0[1], v0 = p1[0], v1 = p1[1];
            __syncthreads();
            As[akq + 0][am] = f2tf(a0.x); As[akq + 1][am] = f2tf(a0.y);
            As[akq + 2][am] = f2tf(a0.z); As[akq + 3][am] = f2tf(a0.w);
            As[akq + 4][am] = f2tf(a1.x); As[akq + 5][am] = f2tf(a1.y);
            As[akq + 6][am] = f2tf(a1.z); As[akq + 7][am] = f2tf(a1.w);
            Bs[bk][bnq + 0] = f2tf(u0.x + v0.x); Bs[bk][bnq + 1] = f2tf(u0.y + v0.y);
            Bs[bk][bnq + 2] = f2tf(u0.z + v0.z); Bs[bk][bnq + 3] = f2tf(u0.w + v0.w);
            Bs[bk][bnq + 4] = f2tf(u1.x + v1.x); Bs[bk][bnq + 5] = f2tf(u1.y + v1.y);
            Bs[bk][bnq + 6] = f2tf(u1.z + v1.z); Bs[bk][bnq + 7] = f2tf(u1.w + v1.w);
            __syncthreads();
            ktile_mma132((const uint32_t(*)[132])As, (const uint32_t(*)[132])Bs, m0, n0, lane, acc);
        }
    }
    out_term_phase(t1, Wo, As, Bs, bm0, m0, n0, t, lane, n, 1, acc);
    out_term_phase(t2, Wo, As, Bs, bm0, m0, n0, t, lane, n, 2, acc);

#pragma unroll
    for (int mt = 0; mt < 4; mt++) {
        int row = bm0 + m0 + mt * 16 + (lane >> 2);
#pragma unroll
        for (int nt = 0; nt < 4; nt++) {
            int col = n0 + nt * 8 + 2 * (lane & 3);
            float bx = Wob[col], by2 = Wob[col + 1];
            if (row < n) {
                float2 v = make_float2(0.5f * (acc[mt][nt][0] + bx), 0.5f * (acc[mt][nt][1] + by2));
                *(float2*)&out[(size_t)row * 128 + col] = v;
            }
            if (row + 8 < n) {
                float2 v = make_float2(0.5f * (acc[mt][nt][2] + bx), 0.5f * (acc[mt][nt][3] + by2));
                *(float2*)&out[(size_t)(row + 8) * 128 + col] = v;
            }
        }
    }
}

// ---------------- out += 0.5 * term @ Wo_slice (single-term RMW) ----------------
__global__ void __launch_bounds__(256) out_term_rmw_kernel(
    const float* __restrict__ Wo, const __nv_bfloat16* __restrict__ term,
    float* __restrict__ out, int n, int ksl) {
    __shared__ uint32_t As[32][132];
    __shared__ uint32_t Bs[32][132];
    int t = threadIdx.x;
    int lane = t & 31, wid = t >> 5;
    int m0 = (wid & 1) * 64, n0 = (wid >> 1) * 32;
    int bm0 = blockIdx.x * 128;
    float acc[4][4][4];
#pragma unroll
    for (int i = 0; i < 4; i++)
#pragma unroll
        for (int j = 0; j < 4; j++)
#pragma unroll
            for (int r = 0; r < 4; r++) acc[i][j][r] = 0.f;

    out_term_phase(term, Wo, As, Bs, bm0, m0, n0, t, lane, n, ksl, acc);

#pragma unroll
    for (int mt = 0; mt < 4; mt++) {
        int row = bm0 + m0 + mt * 16 + (lane >> 2);
#pragma unroll
        for (int nt = 0; nt < 4; nt++) {
            int col = n0 + nt * 8 + 2 * (lane & 3);
            if (row < n) {
                float2 c = *(float2*)&out[(size_t)row * 128 + col];
                c.x += 0.5f * acc[mt][nt][0];
                c.y += 0.5f * acc[mt][nt][1];
                *(float2*)&out[(size_t)row * 128 + col] = c;
            }
            if (row + 8 < n) {
                float2 c = *(float2*)&out[(size_t)(row + 8) * 128 + col];
                c.x += 0.5f * acc[mt][nt][2];
                c.y += 0.5f * acc[mt][nt][3];
                *(float2*)&out[(size_t)(row + 8) * 128 + col] = c;
            }
        }
    }
}

// ---------------- host orchestration ----------------
extern "C" void kernel_launch(void* const* d_in, const int* in_sizes, int n_in,
                              void* d_out, int out_size) {
    const float* x   = (const float*)d_in[0];
    const void*  ei  = d_in[1];
    const float* Wqw = (const float*)d_in[2];
    const float* Wqb = (const float*)d_in[3];
    const float* Wkw = (const float*)d_in[4];
    const float* Wkb = (const float*)d_in[5];
    const float* Wow = (const float*)d_in[6];
    const float* Wob = (const float*)d_in[7];
    float* out = (float*)d_out;

    int n = in_sizes[0] / CC;
    int E = in_sizes[1] / 2;

    void *pDeg, *pKvs, *pVs, *pKs, *pG, *pA;
    void *pT[4];
    cudaGetSymbolAddress(&pDeg, g_deg);
    cudaGetSymbolAddress(&pKvs, g_kvs);
    cudaGetSymbolAddress(&pVs,  g_vssum);
    cudaGetSymbolAddress(&pKs,  g_kssum);
    cudaGetSymbolAddress(&pG,   g_G);
    cudaGetSymbolAddress(&pA,   g_A);
    cudaGetSymbolAddress(&pT[0], g_t1);
    cudaGetSymbolAddress(&pT[1], g_t2);
    cudaGetSymbolAddress(&pT[2], g_t3);
    cudaGetSymbolAddress(&pT[3], g_t4);

    static int inited = 0;
    static cudaStream_t sB, sC;
    static cudaEvent_t evQ[5], evC[5], evA, evPC;
    if (!inited) {
        cudaStreamCreateWithFlags(&sB, cudaStreamNonBlocking);
        cudaStreamCreateWithFlags(&sC, cudaStreamNonBlocking);
        for (int i = 0; i < 5; i++) {
            cudaEventCreateWithFlags(&evQ[i], cudaEventDisableTiming);
            cudaEventCreateWithFlags(&evC[i], cudaEventDisableTiming);
        }
        cudaEventCreateWithFlags(&evA, cudaEventDisableTiming);
        cudaEventCreateWithFlags(&evPC, cudaEventDisableTiming);
        inited = 1;
    }

    int nb  = (n + 127) / 128;
    int nkv = (n + 1023) / 1024;
    int nbScan = (n + 1023) / 1024;
    int nMerge = (n * 32 + 255) / 256;

    __nv_bfloat16* G = (__nv_bfloat16*)pG;
    __nv_bfloat16* A = (__nv_bfloat16*)pA;

    // fork sC off stream 0 at capture start
    cudaEventRecord(evC[0], 0);
    cudaStreamWaitEvent(sC, evC[0], 0);

    // ---- edge chain on sC ----
    x_to_bf16_kernel<<<(n * 32 + 255) / 256, 256, 0, sC>>>(x, n);
    cudaMemsetAsync(pDeg, 0, (size_t)n * sizeof(int), sC);
    detect_dtype_kernel<<<1, 256, 0, sC>>>((const int*)ei, in_sizes[1]);
    edge_deg_kernel<<<(E + 255) / 256, 256, 0, sC>>>(ei, E);
    scan_blocks_kernel<<<nbScan, 1024, 0, sC>>>(n);
    scan_tops_kernel<<<1, 128, 0, sC>>>(nbScan);
    scan_apply_kernel<<<(n + 255) / 256, 256, 0, sC>>>(n, E);
    csr_scatter_kernel<<<(E + 255) / 256, 256, 0, sC>>>(ei, E);
    gcn_gather_x16_kernel<<<(n * 32 + 255) / 256, 256, 0, sC>>>(G, n);
    cudaEventRecord(evC[1], sC);

    // ---- projection chain on stream 0 (concurrent) ----
    dim3 gqk((n + 127) / 128, 4);
    qk_gemm_kernel<<<gqk, 256>>>(x, Wqw, Wqb, Wkw, Wkb, n);
    cudaMemsetAsync(pKs, 0, (size_t)HH * CC * sizeof(float));
    kssum_kernel<<<(n + 511) / 512, 256>>>(n);
    den_kernel<<<(n * 2 * 32 + 255) / 256, 256>>>(n);

    // ---- iter 1: kvs from x fp32; combine_attn -> A; merge(t1) ----
    cudaMemsetAsync(pKvs, 0, (size_t)HH * CC * CC * sizeof(float));
    cudaMemsetAsync(pVs,  0, (size_t)HH * CC * sizeof(float));
    kvs_reduce_t_kernel<1><<<dim3(nkv, 2), 256>>>(x, n);
    combine_attn_kernel<<<dim3(nb, 2), 256>>>(A, n);
    cudaStreamWaitEvent(0, evC[1], 0);
    merge_kernel<<<nMerge, 256>>>((__nv_bfloat16*)pT[0], G, A, n);
    cudaEventRecord(evQ[1], 0);

    // ---- iters 2..4: gather->G on sC || kvs+attn->A on 0; merge joins ----
    for (int ksl = 2; ksl <= 4; ksl++) {
        __nv_bfloat16* prev = (__nv_bfloat16*)pT[ksl - 2];
        __nv_bfloat16* nxt  = (__nv_bfloat16*)pT[ksl - 1];
        cudaStreamWaitEvent(sC, evQ[ksl - 1], 0);
        gcn_gather_kernel<<<(n * 32 + 255) / 256, 256, 0, sC>>>(G, prev, n);
        cudaEventRecord(evC[ksl], sC);

        cudaMemsetAsync(pKvs, 0, (size_t)HH * CC * CC * sizeof(float));
        cudaMemsetAsync(pVs,  0, (size_t)HH * CC * sizeof(float));
        kvs_reduce_t_kernel<0><<<dim3(nkv, 2), 256>>>(prev, n);
        combine_attn_kernel<<<dim3(nb, 2), 256>>>(A, n);

        cudaStreamWaitEvent(0, evC[ksl], 0);
        merge_kernel<<<nMerge, 256>>>(nxt, G, A, n);
        cudaEventRecord(evQ[ksl], 0);

        if (ksl == 2) {
            // t1, t2 final -> out part A overlapped with iters 3-4
            cudaStreamWaitEvent(sB, evQ[2], 0);
            out_partA_kernel<<<nb, 256, 0, sB>>>(x, Wow, Wob,
                                                 (const __nv_bfloat16*)pT[0],
                                                 (const __nv_bfloat16*)pT[1], out, n);
            cudaEventRecord(evA, sB);
        }
        if (ksl == 3) {
            // t3 final -> RMW t3 phase overlapped with iter 4 (sB ordered after partA)
            cudaStreamWaitEvent(sB, evQ[3], 0);
            out_term_rmw_kernel<<<nb, 256, 0, sB>>>(Wow, (const __nv_bfloat16*)pT[2], out, n, 3);
            cudaEventRecord(evPC, sB);
        }
    }

    // ---- tail: out += t4 phase (after merge4 on stream 0 + t3 RMW done) ----
    cudaStreamWaitEvent(0, evPC, 0);
    out_term_rmw_kernel<<<nb, 256>>>(Wow, (const __nv_bfloat16*)pT[3], out, n, 4);
}